// round 1
// baseline (speedup 1.0000x reference)
#include <cuda_runtime.h>
#include <math.h>
#include <stdint.h>

// Problem dims (fixed by reference)
#define S_    2048
#define B_    2
#define H_    1024
#define NH_   16
#define HD_   64
#define ROWS  (S_*B_)      // 4096
#define H3    (3*H_)       // 3072
#define H4    (4*H_)       // 4096

// ---------------- scratch (no allocations allowed) ----------------
__device__ float g_ln1 [ROWS*(size_t)H_];
__device__ float g_qkv [ROWS*(size_t)H3];
__device__ float g_attn[ROWS*(size_t)H_];
__device__ float g_x1  [ROWS*(size_t)H_];
__device__ float g_ln2 [ROWS*(size_t)H_];
__device__ float g_mid [ROWS*(size_t)H4];

// ---------------- LayerNorm: one block per row, H=1024, 256 threads ----------------
__global__ void ln_kernel(const float* __restrict__ x, const float* __restrict__ w,
                          const float* __restrict__ b, float* __restrict__ y)
{
    const int row = blockIdx.x;
    const int t   = threadIdx.x;
    const float4* xr = (const float4*)(x + (size_t)row * H_);
    float4 v = xr[t];
    float s  = v.x + v.y + v.z + v.w;
    float sq = v.x*v.x + v.y*v.y + v.z*v.z + v.w*v.w;
    #pragma unroll
    for (int o = 16; o > 0; o >>= 1) {
        s  += __shfl_xor_sync(0xffffffffu, s,  o);
        sq += __shfl_xor_sync(0xffffffffu, sq, o);
    }
    __shared__ float ss[8], ssq[8];
    const int wid = t >> 5, lid = t & 31;
    if (lid == 0) { ss[wid] = s; ssq[wid] = sq; }
    __syncthreads();
    if (wid == 0) {
        float s2 = (lid < 8) ? ss[lid]  : 0.f;
        float q2 = (lid < 8) ? ssq[lid] : 0.f;
        #pragma unroll
        for (int o = 4; o > 0; o >>= 1) {
            s2 += __shfl_xor_sync(0xffffffffu, s2, o);
            q2 += __shfl_xor_sync(0xffffffffu, q2, o);
        }
        if (lid == 0) { ss[0] = s2; ssq[0] = q2; }
    }
    __syncthreads();
    const float mean = ss[0] * (1.f / H_);
    const float var  = ssq[0] * (1.f / H_) - mean * mean;
    const float rstd = rsqrtf(var + 1e-5f);
    float4 wv = ((const float4*)w)[t];
    float4 bv = ((const float4*)b)[t];
    float4 o;
    o.x = (v.x - mean) * rstd * wv.x + bv.x;
    o.y = (v.y - mean) * rstd * wv.y + bv.y;
    o.z = (v.z - mean) * rstd * wv.z + bv.z;
    o.w = (v.w - mean) * rstd * wv.w + bv.w;
    ((float4*)(y + (size_t)row * H_))[t] = o;
}

// ---------------- SGEMM: C[M,N] = A[M,K] * W[N,K]^T + epilogue ----------------
// MODE 0: +bias; MODE 1: gelu_tanh(+bias); MODE 2: +bias+residual
// Requires M%128==0, N%128==0, K%8==0.
template<int MODE>
__global__ void __launch_bounds__(256, 2)
sgemm_nt(const float* __restrict__ A, const float* __restrict__ W,
         const float* __restrict__ bias, const float* __restrict__ resid,
         float* __restrict__ C, int M, int N, int K)
{
    __shared__ float As[8][128];
    __shared__ float Ws[8][128];

    const int tid  = threadIdx.x;
    const int tx   = tid & 15;      // 0..15 -> N sub-tile
    const int ty   = tid >> 4;      // 0..15 -> M sub-tile
    const int brow = blockIdx.y << 7;
    const int bcol = blockIdx.x << 7;

    const int lr = tid >> 1;          // 0..127
    const int lc = (tid & 1) << 2;    // 0 or 4

    const float* Ap = A + (size_t)(brow + lr) * K + lc;
    const float* Wp = W + (size_t)(bcol + lr) * K + lc;

    float acc[8][8];
    #pragma unroll
    for (int i = 0; i < 8; i++)
        #pragma unroll
        for (int j = 0; j < 8; j++) acc[i][j] = 0.f;

    for (int k0 = 0; k0 < K; k0 += 8) {
        float4 av = *(const float4*)(Ap + k0);
        float4 wv = *(const float4*)(Wp + k0);
        __syncthreads();   // previous iteration's reads complete
        As[lc+0][lr] = av.x; As[lc+1][lr] = av.y; As[lc+2][lr] = av.z; As[lc+3][lr] = av.w;
        Ws[lc+0][lr] = wv.x; Ws[lc+1][lr] = wv.y; Ws[lc+2][lr] = wv.z; Ws[lc+3][lr] = wv.w;
        __syncthreads();
        #pragma unroll
        for (int k = 0; k < 8; k++) {
            float ar[8], wr[8];
            *(float4*)(ar)     = *(const float4*)&As[k][ty*8];
            *(float4*)(ar + 4) = *(const float4*)&As[k][ty*8 + 4];
            *(float4*)(wr)     = *(const float4*)&Ws[k][tx*8];
            *(float4*)(wr + 4) = *(const float4*)&Ws[k][tx*8 + 4];
            #pragma unroll
            for (int i = 0; i < 8; i++)
                #pragma unroll
                for (int j = 0; j < 8; j++)
                    acc[i][j] = fmaf(ar[i], wr[j], acc[i][j]);
        }
    }

    // epilogue
    float bv[8];
    #pragma unroll
    for (int j = 0; j < 8; j++) bv[j] = bias[bcol + tx*8 + j];

    #pragma unroll
    for (int i = 0; i < 8; i++) {
        const int m = brow + ty*8 + i;
        const size_t off = (size_t)m * N + bcol + tx*8;
        float vout[8];
        #pragma unroll
        for (int j = 0; j < 8; j++) {
            float v = acc[i][j] + bv[j];
            if (MODE == 1) {
                float u = v;
                float c = 0.7978845608028654f * (u + 0.044715f * u * u * u);
                v = 0.5f * u * (1.f + tanhf(c));
            }
            if (MODE == 2) v += resid[off + j];
            vout[j] = v;
        }
        *(float4*)&C[off]     = *(float4*)(vout);
        *(float4*)&C[off + 4] = *(float4*)(vout + 4);
    }
}

// ---------------- Flash attention (fp32, causal), BQ=BKV=64, HD=64 ----------------
// qkv: [S,B,3H] with per-head interleave: offset(s,b,h,which,d) = (s*B+b)*3072 + h*192 + which*64 + d
// out: [S,B,H] at (s*B+b)*1024 + h*64 + d
__global__ void __launch_bounds__(256)
flash_kernel(const float* __restrict__ qkv, float* __restrict__ out)
{
    __shared__ float sQ[64*64];   // Q transposed: sQ[d*64 + r], pre-scaled by 1/8
    __shared__ float sK[64*64];   // K transposed: sK[d*64 + c]; later aliased as P[r*64 + t]
    __shared__ float sV[64*64];   // V row-major:  sV[t*64 + dd]

    const int tid = threadIdx.x;
    const int tx  = tid & 15;     // column group (key / hd dim)
    const int ty  = tid >> 4;     // row group (query dim)
    const int bh  = blockIdx.y;
    const int b   = bh >> 4;
    const int h   = bh & 15;
    const int q0  = blockIdx.x << 6;
    const int hbase = h * 192;

    // ---- load Q tile transposed, scaled ----
    {
        const int r  = tid >> 2;           // 0..63
        const int d0 = (tid & 3) << 4;     // 0,16,32,48
        const float* qp = qkv + ((size_t)(q0 + r) * B_ + b) * (size_t)H3 + hbase + d0;
        #pragma unroll
        for (int c4 = 0; c4 < 4; c4++) {
            float4 v = *(const float4*)(qp + c4*4);
            const int d = d0 + c4*4;
            sQ[(d+0)*64 + r] = v.x * 0.125f;
            sQ[(d+1)*64 + r] = v.y * 0.125f;
            sQ[(d+2)*64 + r] = v.z * 0.125f;
            sQ[(d+3)*64 + r] = v.w * 0.125f;
        }
    }

    float m_i[4], l_i[4], O[4][4];
    #pragma unroll
    for (int i = 0; i < 4; i++) {
        m_i[i] = -1e30f; l_i[i] = 0.f;
        #pragma unroll
        for (int j = 0; j < 4; j++) O[i][j] = 0.f;
    }

    const int ntiles = (q0 >> 6) + 1;   // causal: only key tiles t0 <= q0
    for (int kt = 0; kt < ntiles; kt++) {
        const int t0 = kt << 6;
        __syncthreads();   // sQ ready (1st iter) / previous PV done

        // ---- load K (transposed) and V ----
        {
            const int r  = tid >> 2;
            const int d0 = (tid & 3) << 4;
            const float* kp = qkv + ((size_t)(t0 + r) * B_ + b) * (size_t)H3 + hbase + 64 + d0;
            const float* vp = kp + 64;
            #pragma unroll
            for (int c4 = 0; c4 < 4; c4++) {
                const int d = d0 + c4*4;
                float4 v = *(const float4*)(kp + c4*4);
                sK[(d+0)*64 + r] = v.x; sK[(d+1)*64 + r] = v.y;
                sK[(d+2)*64 + r] = v.z; sK[(d+3)*64 + r] = v.w;
                float4 vv = *(const float4*)(vp + c4*4);
                *(float4*)&sV[r*64 + d] = vv;
            }
        }
        __syncthreads();

        // ---- S = (Q/8) K^T ----
        float s[4][4];
        #pragma unroll
        for (int i = 0; i < 4; i++)
            #pragma unroll
            for (int j = 0; j < 4; j++) s[i][j] = 0.f;

        #pragma unroll 8
        for (int d = 0; d < 64; d++) {
            float qa[4], ka[4];
            *(float4*)qa = *(const float4*)&sQ[d*64 + (ty<<2)];
            *(float4*)ka = *(const float4*)&sK[d*64 + (tx<<2)];
            #pragma unroll
            for (int i = 0; i < 4; i++)
                #pragma unroll
                for (int j = 0; j < 4; j++)
                    s[i][j] = fmaf(qa[i], ka[j], s[i][j]);
        }

        // ---- causal mask on diagonal tile ----
        if (t0 == q0) {
            #pragma unroll
            for (int i = 0; i < 4; i++)
                #pragma unroll
                for (int j = 0; j < 4; j++)
                    if ((t0 + (tx<<2) + j) > (q0 + (ty<<2) + i)) s[i][j] = -1e30f;
        }

        // ---- online softmax (row reductions across 16-lane groups) ----
        float p[4][4];
        #pragma unroll
        for (int i = 0; i < 4; i++) {
            float rm = fmaxf(fmaxf(s[i][0], s[i][1]), fmaxf(s[i][2], s[i][3]));
            #pragma unroll
            for (int o = 1; o < 16; o <<= 1)
                rm = fmaxf(rm, __shfl_xor_sync(0xffffffffu, rm, o, 16));
            const float mnew = fmaxf(m_i[i], rm);
            const float corr = __expf(m_i[i] - mnew);
            float rs = 0.f;
            #pragma unroll
            for (int j = 0; j < 4; j++) {
                float e = __expf(s[i][j] - mnew);
                p[i][j] = e; rs += e;
            }
            #pragma unroll
            for (int o = 1; o < 16; o <<= 1)
                rs += __shfl_xor_sync(0xffffffffu, rs, o, 16);
            l_i[i] = l_i[i] * corr + rs;
            m_i[i] = mnew;
            #pragma unroll
            for (int j = 0; j < 4; j++) O[i][j] *= corr;
        }

        __syncthreads();   // everyone done reading sK as K
        float* Ps = sK;    // alias
        #pragma unroll
        for (int i = 0; i < 4; i++)
            #pragma unroll
            for (int j = 0; j < 4; j++)
                Ps[((ty<<2)+i)*64 + (tx<<2)+j] = p[i][j];
        __syncthreads();

        // ---- O += P V ----
        #pragma unroll 4
        for (int t = 0; t < 64; t++) {
            float va[4];
            *(float4*)va = *(const float4*)&sV[t*64 + (tx<<2)];
            float pr[4];
            #pragma unroll
            for (int i = 0; i < 4; i++) pr[i] = Ps[((ty<<2)+i)*64 + t];
            #pragma unroll
            for (int i = 0; i < 4; i++)
                #pragma unroll
                for (int j = 0; j < 4; j++)
                    O[i][j] = fmaf(pr[i], va[j], O[i][j]);
        }
    }

    // ---- epilogue: normalize + store ----
    #pragma unroll
    for (int i = 0; i < 4; i++) {
        const float inv = 1.f / l_i[i];
        const int srow = q0 + (ty<<2) + i;
        float4 o4;
        o4.x = O[i][0]*inv; o4.y = O[i][1]*inv; o4.z = O[i][2]*inv; o4.w = O[i][3]*inv;
        *(float4*)&out[((size_t)srow * B_ + b) * H_ + h*HD_ + (tx<<2)] = o4;
    }
}

// ---------------- launch ----------------
extern "C" void kernel_launch(void* const* d_in, const int* in_sizes, int n_in,
                              void* d_out, int out_size)
{
    const float* x     = (const float*)d_in[0];
    const float* ln1w  = (const float*)d_in[1];
    const float* ln1b  = (const float*)d_in[2];
    const float* wqkv  = (const float*)d_in[3];
    const float* bqkv  = (const float*)d_in[4];
    const float* wproj = (const float*)d_in[5];
    const float* bproj = (const float*)d_in[6];
    const float* ln2w  = (const float*)d_in[7];
    const float* ln2b  = (const float*)d_in[8];
    const float* wfc1  = (const float*)d_in[9];
    const float* bfc1  = (const float*)d_in[10];
    const float* wfc2  = (const float*)d_in[11];
    const float* bfc2  = (const float*)d_in[12];
    float* out = (float*)d_out;

    float *ln1, *qkv, *attn, *x1, *ln2, *mid;
    cudaGetSymbolAddress((void**)&ln1,  g_ln1);
    cudaGetSymbolAddress((void**)&qkv,  g_qkv);
    cudaGetSymbolAddress((void**)&attn, g_attn);
    cudaGetSymbolAddress((void**)&x1,   g_x1);
    cudaGetSymbolAddress((void**)&ln2,  g_ln2);
    cudaGetSymbolAddress((void**)&mid,  g_mid);

    // 1) ln1 = LN(x)
    ln_kernel<<<ROWS, 256>>>(x, ln1w, ln1b, ln1);
    // 2) qkv = ln1 @ w_qkv^T + b_qkv        [4096,3072] k=1024
    sgemm_nt<0><<<dim3(H3/128, ROWS/128), 256>>>(ln1, wqkv, bqkv, nullptr, qkv, ROWS, H3, H_);
    // 3) attn = causal MHA(qkv)
    flash_kernel<<<dim3(S_/64, B_*NH_), 256>>>(qkv, attn);
    // 4) x1 = x + attn @ w_proj^T + b_proj  [4096,1024] k=1024
    sgemm_nt<2><<<dim3(H_/128, ROWS/128), 256>>>(attn, wproj, bproj, x, x1, ROWS, H_, H_);
    // 5) ln2 = LN(x1)
    ln_kernel<<<ROWS, 256>>>(x1, ln2w, ln2b, ln2);
    // 6) mid = gelu(ln2 @ w_fc1^T + b_fc1)  [4096,4096] k=1024
    sgemm_nt<1><<<dim3(H4/128, ROWS/128), 256>>>(ln2, wfc1, bfc1, nullptr, mid, ROWS, H4, H_);
    // 7) out = x1 + mid @ w_fc2^T + b_fc2   [4096,1024] k=4096
    sgemm_nt<2><<<dim3(H_/128, ROWS/128), 256>>>(mid, wfc2, bfc2, x1, out, ROWS, H_, H4);
}

// round 3
// speedup vs baseline: 2.5368x; 2.5368x over previous
#include <cuda_runtime.h>
#include <cuda.h>
#include <cuda_bf16.h>
#include <math.h>
#include <stdint.h>

// Problem dims (fixed by reference)
#define S_    2048
#define B_    2
#define H_    1024
#define NH_   16
#define HD_   64
#define ROWS  (S_*B_)      // 4096
#define H3    (3*H_)       // 3072
#define H4    (4*H_)       // 4096

// ---------------- scratch (no allocations allowed) ----------------
__device__ float          g_qkv[ROWS*(size_t)H3];   // fp32 qkv (flash input)
__device__ float          g_x1 [ROWS*(size_t)H_];   // fp32 post-attn residual
__device__ __nv_bfloat16  g_ah [ROWS*(size_t)H_];   // activation hi
__device__ __nv_bfloat16  g_al [ROWS*(size_t)H_];   // activation lo
__device__ __nv_bfloat16  g_mh [ROWS*(size_t)H4];   // mid hi (fc2 input)
__device__ __nv_bfloat16  g_ml [ROWS*(size_t)H4];   // mid lo
__device__ __nv_bfloat16  g_wh [H4*(size_t)H_];     // weight hi (reused)
__device__ __nv_bfloat16  g_wl [H4*(size_t)H_];     // weight lo

// ---------------- PTX helpers ----------------
__device__ __forceinline__ uint32_t smem_u32(const void* p) {
    uint32_t a;
    asm("{ .reg .u64 t; cvta.to.shared.u64 t, %1; cvt.u32.u64 %0, t; }" : "=r"(a) : "l"(p));
    return a;
}

#define MBARRIER_INIT(addr, cnt) \
    asm volatile("mbarrier.init.shared.b64 [%0], %1;" :: "r"(addr), "r"(cnt) : "memory")

#define MBARRIER_ARRIVE(addr) \
    asm volatile("mbarrier.arrive.shared.b64 _, [%0];" :: "r"(addr) : "memory")

#define MBARRIER_EXPECT_TX(addr, bytes) \
    asm volatile("mbarrier.arrive.expect_tx.shared.b64 _, [%0], %1;" :: "r"(addr), "r"(bytes) : "memory")

#define MBARRIER_WAIT_PARITY(addr, phase) do { \
    uint32_t _m = (addr); uint32_t _p = (phase); uint32_t _d; \
    asm volatile("{\n\t.reg .pred p;\n\t" \
        "mbarrier.try_wait.parity.acquire.cta.shared::cta.b64 p, [%1], %2;\n\t" \
        "selp.b32 %0, 1, 0, p;\n\t}" : "=r"(_d) : "r"(_m), "r"(_p) : "memory"); \
    if (!_d) { \
        asm volatile("{\n\t.reg .pred P1;\n\t" \
            "WL_%=:\n\t" \
            "mbarrier.try_wait.parity.acquire.cta.shared::cta.b64 P1, [%0], %1, 0x989680;\n\t" \
            "@P1 bra.uni WD_%=;\n\t" \
            "bra.uni WL_%=;\n\t" \
            "WD_%=:\n\t}" :: "r"(_m), "r"(_p) : "memory"); \
    } \
} while (0)

#define MBARRIER_WAIT_PARITY_RELAXED(addr, phase) do { \
    uint32_t _m = (addr); uint32_t _p = (phase); uint32_t _d; \
    asm volatile("{\n\t.reg .pred p;\n\t" \
        "mbarrier.try_wait.parity.relaxed.cta.shared::cta.b64 p, [%1], %2, 0x989680;\n\t" \
        "selp.b32 %0, 1, 0, p;\n\t}" : "=r"(_d) : "r"(_m), "r"(_p) : "memory"); \
    if (!_d) { \
        asm volatile("{\n\t.reg .pred P1;\n\t" \
            "WL_%=:\n\t" \
            "mbarrier.try_wait.parity.relaxed.cta.shared::cta.b64 P1, [%0], %1, 0x989680;\n\t" \
            "@P1 bra.uni WD_%=;\n\t" \
            "bra.uni WL_%=;\n\t" \
            "WD_%=:\n\t}" :: "r"(_m), "r"(_p) : "memory"); \
    } \
} while (0)

__device__ __forceinline__ void tma2d(uint32_t dst, const void* map, int x, int y, uint32_t mbar) {
    asm volatile("cp.async.bulk.tensor.2d.shared::cta.global.tile.mbarrier::complete_tx::bytes "
                 "[%0], [%1, {%2, %3}], [%4];"
                 :: "r"(dst), "l"(map), "r"(x), "r"(y), "r"(mbar) : "memory");
}

__device__ __forceinline__ void ldsm4(uint32_t* r, uint32_t addr) {
    asm volatile("ldmatrix.sync.aligned.m8n8.x4.shared.b16 {%0,%1,%2,%3}, [%4];"
                 : "=r"(r[0]), "=r"(r[1]), "=r"(r[2]), "=r"(r[3]) : "r"(addr));
}

__device__ __forceinline__ void mma16816(float* d, const uint32_t* a, const uint32_t* b) {
    asm volatile("mma.sync.aligned.m16n8k16.row.col.f32.bf16.bf16.f32 "
                 "{%0,%1,%2,%3}, {%4,%5,%6,%7}, {%8,%9}, {%0,%1,%2,%3};"
                 : "+f"(d[0]), "+f"(d[1]), "+f"(d[2]), "+f"(d[3])
                 : "r"(a[0]), "r"(a[1]), "r"(a[2]), "r"(a[3]), "r"(b[0]), "r"(b[1]));
}

// ---------------- bf16 hi/lo split helper ----------------
__device__ __forceinline__ void split2(float a, float b, __nv_bfloat162& h, __nv_bfloat162& l) {
    __nv_bfloat16 ha = __float2bfloat16(a);
    __nv_bfloat16 hb = __float2bfloat16(b);
    h.x = ha; h.y = hb;
    l.x = __float2bfloat16(a - __bfloat162float(ha));
    l.y = __float2bfloat16(b - __bfloat162float(hb));
}

__device__ __forceinline__ float gelu_tanh(float u) {
    float c = 0.7978845608028654f * (u + 0.044715f * u * u * u);
    return 0.5f * u * (1.f + tanhf(c));
}

// ---------------- LayerNorm -> bf16 hi/lo ----------------
__global__ void __launch_bounds__(256)
ln_hl(const float* __restrict__ x, const float* __restrict__ w, const float* __restrict__ b,
      __nv_bfloat16* __restrict__ hi, __nv_bfloat16* __restrict__ lo)
{
    const int row = blockIdx.x;
    const int t   = threadIdx.x;
    float4 v = ((const float4*)(x + (size_t)row * H_))[t];
    float s  = v.x + v.y + v.z + v.w;
    float sq = v.x*v.x + v.y*v.y + v.z*v.z + v.w*v.w;
    #pragma unroll
    for (int o = 16; o > 0; o >>= 1) {
        s  += __shfl_xor_sync(0xffffffffu, s,  o);
        sq += __shfl_xor_sync(0xffffffffu, sq, o);
    }
    __shared__ float ss[8], ssq[8];
    const int wid = t >> 5, lid = t & 31;
    if (lid == 0) { ss[wid] = s; ssq[wid] = sq; }
    __syncthreads();
    if (wid == 0) {
        float s2 = (lid < 8) ? ss[lid]  : 0.f;
        float q2 = (lid < 8) ? ssq[lid] : 0.f;
        #pragma unroll
        for (int o = 4; o > 0; o >>= 1) {
            s2 += __shfl_xor_sync(0xffffffffu, s2, o);
            q2 += __shfl_xor_sync(0xffffffffu, q2, o);
        }
        if (lid == 0) { ss[0] = s2; ssq[0] = q2; }
    }
    __syncthreads();
    const float mean = ss[0] * (1.f / H_);
    const float var  = ssq[0] * (1.f / H_) - mean * mean;
    const float rstd = rsqrtf(var + 1e-5f);
    float4 wv = ((const float4*)w)[t];
    float4 bv = ((const float4*)b)[t];
    float y0 = (v.x - mean) * rstd * wv.x + bv.x;
    float y1 = (v.y - mean) * rstd * wv.y + bv.y;
    float y2 = (v.z - mean) * rstd * wv.z + bv.z;
    float y3 = (v.w - mean) * rstd * wv.w + bv.w;
    __nv_bfloat162 h0, l0, h1, l1;
    split2(y0, y1, h0, l0);
    split2(y2, y3, h1, l1);
    __nv_bfloat162* hp = (__nv_bfloat162*)(hi + (size_t)row * H_);
    __nv_bfloat162* lp = (__nv_bfloat162*)(lo + (size_t)row * H_);
    hp[t*2] = h0; hp[t*2+1] = h1;
    lp[t*2] = l0; lp[t*2+1] = l1;
}

// ---------------- fp32 -> bf16 hi/lo (weights) ----------------
__global__ void __launch_bounds__(256)
split4(const float* __restrict__ w, __nv_bfloat16* __restrict__ hi,
       __nv_bfloat16* __restrict__ lo, int n4)
{
    int i = blockIdx.x * blockDim.x + threadIdx.x;
    if (i >= n4) return;
    float4 v = ((const float4*)w)[i];
    __nv_bfloat162 h0, l0, h1, l1;
    split2(v.x, v.y, h0, l0);
    split2(v.z, v.w, h1, l1);
    ((__nv_bfloat162*)hi)[2*i]   = h0; ((__nv_bfloat162*)hi)[2*i+1] = h1;
    ((__nv_bfloat162*)lo)[2*i]   = l0; ((__nv_bfloat162*)lo)[2*i+1] = l1;
}

// ---------------- HMMA bf16x3 GEMM: C[M,N] = A[M,K] @ W[N,K]^T + epi ----------------
// TMA 3-stage pipeline (64KB/stage: Ah,Al,Bh,Bl tiles 128x64 bf16 SW128),
// 8 consumer warps (mma.sync m16n8k16), 1 producer thread.
// MODE 0: +bias -> fp32 C
// MODE 1: gelu(+bias) -> bf16 hi/lo (Chi/Clo)
// MODE 2: +bias+resid -> fp32 C
static constexpr int SMEM_BYTES = 3*65536 + 1024;

template<int MODE>
__global__ void __launch_bounds__(288, 1)
gemm_tc(const __grid_constant__ CUtensorMap mAh,
        const __grid_constant__ CUtensorMap mAl,
        const __grid_constant__ CUtensorMap mBh,
        const __grid_constant__ CUtensorMap mBl,
        const float* __restrict__ bias, const float* __restrict__ resid,
        float* __restrict__ C, __nv_bfloat16* __restrict__ Chi, __nv_bfloat16* __restrict__ Clo,
        int N, int nc)
{
    extern __shared__ char smem[];
    const uint32_t sb  = smem_u32(smem);
    const uint32_t st0 = (sb + 64 + 1023) & ~1023u;   // stage base, 1024-aligned
    const int tid = threadIdx.x;

    // barriers: full[i]=sb+8i (i<3), empty[i]=sb+24+8i
    if (tid == 0) {
        #pragma unroll
        for (int i = 0; i < 3; i++) {
            MBARRIER_INIT(sb + 8*i, 1);         // full: TMA tx-based
            MBARRIER_INIT(sb + 24 + 8*i, 8);    // empty: one arrive per consumer warp
        }
    }
    __syncthreads();

    const int bx = blockIdx.x, by = blockIdx.y;

    if (tid >= 256) {
        // ---- TMA producer (single thread) ----
        if (tid == 256) {
            for (int c = 0; c < nc; c++) {
                const int s = c % 3, r = c / 3;
                const uint32_t stg = st0 + s * 65536;
                if (r > 0) MBARRIER_WAIT_PARITY_RELAXED(sb + 24 + 8*s, (r - 1) & 1);
                MBARRIER_EXPECT_TX(sb + 8*s, 65536u);
                const int kx = c * 64;
                tma2d(stg,         &mAh, kx, by * 128, sb + 8*s);
                tma2d(stg + 16384, &mAl, kx, by * 128, sb + 8*s);
                tma2d(stg + 32768, &mBh, kx, bx * 128, sb + 8*s);
                tma2d(stg + 49152, &mBl, kx, bx * 128, sb + 8*s);
            }
        }
        return;
    }

    // ---- consumer warps ----
    const int lane = tid & 31;
    const int wm = (tid >> 5) >> 1;   // 0..3 (M)
    const int wn = (tid >> 5) & 1;    // 0..1 (N)

    const int arow0 = wm*32 + (lane & 15);                      // A row for ldsm
    const int acx   = lane >> 4;                                // A k-chunk sub (0/1)
    const int brow0 = wn*64 + (lane & 7) + ((lane >> 4) << 3);  // B row for ldsm
    const int bcx   = (lane >> 3) & 1;                          // B k-chunk sub

    float acc[2][8][4];
    #pragma unroll
    for (int i = 0; i < 2; i++)
        #pragma unroll
        for (int j = 0; j < 8; j++)
            #pragma unroll
            for (int q = 0; q < 4; q++) acc[i][j][q] = 0.f;

    for (int c = 0; c < nc; c++) {
        const int s = c % 3, r = c / 3;
        const uint32_t stg = st0 + s * 65536;
        MBARRIER_WAIT_PARITY(sb + 8*s, r & 1);

        #pragma unroll
        for (int ks = 0; ks < 4; ks++) {
            uint32_t ah[2][4], al[2][4], bh[4][4], bl[4][4];
            #pragma unroll
            for (int i = 0; i < 2; i++) {
                const int row = arow0 + i*16;
                const int cc  = 2*ks + acx;
                const uint32_t off = row*128 + (((uint32_t)(cc ^ (row & 7))) << 4);
                ldsm4(ah[i], stg + off);
                ldsm4(al[i], stg + 16384 + off);
            }
            #pragma unroll
            for (int jt = 0; jt < 4; jt++) {
                const int row = brow0 + jt*16;
                const int cc  = 2*ks + bcx;
                const uint32_t off = row*128 + (((uint32_t)(cc ^ (row & 7))) << 4);
                ldsm4(bh[jt], stg + 32768 + off);
                ldsm4(bl[jt], stg + 49152 + off);
            }
            #pragma unroll
            for (int i = 0; i < 2; i++)
                #pragma unroll
                for (int j = 0; j < 8; j++) {
                    const uint32_t* ph = &bh[j>>1][(j&1)*2];
                    const uint32_t* pl = &bl[j>>1][(j&1)*2];
                    mma16816(acc[i][j], ah[i], ph);
                    mma16816(acc[i][j], ah[i], pl);
                    mma16816(acc[i][j], al[i], ph);
                }
        }
        if (lane == 0) MBARRIER_ARRIVE(sb + 24 + 8*s);
    }

    // ---- epilogue ----
    const int rbase = by*128 + wm*32 + (lane >> 2);
    const int cbase = bx*128 + wn*64 + (lane & 3)*2;
    #pragma unroll
    for (int j = 0; j < 8; j++) {
        const int col = cbase + j*8;
        const float bx0 = bias[col], bx1 = bias[col + 1];
        #pragma unroll
        for (int i = 0; i < 2; i++) {
            #pragma unroll
            for (int half = 0; half < 2; half++) {
                const int rowg = rbase + i*16 + half*8;
                float v0 = acc[i][j][half*2 + 0] + bx0;
                float v1 = acc[i][j][half*2 + 1] + bx1;
                const size_t off = (size_t)rowg * N + col;
                if (MODE == 1) {
                    v0 = gelu_tanh(v0);
                    v1 = gelu_tanh(v1);
                    __nv_bfloat162 h, l;
                    split2(v0, v1, h, l);
                    *(__nv_bfloat162*)&Chi[off] = h;
                    *(__nv_bfloat162*)&Clo[off] = l;
                } else {
                    if (MODE == 2) {
                        float2 rr = *(const float2*)&resid[off];
                        v0 += rr.x; v1 += rr.y;
                    }
                    float2 o; o.x = v0; o.y = v1;
                    *(float2*)&C[off] = o;
                }
            }
        }
    }
}

// ---------------- Flash attention (fp32, causal) -> bf16 hi/lo out ----------------
__global__ void __launch_bounds__(256)
flash_kernel(const float* __restrict__ qkv,
             __nv_bfloat16* __restrict__ ohi, __nv_bfloat16* __restrict__ olo)
{
    __shared__ float sQ[64*64];
    __shared__ float sK[64*64];
    __shared__ float sV[64*64];

    const int tid = threadIdx.x;
    const int tx  = tid & 15;
    const int ty  = tid >> 4;
    const int bh  = blockIdx.y;
    const int b   = bh >> 4;
    const int h   = bh & 15;
    const int q0  = blockIdx.x << 6;
    const int hbase = h * 192;

    {
        const int r  = tid >> 2;
        const int d0 = (tid & 3) << 4;
        const float* qp = qkv + ((size_t)(q0 + r) * B_ + b) * (size_t)H3 + hbase + d0;
        #pragma unroll
        for (int c4 = 0; c4 < 4; c4++) {
            float4 v = *(const float4*)(qp + c4*4);
            const int d = d0 + c4*4;
            sQ[(d+0)*64 + r] = v.x * 0.125f;
            sQ[(d+1)*64 + r] = v.y * 0.125f;
            sQ[(d+2)*64 + r] = v.z * 0.125f;
            sQ[(d+3)*64 + r] = v.w * 0.125f;
        }
    }

    float m_i[4], l_i[4], O[4][4];
    #pragma unroll
    for (int i = 0; i < 4; i++) {
        m_i[i] = -1e30f; l_i[i] = 0.f;
        #pragma unroll
        for (int j = 0; j < 4; j++) O[i][j] = 0.f;
    }

    const int ntiles = (q0 >> 6) + 1;
    for (int kt = 0; kt < ntiles; kt++) {
        const int t0 = kt << 6;
        __syncthreads();
        {
            const int r  = tid >> 2;
            const int d0 = (tid & 3) << 4;
            const float* kp = qkv + ((size_t)(t0 + r) * B_ + b) * (size_t)H3 + hbase + 64 + d0;
            const float* vp = kp + 64;
            #pragma unroll
            for (int c4 = 0; c4 < 4; c4++) {
                const int d = d0 + c4*4;
                float4 v = *(const float4*)(kp + c4*4);
                sK[(d+0)*64 + r] = v.x; sK[(d+1)*64 + r] = v.y;
                sK[(d+2)*64 + r] = v.z; sK[(d+3)*64 + r] = v.w;
                float4 vv = *(const float4*)(vp + c4*4);
                *(float4*)&sV[r*64 + d] = vv;
            }
        }
        __syncthreads();

        float s[4][4];
        #pragma unroll
        for (int i = 0; i < 4; i++)
            #pragma unroll
            for (int j = 0; j < 4; j++) s[i][j] = 0.f;

        #pragma unroll 8
        for (int d = 0; d < 64; d++) {
            float qa[4], ka[4];
            *(float4*)qa = *(const float4*)&sQ[d*64 + (ty<<2)];
            *(float4*)ka = *(const float4*)&sK[d*64 + (tx<<2)];
            #pragma unroll
            for (int i = 0; i < 4; i++)
                #pragma unroll
                for (int j = 0; j < 4; j++)
                    s[i][j] = fmaf(qa[i], ka[j], s[i][j]);
        }

        if (t0 == q0) {
            #pragma unroll
            for (int i = 0; i < 4; i++)
                #pragma unroll
                for (int j = 0; j < 4; j++)
                    if ((t0 + (tx<<2) + j) > (q0 + (ty<<2) + i)) s[i][j] = -1e30f;
        }

        float p[4][4];
        #pragma unroll
        for (int i = 0; i < 4; i++) {
            float rm = fmaxf(fmaxf(s[i][0], s[i][1]), fmaxf(s[i][2], s[i][3]));
            #pragma unroll
            for (int o = 1; o < 16; o <<= 1)
                rm = fmaxf(rm, __shfl_xor_sync(0xffffffffu, rm, o, 16));
            const float mnew = fmaxf(m_i[i], rm);
            const float corr = __expf(m_i[i] - mnew);
            float rs = 0.f;
            #pragma unroll
            for (int j = 0; j < 4; j++) {
                float e = __expf(s[i][j] - mnew);
                p[i][j] = e; rs += e;
            }
            #pragma unroll
            for (int o = 1; o < 16; o <<= 1)
                rs += __shfl_xor_sync(0xffffffffu, rs, o, 16);
            l_i[i] = l_i[i] * corr + rs;
            m_i[i] = mnew;
            #pragma unroll
            for (int j = 0; j < 4; j++) O[i][j] *= corr;
        }

        __syncthreads();
        float* Ps = sK;
        #pragma unroll
        for (int i = 0; i < 4; i++)
            #pragma unroll
            for (int j = 0; j < 4; j++)
                Ps[((ty<<2)+i)*64 + (tx<<2)+j] = p[i][j];
        __syncthreads();

        #pragma unroll 4
        for (int t = 0; t < 64; t++) {
            float va[4];
            *(float4*)va = *(const float4*)&sV[t*64 + (tx<<2)];
            float pr[4];
            #pragma unroll
            for (int i = 0; i < 4; i++) pr[i] = Ps[((ty<<2)+i)*64 + t];
            #pragma unroll
            for (int i = 0; i < 4; i++)
                #pragma unroll
                for (int j = 0; j < 4; j++)
                    O[i][j] = fmaf(pr[i], va[j], O[i][j]);
        }
    }

    #pragma unroll
    for (int i = 0; i < 4; i++) {
        const float inv = 1.f / l_i[i];
        const int srow = q0 + (ty<<2) + i;
        float o0 = O[i][0]*inv, o1 = O[i][1]*inv, o2 = O[i][2]*inv, o3 = O[i][3]*inv;
        __nv_bfloat162 h0, l0, h1, l1;
        split2(o0, o1, h0, l0);
        split2(o2, o3, h1, l1);
        const size_t base = ((size_t)srow * B_ + b) * H_ + h*HD_ + (tx<<2);
        *(__nv_bfloat162*)&ohi[base]     = h0;
        *(__nv_bfloat162*)&ohi[base + 2] = h1;
        *(__nv_bfloat162*)&olo[base]     = l0;
        *(__nv_bfloat162*)&olo[base + 2] = l1;
    }
}

// ---------------- host ----------------
typedef CUresult (CUDAAPI *TMEncodeFn)(
    CUtensorMap*, CUtensorMapDataType, cuuint32_t, void*,
    const cuuint64_t*, const cuuint64_t*, const cuuint32_t*, const cuuint32_t*,
    CUtensorMapInterleave, CUtensorMapSwizzle, CUtensorMapL2promotion, CUtensorMapFloatOOBfill);

static void enc_map(TMEncodeFn fn, CUtensorMap* m, void* p, uint64_t rows, uint64_t k)
{
    cuuint64_t dims[2]    = {k, rows};
    cuuint64_t strides[1] = {k * 2};          // bytes
    cuuint32_t box[2]     = {64, 128};        // 64 bf16 = 128B (SW128), 128 rows
    cuuint32_t es[2]      = {1, 1};
    fn(m, CU_TENSOR_MAP_DATA_TYPE_BFLOAT16, 2, p, dims, strides, box, es,
       CU_TENSOR_MAP_INTERLEAVE_NONE, CU_TENSOR_MAP_SWIZZLE_128B,
       CU_TENSOR_MAP_L2_PROMOTION_L2_128B, CU_TENSOR_MAP_FLOAT_OOB_FILL_NONE);
}

extern "C" void kernel_launch(void* const* d_in, const int* in_sizes, int n_in,
                              void* d_out, int out_size)
{
    const float* x     = (const float*)d_in[0];
    const float* ln1w  = (const float*)d_in[1];
    const float* ln1b  = (const float*)d_in[2];
    const float* wqkv  = (const float*)d_in[3];
    const float* bqkv  = (const float*)d_in[4];
    const float* wproj = (const float*)d_in[5];
    const float* bproj = (const float*)d_in[6];
    const float* ln2w  = (const float*)d_in[7];
    const float* ln2b  = (const float*)d_in[8];
    const float* wfc1  = (const float*)d_in[9];
    const float* bfc1  = (const float*)d_in[10];
    const float* wfc2  = (const float*)d_in[11];
    const float* bfc2  = (const float*)d_in[12];
    float* out = (float*)d_out;

    float *qkv, *x1;
    __nv_bfloat16 *ah, *al, *mh, *ml, *wh, *wl;
    cudaGetSymbolAddress((void**)&qkv, g_qkv);
    cudaGetSymbolAddress((void**)&x1,  g_x1);
    cudaGetSymbolAddress((void**)&ah,  g_ah);
    cudaGetSymbolAddress((void**)&al,  g_al);
    cudaGetSymbolAddress((void**)&mh,  g_mh);
    cudaGetSymbolAddress((void**)&ml,  g_ml);
    cudaGetSymbolAddress((void**)&wh,  g_wh);
    cudaGetSymbolAddress((void**)&wl,  g_wl);

    TMEncodeFn enc = nullptr;
    cudaDriverEntryPointQueryResult qres;
    cudaGetDriverEntryPointByVersion("cuTensorMapEncodeTiled", (void**)&enc, 12000,
                                     cudaEnableDefault, &qres);

    cudaFuncSetAttribute((const void*)gemm_tc<0>, cudaFuncAttributeMaxDynamicSharedMemorySize, SMEM_BYTES);
    cudaFuncSetAttribute((const void*)gemm_tc<1>, cudaFuncAttributeMaxDynamicSharedMemorySize, SMEM_BYTES);
    cudaFuncSetAttribute((const void*)gemm_tc<2>, cudaFuncAttributeMaxDynamicSharedMemorySize, SMEM_BYTES);

    CUtensorMap mAh, mAl, mBh, mBl;

    // 1) ln1 -> actA (hi/lo)
    ln_hl<<<ROWS, 256>>>(x, ln1w, ln1b, ah, al);
    // 2) qkv = ln1 @ wqkv^T + b : [4096,3072], K=1024
    split4<<<(H3*H_/4 + 255)/256, 256>>>(wqkv, wh, wl, H3*H_/4);
    enc_map(enc, &mAh, ah, ROWS, H_);
    enc_map(enc, &mAl, al, ROWS, H_);
    enc_map(enc, &mBh, wh, H3, H_);
    enc_map(enc, &mBl, wl, H3, H_);
    gemm_tc<0><<<dim3(H3/128, ROWS/128), 288, SMEM_BYTES>>>(
        mAh, mAl, mBh, mBl, bqkv, nullptr, qkv, nullptr, nullptr, H3, H_/64);
    // 3) attention -> actA (hi/lo)
    flash_kernel<<<dim3(S_/64, B_*NH_), 256>>>(qkv, ah, al);
    // 4) x1 = x + attn @ wproj^T + b : [4096,1024], K=1024
    split4<<<(H_*H_/4 + 255)/256, 256>>>(wproj, wh, wl, H_*H_/4);
    enc_map(enc, &mBh, wh, H_, H_);
    enc_map(enc, &mBl, wl, H_, H_);
    gemm_tc<2><<<dim3(H_/128, ROWS/128), 288, SMEM_BYTES>>>(
        mAh, mAl, mBh, mBl, bproj, x, x1, nullptr, nullptr, H_, H_/64);
    // 5) ln2 -> actA (hi/lo)
    ln_hl<<<ROWS, 256>>>(x1, ln2w, ln2b, ah, al);
    // 6) mid = gelu(ln2 @ wfc1^T + b) -> bf16 hi/lo : [4096,4096], K=1024
    split4<<<(H4*H_/4 + 255)/256, 256>>>(wfc1, wh, wl, H4*H_/4);
    enc_map(enc, &mBh, wh, H4, H_);
    enc_map(enc, &mBl, wl, H4, H_);
    gemm_tc<1><<<dim3(H4/128, ROWS/128), 288, SMEM_BYTES>>>(
        mAh, mAl, mBh, mBl, bfc1, nullptr, nullptr, mh, ml, H4, H_/64);
    // 7) out = x1 + mid @ wfc2^T + b : [4096,1024], K=4096
    split4<<<(H_*H4/4 + 255)/256, 256>>>(wfc2, wh, wl, H_*H4/4);
    enc_map(enc, &mAh, mh, ROWS, H4);
    enc_map(enc, &mAl, ml, ROWS, H4);
    enc_map(enc, &mBh, wh, H_, H4);
    enc_map(enc, &mBl, wl, H_, H4);
    gemm_tc<2><<<dim3(H_/128, ROWS/128), 288, SMEM_BYTES>>>(
        mAh, mAl, mBh, mBl, bfc2, x1, out, nullptr, nullptr, H_, H4/64);
}

// round 4
// speedup vs baseline: 3.8974x; 1.5364x over previous
#include <cuda_runtime.h>
#include <cuda.h>
#include <cuda_bf16.h>
#include <math.h>
#include <stdint.h>

// Problem dims (fixed by reference)
#define S_    2048
#define B_    2
#define H_    1024
#define NH_   16
#define HD_   64
#define ROWS  (S_*B_)      // 4096
#define H3    (3*H_)       // 3072
#define H4    (4*H_)       // 4096
#define BHN   (B_*NH_)     // 32

// ---------------- scratch (no allocations allowed) ----------------
__device__ float          g_x1 [ROWS*(size_t)H_];   // fp32 post-attn residual
__device__ __nv_bfloat16  g_ah [ROWS*(size_t)H_];   // activation hi
__device__ __nv_bfloat16  g_al [ROWS*(size_t)H_];   // activation lo
__device__ __nv_bfloat16  g_mh [ROWS*(size_t)H4];   // mid hi (fc2 input)
__device__ __nv_bfloat16  g_ml [ROWS*(size_t)H4];   // mid lo
__device__ __nv_bfloat16  g_wh [H4*(size_t)H_];     // weight hi (reused)
__device__ __nv_bfloat16  g_wl [H4*(size_t)H_];     // weight lo
// Q/K/V split buffers, layout [(b*16+h), s, d]
__device__ __nv_bfloat16  g_qh [BHN*(size_t)S_*HD_];
__device__ __nv_bfloat16  g_ql [BHN*(size_t)S_*HD_];
__device__ __nv_bfloat16  g_kh [BHN*(size_t)S_*HD_];
__device__ __nv_bfloat16  g_kl [BHN*(size_t)S_*HD_];
__device__ __nv_bfloat16  g_vh [BHN*(size_t)S_*HD_];
__device__ __nv_bfloat16  g_vl [BHN*(size_t)S_*HD_];

// ---------------- PTX helpers ----------------
__device__ __forceinline__ uint32_t smem_u32(const void* p) {
    uint32_t a;
    asm("{ .reg .u64 t; cvta.to.shared.u64 t, %1; cvt.u32.u64 %0, t; }" : "=r"(a) : "l"(p));
    return a;
}

#define MBARRIER_INIT(addr, cnt) \
    asm volatile("mbarrier.init.shared.b64 [%0], %1;" :: "r"(addr), "r"(cnt) : "memory")
#define MBARRIER_ARRIVE(addr) \
    asm volatile("mbarrier.arrive.shared.b64 _, [%0];" :: "r"(addr) : "memory")
#define MBARRIER_EXPECT_TX(addr, bytes) \
    asm volatile("mbarrier.arrive.expect_tx.shared.b64 _, [%0], %1;" :: "r"(addr), "r"(bytes) : "memory")

#define MBARRIER_WAIT_PARITY(addr, phase) do { \
    uint32_t _m = (addr); uint32_t _p = (phase); uint32_t _d; \
    asm volatile("{\n\t.reg .pred p;\n\t" \
        "mbarrier.try_wait.parity.acquire.cta.shared::cta.b64 p, [%1], %2;\n\t" \
        "selp.b32 %0, 1, 0, p;\n\t}" : "=r"(_d) : "r"(_m), "r"(_p) : "memory"); \
    if (!_d) { \
        asm volatile("{\n\t.reg .pred P1;\n\t" \
            "WL_%=:\n\t" \
            "mbarrier.try_wait.parity.acquire.cta.shared::cta.b64 P1, [%0], %1, 0x989680;\n\t" \
            "@P1 bra.uni WD_%=;\n\t" \
            "bra.uni WL_%=;\n\t" \
            "WD_%=:\n\t}" :: "r"(_m), "r"(_p) : "memory"); \
    } \
} while (0)

#define MBARRIER_WAIT_PARITY_RELAXED(addr, phase) do { \
    uint32_t _m = (addr); uint32_t _p = (phase); uint32_t _d; \
    asm volatile("{\n\t.reg .pred p;\n\t" \
        "mbarrier.try_wait.parity.relaxed.cta.shared::cta.b64 p, [%1], %2, 0x989680;\n\t" \
        "selp.b32 %0, 1, 0, p;\n\t}" : "=r"(_d) : "r"(_m), "r"(_p) : "memory"); \
    if (!_d) { \
        asm volatile("{\n\t.reg .pred P1;\n\t" \
            "WL_%=:\n\t" \
            "mbarrier.try_wait.parity.relaxed.cta.shared::cta.b64 P1, [%0], %1, 0x989680;\n\t" \
            "@P1 bra.uni WD_%=;\n\t" \
            "bra.uni WL_%=;\n\t" \
            "WD_%=:\n\t}" :: "r"(_m), "r"(_p) : "memory"); \
    } \
} while (0)

__device__ __forceinline__ void tma2d(uint32_t dst, const void* map, int x, int y, uint32_t mbar) {
    asm volatile("cp.async.bulk.tensor.2d.shared::cta.global.tile.mbarrier::complete_tx::bytes "
                 "[%0], [%1, {%2, %3}], [%4];"
                 :: "r"(dst), "l"(map), "r"(x), "r"(y), "r"(mbar) : "memory");
}

__device__ __forceinline__ void ldsm4(uint32_t* r, uint32_t addr) {
    asm volatile("ldmatrix.sync.aligned.m8n8.x4.shared.b16 {%0,%1,%2,%3}, [%4];"
                 : "=r"(r[0]), "=r"(r[1]), "=r"(r[2]), "=r"(r[3]) : "r"(addr));
}
__device__ __forceinline__ void ldsm4t(uint32_t* r, uint32_t addr) {
    asm volatile("ldmatrix.sync.aligned.m8n8.x4.trans.shared.b16 {%0,%1,%2,%3}, [%4];"
                 : "=r"(r[0]), "=r"(r[1]), "=r"(r[2]), "=r"(r[3]) : "r"(addr));
}

__device__ __forceinline__ void mma16816(float* d, const uint32_t* a, const uint32_t* b) {
    asm volatile("mma.sync.aligned.m16n8k16.row.col.f32.bf16.bf16.f32 "
                 "{%0,%1,%2,%3}, {%4,%5,%6,%7}, {%8,%9}, {%0,%1,%2,%3};"
                 : "+f"(d[0]), "+f"(d[1]), "+f"(d[2]), "+f"(d[3])
                 : "r"(a[0]), "r"(a[1]), "r"(a[2]), "r"(a[3]), "r"(b[0]), "r"(b[1]));
}

__device__ __forceinline__ void cp16(uint32_t dst, const void* src) {
    asm volatile("cp.async.cg.shared.global [%0], [%1], 16;" :: "r"(dst), "l"(src) : "memory");
}
#define CP_COMMIT() asm volatile("cp.async.commit_group;" ::: "memory")
#define CP_WAIT(n)  asm volatile("cp.async.wait_group %0;" :: "n"(n) : "memory")

// ---------------- bf16 hi/lo split helper ----------------
__device__ __forceinline__ void split2(float a, float b, __nv_bfloat162& h, __nv_bfloat162& l) {
    __nv_bfloat16 ha = __float2bfloat16(a);
    __nv_bfloat16 hb = __float2bfloat16(b);
    h.x = ha; h.y = hb;
    l.x = __float2bfloat16(a - __bfloat162float(ha));
    l.y = __float2bfloat16(b - __bfloat162float(hb));
}

__device__ __forceinline__ float gelu_tanh(float u) {
    float c = 0.7978845608028654f * (u + 0.044715f * u * u * u);
    return 0.5f * u * (1.f + tanhf(c));
}

// ---------------- LayerNorm -> bf16 hi/lo ----------------
__global__ void __launch_bounds__(256)
ln_hl(const float* __restrict__ x, const float* __restrict__ w, const float* __restrict__ b,
      __nv_bfloat16* __restrict__ hi, __nv_bfloat16* __restrict__ lo)
{
    const int row = blockIdx.x;
    const int t   = threadIdx.x;
    float4 v = ((const float4*)(x + (size_t)row * H_))[t];
    float s  = v.x + v.y + v.z + v.w;
    float sq = v.x*v.x + v.y*v.y + v.z*v.z + v.w*v.w;
    #pragma unroll
    for (int o = 16; o > 0; o >>= 1) {
        s  += __shfl_xor_sync(0xffffffffu, s,  o);
        sq += __shfl_xor_sync(0xffffffffu, sq, o);
    }
    __shared__ float ss[8], ssq[8];
    const int wid = t >> 5, lid = t & 31;
    if (lid == 0) { ss[wid] = s; ssq[wid] = sq; }
    __syncthreads();
    if (wid == 0) {
        float s2 = (lid < 8) ? ss[lid]  : 0.f;
        float q2 = (lid < 8) ? ssq[lid] : 0.f;
        #pragma unroll
        for (int o = 4; o > 0; o >>= 1) {
            s2 += __shfl_xor_sync(0xffffffffu, s2, o);
            q2 += __shfl_xor_sync(0xffffffffu, q2, o);
        }
        if (lid == 0) { ss[0] = s2; ssq[0] = q2; }
    }
    __syncthreads();
    const float mean = ss[0] * (1.f / H_);
    const float var  = ssq[0] * (1.f / H_) - mean * mean;
    const float rstd = rsqrtf(var + 1e-5f);
    float4 wv = ((const float4*)w)[t];
    float4 bv = ((const float4*)b)[t];
    float y0 = (v.x - mean) * rstd * wv.x + bv.x;
    float y1 = (v.y - mean) * rstd * wv.y + bv.y;
    float y2 = (v.z - mean) * rstd * wv.z + bv.z;
    float y3 = (v.w - mean) * rstd * wv.w + bv.w;
    __nv_bfloat162 h0, l0, h1, l1;
    split2(y0, y1, h0, l0);
    split2(y2, y3, h1, l1);
    __nv_bfloat162* hp = (__nv_bfloat162*)(hi + (size_t)row * H_);
    __nv_bfloat162* lp = (__nv_bfloat162*)(lo + (size_t)row * H_);
    hp[t*2] = h0; hp[t*2+1] = h1;
    lp[t*2] = l0; lp[t*2+1] = l1;
}

// ---------------- fp32 -> bf16 hi/lo (weights) ----------------
__global__ void __launch_bounds__(256)
split4(const float* __restrict__ w, __nv_bfloat16* __restrict__ hi,
       __nv_bfloat16* __restrict__ lo, int n4)
{
    int i = blockIdx.x * blockDim.x + threadIdx.x;
    if (i >= n4) return;
    float4 v = ((const float4*)w)[i];
    __nv_bfloat162 h0, l0, h1, l1;
    split2(v.x, v.y, h0, l0);
    split2(v.z, v.w, h1, l1);
    ((__nv_bfloat162*)hi)[2*i]   = h0; ((__nv_bfloat162*)hi)[2*i+1] = h1;
    ((__nv_bfloat162*)lo)[2*i]   = l0; ((__nv_bfloat162*)lo)[2*i+1] = l1;
}

// ---------------- HMMA bf16x3 GEMM: C[M,N] = A[M,K] @ W[N,K]^T + epi ----------------
// MODE 0: +bias -> scatter qkv as bf16 hi/lo (Q scaled 1/8), layout [(b*16+h), s, d]
// MODE 1: gelu(+bias) -> bf16 hi/lo (Chi/Clo)
// MODE 2: +bias+resid -> fp32 C
static constexpr int SMEM_BYTES = 3*65536 + 1024;

template<int MODE>
__global__ void __launch_bounds__(288, 1)
gemm_tc(const __grid_constant__ CUtensorMap mAh,
        const __grid_constant__ CUtensorMap mAl,
        const __grid_constant__ CUtensorMap mBh,
        const __grid_constant__ CUtensorMap mBl,
        const float* __restrict__ bias, const float* __restrict__ resid,
        float* __restrict__ C, __nv_bfloat16* __restrict__ Chi, __nv_bfloat16* __restrict__ Clo,
        __nv_bfloat16* __restrict__ qh, __nv_bfloat16* __restrict__ ql,
        __nv_bfloat16* __restrict__ kh, __nv_bfloat16* __restrict__ kl,
        __nv_bfloat16* __restrict__ vh, __nv_bfloat16* __restrict__ vl,
        int N, int nc)
{
    extern __shared__ char smem[];
    const uint32_t sb  = smem_u32(smem);
    const uint32_t st0 = (sb + 64 + 1023) & ~1023u;   // stage base, 1024-aligned
    const int tid = threadIdx.x;

    if (tid == 0) {
        #pragma unroll
        for (int i = 0; i < 3; i++) {
            MBARRIER_INIT(sb + 8*i, 1);         // full: TMA tx-based
            MBARRIER_INIT(sb + 24 + 8*i, 8);    // empty: one arrive per consumer warp
        }
    }
    __syncthreads();

    const int bx = blockIdx.x, by = blockIdx.y;

    if (tid >= 256) {
        if (tid == 256) {
            for (int c = 0; c < nc; c++) {
                const int s = c % 3, r = c / 3;
                const uint32_t stg = st0 + s * 65536;
                if (r > 0) MBARRIER_WAIT_PARITY_RELAXED(sb + 24 + 8*s, (r - 1) & 1);
                MBARRIER_EXPECT_TX(sb + 8*s, 65536u);
                const int kx = c * 64;
                tma2d(stg,         &mAh, kx, by * 128, sb + 8*s);
                tma2d(stg + 16384, &mAl, kx, by * 128, sb + 8*s);
                tma2d(stg + 32768, &mBh, kx, bx * 128, sb + 8*s);
                tma2d(stg + 49152, &mBl, kx, bx * 128, sb + 8*s);
            }
        }
        return;
    }

    const int lane = tid & 31;
    const int wm = (tid >> 5) >> 1;
    const int wn = (tid >> 5) & 1;

    const int arow0 = wm*32 + (lane & 15);
    const int acx   = lane >> 4;
    const int brow0 = wn*64 + (lane & 7) + ((lane >> 4) << 3);
    const int bcx   = (lane >> 3) & 1;

    float acc[2][8][4];
    #pragma unroll
    for (int i = 0; i < 2; i++)
        #pragma unroll
        for (int j = 0; j < 8; j++)
            #pragma unroll
            for (int q = 0; q < 4; q++) acc[i][j][q] = 0.f;

    for (int c = 0; c < nc; c++) {
        const int s = c % 3, r = c / 3;
        const uint32_t stg = st0 + s * 65536;
        MBARRIER_WAIT_PARITY(sb + 8*s, r & 1);

        #pragma unroll
        for (int ks = 0; ks < 4; ks++) {
            uint32_t ah[2][4], al[2][4], bh[4][4], bl[4][4];
            #pragma unroll
            for (int i = 0; i < 2; i++) {
                const int row = arow0 + i*16;
                const int cc  = 2*ks + acx;
                const uint32_t off = row*128 + (((uint32_t)(cc ^ (row & 7))) << 4);
                ldsm4(ah[i], stg + off);
                ldsm4(al[i], stg + 16384 + off);
            }
            #pragma unroll
            for (int jt = 0; jt < 4; jt++) {
                const int row = brow0 + jt*16;
                const int cc  = 2*ks + bcx;
                const uint32_t off = row*128 + (((uint32_t)(cc ^ (row & 7))) << 4);
                ldsm4(bh[jt], stg + 32768 + off);
                ldsm4(bl[jt], stg + 49152 + off);
            }
            #pragma unroll
            for (int i = 0; i < 2; i++)
                #pragma unroll
                for (int j = 0; j < 8; j++) {
                    const uint32_t* ph = &bh[j>>1][(j&1)*2];
                    const uint32_t* pl = &bl[j>>1][(j&1)*2];
                    mma16816(acc[i][j], ah[i], ph);
                    mma16816(acc[i][j], ah[i], pl);
                    mma16816(acc[i][j], al[i], ph);
                }
        }
        if (lane == 0) MBARRIER_ARRIVE(sb + 24 + 8*s);
    }

    // ---- epilogue ----
    const int rbase = by*128 + wm*32 + (lane >> 2);
    const int cbase = bx*128 + wn*64 + (lane & 3)*2;
    #pragma unroll
    for (int j = 0; j < 8; j++) {
        const int col = cbase + j*8;
        const float bx0 = bias[col], bx1 = bias[col + 1];
        #pragma unroll
        for (int i = 0; i < 2; i++) {
            #pragma unroll
            for (int half = 0; half < 2; half++) {
                const int rowg = rbase + i*16 + half*8;
                float v0 = acc[i][j][half*2 + 0] + bx0;
                float v1 = acc[i][j][half*2 + 1] + bx1;
                if (MODE == 0) {
                    const int hh   = col / 192;
                    const int rem  = col - hh*192;
                    const int whch = rem >> 6;
                    const int d    = rem & 63;
                    const int ss   = rowg >> 1, bb = rowg & 1;
                    const size_t dst = ((size_t)(bb*16 + hh) * S_ + ss) * HD_ + d;
                    if (whch == 0) { v0 *= 0.125f; v1 *= 0.125f; }
                    __nv_bfloat162 ph2, pl2;
                    split2(v0, v1, ph2, pl2);
                    __nv_bfloat16* dh = (whch == 0) ? qh : (whch == 1) ? kh : vh;
                    __nv_bfloat16* dl = (whch == 0) ? ql : (whch == 1) ? kl : vl;
                    *(__nv_bfloat162*)&dh[dst] = ph2;
                    *(__nv_bfloat162*)&dl[dst] = pl2;
                } else if (MODE == 1) {
                    const size_t off = (size_t)rowg * N + col;
                    v0 = gelu_tanh(v0);
                    v1 = gelu_tanh(v1);
                    __nv_bfloat162 h, l;
                    split2(v0, v1, h, l);
                    *(__nv_bfloat162*)&Chi[off] = h;
                    *(__nv_bfloat162*)&Clo[off] = l;
                } else {
                    const size_t off = (size_t)rowg * N + col;
                    float2 rr = *(const float2*)&resid[off];
                    v0 += rr.x; v1 += rr.y;
                    float2 o; o.x = v0; o.y = v1;
                    *(float2*)&C[off] = o;
                }
            }
        }
    }
}

// ---------------- Flash attention (bf16x3 HMMA, causal) ----------------
// BQ=128, BKV=64, 8 warps x 16 query rows. Q frags in regs; K/V cp.async double-buffered.
// smem: Qh(16K) Ql(16K) + 2 x [Kh Kl Vh Vl](8K each) = 96KB dynamic.
static constexpr int FLASH_SMEM = 96*1024 + 1024;

__global__ void __launch_bounds__(256, 1)
flash_mma(const __nv_bfloat16* __restrict__ Qh, const __nv_bfloat16* __restrict__ Ql,
          const __nv_bfloat16* __restrict__ Kh, const __nv_bfloat16* __restrict__ Kl,
          const __nv_bfloat16* __restrict__ Vh, const __nv_bfloat16* __restrict__ Vl,
          __nv_bfloat16* __restrict__ ohi, __nv_bfloat16* __restrict__ olo)
{
    extern __shared__ char smem[];
    const uint32_t sq  = (smem_u32(smem) + 1023) & ~1023u;
    const uint32_t sqh = sq, sql = sq + 16384;
    const uint32_t skv = sq + 32768;   // + buf*32768; within: Kh 0, Kl 8192, Vh 16384, Vl 24576

    const int tid  = threadIdx.x;
    const int lane = tid & 31;
    const int wq   = tid >> 5;            // warp -> 16 query rows
    const int bhid = blockIdx.y;          // b*16+h
    const int bb   = bhid >> 4;
    const int hh   = bhid & 15;
    const int qi   = (int)gridDim.x - 1 - (int)blockIdx.x;   // heavy tiles first
    const int q0   = qi << 7;
    const int ntiles = (q0 >> 6) + 2;

    const size_t hbase = (size_t)bhid * (S_ * HD_);

    // ---- prologue: load Q (hi/lo) + KV tile 0 ----
    #pragma unroll
    for (int i = 0; i < 4; i++) {
        const int idx = tid*4 + i;           // 0..1023 over 128 rows x 8 chunks
        const int row = idx >> 3, cc = idx & 7;
        const uint32_t off = row*128 + (uint32_t)((cc ^ (row & 7)) << 4);
        const size_t src = hbase + (size_t)(q0 + row) * HD_ + cc*8;
        cp16(sqh + off, Qh + src);
        cp16(sql + off, Ql + src);
    }
    {
        #pragma unroll
        for (int i = 0; i < 2; i++) {
            const int idx = tid*2 + i;       // 0..511 over 64 rows x 8 chunks
            const int row = idx >> 3, cc = idx & 7;
            const uint32_t off = row*128 + (uint32_t)((cc ^ (row & 7)) << 4);
            const size_t src = hbase + (size_t)row * HD_ + cc*8;
            cp16(skv + off,         Kh + src);
            cp16(skv + 8192  + off, Kl + src);
            cp16(skv + 16384 + off, Vh + src);
            cp16(skv + 24576 + off, Vl + src);
        }
    }
    CP_COMMIT();
    CP_WAIT(0);
    __syncthreads();

    // ---- Q fragments (registers, persist across kv loop) ----
    uint32_t qfh[4][4], qfl[4][4];
    {
        const int row = wq*16 + (lane & 15);
        #pragma unroll
        for (int ks = 0; ks < 4; ks++) {
            const int cc = 2*ks + (lane >> 4);
            const uint32_t off = row*128 + (uint32_t)((cc ^ (row & 7)) << 4);
            ldsm4(qfh[ks], sqh + off);
            ldsm4(qfl[ks], sql + off);
        }
    }

    float m_i[2] = {-1e30f, -1e30f};
    float l_i[2] = {0.f, 0.f};
    float O[8][4];
    #pragma unroll
    for (int j = 0; j < 8; j++)
        #pragma unroll
        for (int q = 0; q < 4; q++) O[j][q] = 0.f;

    for (int kt = 0; kt < ntiles; kt++) {
        const int t0 = kt << 6;
        __syncthreads();   // all warps done with buf[(kt+1)&1]'s previous contents
        if (kt + 1 < ntiles) {
            const uint32_t stg = skv + ((kt+1) & 1) * 32768;
            const int tn0 = (kt+1) << 6;
            #pragma unroll
            for (int i = 0; i < 2; i++) {
                const int idx = tid*2 + i;
                const int row = idx >> 3, cc = idx & 7;
                const uint32_t off = row*128 + (uint32_t)((cc ^ (row & 7)) << 4);
                const size_t src = hbase + (size_t)(tn0 + row) * HD_ + cc*8;
                cp16(stg + off,         Kh + src);
                cp16(stg + 8192  + off, Kl + src);
                cp16(stg + 16384 + off, Vh + src);
                cp16(stg + 24576 + off, Vl + src);
            }
        }
        CP_COMMIT();
        CP_WAIT(1);
        __syncthreads();

        const uint32_t stg = skv + (kt & 1) * 32768;
        const uint32_t skh = stg, skl = stg + 8192, svh = stg + 16384, svl = stg + 24576;

        // ---- scores S = Qh Kh^T + Qh Kl^T + Ql Kh^T (16x64 per warp) ----
        float sc[8][4];
        #pragma unroll
        for (int j = 0; j < 8; j++)
            #pragma unroll
            for (int q = 0; q < 4; q++) sc[j][q] = 0.f;

        const int krow_b = (lane & 7) + ((lane >> 4) << 3);
        #pragma unroll
        for (int ks = 0; ks < 4; ks++) {
            uint32_t bhf[4][4], blf[4][4];
            const int cc = 2*ks + ((lane >> 3) & 1);
            #pragma unroll
            for (int jt = 0; jt < 4; jt++) {
                const int row = jt*16 + krow_b;
                const uint32_t off = row*128 + (uint32_t)((cc ^ (row & 7)) << 4);
                ldsm4(bhf[jt], skh + off);
                ldsm4(blf[jt], skl + off);
            }
            #pragma unroll
            for (int j = 0; j < 8; j++) {
                const uint32_t* ph = &bhf[j>>1][(j&1)*2];
                const uint32_t* pl = &blf[j>>1][(j&1)*2];
                mma16816(sc[j], qfh[ks], ph);
                mma16816(sc[j], qfh[ks], pl);
                mma16816(sc[j], qfl[ks], ph);
            }
        }

        // ---- causal mask (last two kv tiles only) ----
        if (kt >= ntiles - 2) {
            const int r0g = q0 + wq*16 + (lane >> 2);
            #pragma unroll
            for (int j = 0; j < 8; j++) {
                const int c0 = t0 + j*8 + (lane & 3)*2;
                if (c0     > r0g)     sc[j][0] = -1e30f;
                if (c0 + 1 > r0g)     sc[j][1] = -1e30f;
                if (c0     > r0g + 8) sc[j][2] = -1e30f;
                if (c0 + 1 > r0g + 8) sc[j][3] = -1e30f;
            }
        }

        // ---- online softmax (2 rows per thread) ----
        #pragma unroll
        for (int v = 0; v < 2; v++) {
            float rm = -1e30f;
            #pragma unroll
            for (int j = 0; j < 8; j++)
                rm = fmaxf(rm, fmaxf(sc[j][2*v], sc[j][2*v+1]));
            rm = fmaxf(rm, __shfl_xor_sync(0xffffffffu, rm, 1));
            rm = fmaxf(rm, __shfl_xor_sync(0xffffffffu, rm, 2));
            const float mnew = fmaxf(m_i[v], rm);
            const float corr = __expf(m_i[v] - mnew);
            float rs = 0.f;
            #pragma unroll
            for (int j = 0; j < 8; j++) {
                float p0 = __expf(sc[j][2*v]   - mnew);
                float p1 = __expf(sc[j][2*v+1] - mnew);
                sc[j][2*v] = p0; sc[j][2*v+1] = p1;
                rs += p0 + p1;
            }
            rs += __shfl_xor_sync(0xffffffffu, rs, 1);
            rs += __shfl_xor_sync(0xffffffffu, rs, 2);
            l_i[v] = l_i[v] * corr + rs;
            m_i[v] = mnew;
            #pragma unroll
            for (int j = 0; j < 8; j++) { O[j][2*v] *= corr; O[j][2*v+1] *= corr; }
        }

        // ---- O += Ph Vh + Ph Vl + Pl Vh ----
        const int vrow_b = (lane & 7) + (((lane >> 3) & 1) << 3);
        #pragma unroll
        for (int kc = 0; kc < 4; kc++) {
            uint32_t pah[4], pal[4];
            {
                __nv_bfloat162 h2, l2;
                split2(sc[2*kc][0],   sc[2*kc][1],   h2, l2); pah[0] = *(uint32_t*)&h2; pal[0] = *(uint32_t*)&l2;
                split2(sc[2*kc][2],   sc[2*kc][3],   h2, l2); pah[1] = *(uint32_t*)&h2; pal[1] = *(uint32_t*)&l2;
                split2(sc[2*kc+1][0], sc[2*kc+1][1], h2, l2); pah[2] = *(uint32_t*)&h2; pal[2] = *(uint32_t*)&l2;
                split2(sc[2*kc+1][2], sc[2*kc+1][3], h2, l2); pah[3] = *(uint32_t*)&h2; pal[3] = *(uint32_t*)&l2;
            }
            const int vrow = kc*16 + vrow_b;
            #pragma unroll
            for (int p = 0; p < 4; p++) {
                const int cc = 2*p + (lane >> 4);
                const uint32_t off = vrow*128 + (uint32_t)((cc ^ (vrow & 7)) << 4);
                uint32_t vhf[4], vlf[4];
                ldsm4t(vhf, svh + off);
                ldsm4t(vlf, svl + off);
                mma16816(O[2*p],   pah, &vhf[0]);
                mma16816(O[2*p],   pah, &vlf[0]);
                mma16816(O[2*p],   pal, &vhf[0]);
                mma16816(O[2*p+1], pah, &vhf[2]);
                mma16816(O[2*p+1], pah, &vlf[2]);
                mma16816(O[2*p+1], pal, &vhf[2]);
            }
        }
    }

    // ---- epilogue: normalize + split + store ----
    #pragma unroll
    for (int v = 0; v < 2; v++) {
        const float inv = 1.f / l_i[v];
        const int srow = q0 + wq*16 + (lane >> 2) + v*8;
        const size_t base = ((size_t)srow * B_ + bb) * H_ + hh*HD_ + (lane & 3)*2;
        #pragma unroll
        for (int j = 0; j < 8; j++) {
            float o0 = O[j][2*v]   * inv;
            float o1 = O[j][2*v+1] * inv;
            __nv_bfloat162 h2, l2;
            split2(o0, o1, h2, l2);
            *(__nv_bfloat162*)&ohi[base + j*8] = h2;
            *(__nv_bfloat162*)&olo[base + j*8] = l2;
        }
    }
}

// ---------------- host ----------------
typedef CUresult (CUDAAPI *TMEncodeFn)(
    CUtensorMap*, CUtensorMapDataType, cuuint32_t, void*,
    const cuuint64_t*, const cuuint64_t*, const cuuint32_t*, const cuuint32_t*,
    CUtensorMapInterleave, CUtensorMapSwizzle, CUtensorMapL2promotion, CUtensorMapFloatOOBfill);

static void enc_map(TMEncodeFn fn, CUtensorMap* m, void* p, uint64_t rows, uint64_t k)
{
    cuuint64_t dims[2]    = {k, rows};
    cuuint64_t strides[1] = {k * 2};
    cuuint32_t box[2]     = {64, 128};
    cuuint32_t es[2]      = {1, 1};
    fn(m, CU_TENSOR_MAP_DATA_TYPE_BFLOAT16, 2, p, dims, strides, box, es,
       CU_TENSOR_MAP_INTERLEAVE_NONE, CU_TENSOR_MAP_SWIZZLE_128B,
       CU_TENSOR_MAP_L2_PROMOTION_L2_128B, CU_TENSOR_MAP_FLOAT_OOB_FILL_NONE);
}

extern "C" void kernel_launch(void* const* d_in, const int* in_sizes, int n_in,
                              void* d_out, int out_size)
{
    const float* x     = (const float*)d_in[0];
    const float* ln1w  = (const float*)d_in[1];
    const float* ln1b  = (const float*)d_in[2];
    const float* wqkv  = (const float*)d_in[3];
    const float* bqkv  = (const float*)d_in[4];
    const float* wproj = (const float*)d_in[5];
    const float* bproj = (const float*)d_in[6];
    const float* ln2w  = (const float*)d_in[7];
    const float* ln2b  = (const float*)d_in[8];
    const float* wfc1  = (const float*)d_in[9];
    const float* bfc1  = (const float*)d_in[10];
    const float* wfc2  = (const float*)d_in[11];
    const float* bfc2  = (const float*)d_in[12];
    float* out = (float*)d_out;

    float *x1;
    __nv_bfloat16 *ah, *al, *mh, *ml, *wh, *wl, *qh, *ql, *kh, *kl, *vh, *vl;
    cudaGetSymbolAddress((void**)&x1,  g_x1);
    cudaGetSymbolAddress((void**)&ah,  g_ah);
    cudaGetSymbolAddress((void**)&al,  g_al);
    cudaGetSymbolAddress((void**)&mh,  g_mh);
    cudaGetSymbolAddress((void**)&ml,  g_ml);
    cudaGetSymbolAddress((void**)&wh,  g_wh);
    cudaGetSymbolAddress((void**)&wl,  g_wl);
    cudaGetSymbolAddress((void**)&qh,  g_qh);
    cudaGetSymbolAddress((void**)&ql,  g_ql);
    cudaGetSymbolAddress((void**)&kh,  g_kh);
    cudaGetSymbolAddress((void**)&kl,  g_kl);
    cudaGetSymbolAddress((void**)&vh,  g_vh);
    cudaGetSymbolAddress((void**)&vl,  g_vl);

    TMEncodeFn enc = nullptr;
    cudaDriverEntryPointQueryResult qres;
    cudaGetDriverEntryPointByVersion("cuTensorMapEncodeTiled", (void**)&enc, 12000,
                                     cudaEnableDefault, &qres);

    cudaFuncSetAttribute((const void*)gemm_tc<0>, cudaFuncAttributeMaxDynamicSharedMemorySize, SMEM_BYTES);
    cudaFuncSetAttribute((const void*)gemm_tc<1>, cudaFuncAttributeMaxDynamicSharedMemorySize, SMEM_BYTES);
    cudaFuncSetAttribute((const void*)gemm_tc<2>, cudaFuncAttributeMaxDynamicSharedMemorySize, SMEM_BYTES);
    cudaFuncSetAttribute((const void*)flash_mma,  cudaFuncAttributeMaxDynamicSharedMemorySize, FLASH_SMEM);

    CUtensorMap mAh, mAl, mBh, mBl;

    // 1) ln1 -> actA (hi/lo)
    ln_hl<<<ROWS, 256>>>(x, ln1w, ln1b, ah, al);
    // 2) qkv GEMM -> scatter Q/K/V bf16 hi/lo : [4096,3072], K=1024
    split4<<<(H3*H_/4 + 255)/256, 256>>>(wqkv, wh, wl, H3*H_/4);
    enc_map(enc, &mAh, ah, ROWS, H_);
    enc_map(enc, &mAl, al, ROWS, H_);
    enc_map(enc, &mBh, wh, H3, H_);
    enc_map(enc, &mBl, wl, H3, H_);
    gemm_tc<0><<<dim3(H3/128, ROWS/128), 288, SMEM_BYTES>>>(
        mAh, mAl, mBh, mBl, bqkv, nullptr, nullptr, nullptr, nullptr,
        qh, ql, kh, kl, vh, vl, H3, H_/64);
    // 3) flash attention (bf16x3 HMMA) -> ah/al
    flash_mma<<<dim3(S_/128, BHN), 256, FLASH_SMEM>>>(qh, ql, kh, kl, vh, vl, ah, al);
    // 4) x1 = x + attn @ wproj^T + b : [4096,1024], K=1024
    split4<<<(H_*H_/4 + 255)/256, 256>>>(wproj, wh, wl, H_*H_/4);
    enc_map(enc, &mBh, wh, H_, H_);
    enc_map(enc, &mBl, wl, H_, H_);
    gemm_tc<2><<<dim3(H_/128, ROWS/128), 288, SMEM_BYTES>>>(
        mAh, mAl, mBh, mBl, bproj, x, x1, nullptr, nullptr,
        nullptr, nullptr, nullptr, nullptr, nullptr, nullptr, H_, H_/64);
    // 5) ln2 -> ah/al
    ln_hl<<<ROWS, 256>>>(x1, ln2w, ln2b, ah, al);
    // 6) mid = gelu(ln2 @ wfc1^T + b) -> bf16 hi/lo : [4096,4096], K=1024
    split4<<<(H4*H_/4 + 255)/256, 256>>>(wfc1, wh, wl, H4*H_/4);
    enc_map(enc, &mBh, wh, H4, H_);
    enc_map(enc, &mBl, wl, H4, H_);
    gemm_tc<1><<<dim3(H4/128, ROWS/128), 288, SMEM_BYTES>>>(
        mAh, mAl, mBh, mBl, bfc1, nullptr, nullptr, mh, ml,
        nullptr, nullptr, nullptr, nullptr, nullptr, nullptr, H4, H_/64);
    // 7) out = x1 + mid @ wfc2^T + b : [4096,1024], K=4096
    split4<<<(H_*H4/4 + 255)/256, 256>>>(wfc2, wh, wl, H_*H4/4);
    enc_map(enc, &mAh, mh, ROWS, H4);
    enc_map(enc, &mAl, ml, ROWS, H4);
    enc_map(enc, &mBh, wh, H_, H4);
    enc_map(enc, &mBl, wl, H_, H4);
    gemm_tc<2><<<dim3(H_/128, ROWS/128), 288, SMEM_BYTES>>>(
        mAh, mAl, mBh, mBl, bfc2, x1, out, nullptr, nullptr,
        nullptr, nullptr, nullptr, nullptr, nullptr, nullptr, H_, H4/64);
}

// round 5
// speedup vs baseline: 3.9481x; 1.0130x over previous
#include <cuda_runtime.h>
#include <cuda.h>
#include <cuda_bf16.h>
#include <math.h>
#include <stdint.h>

// Problem dims (fixed by reference)
#define S_    2048
#define B_    2
#define H_    1024
#define NH_   16
#define HD_   64
#define ROWS  (S_*B_)      // 4096
#define H3    (3*H_)       // 3072
#define H4    (4*H_)       // 4096
#define BHN   (B_*NH_)     // 32

// ---------------- scratch (no allocations allowed) ----------------
__device__ float          g_x1 [ROWS*(size_t)H_];   // fp32 post-attn residual
__device__ __nv_bfloat16  g_ah [ROWS*(size_t)H_];   // activation hi
__device__ __nv_bfloat16  g_al [ROWS*(size_t)H_];   // activation lo
__device__ __nv_bfloat16  g_mh [ROWS*(size_t)H4];   // mid hi (fc2 input)
__device__ __nv_bfloat16  g_ml [ROWS*(size_t)H4];   // mid lo
__device__ __nv_bfloat16  g_wh [H4*(size_t)H_];     // weight hi (reused)
__device__ __nv_bfloat16  g_wl [H4*(size_t)H_];     // weight lo
// Q/K/V split buffers, layout [(b*16+h), s, d]
__device__ __nv_bfloat16  g_qh [BHN*(size_t)S_*HD_];
__device__ __nv_bfloat16  g_ql [BHN*(size_t)S_*HD_];
__device__ __nv_bfloat16  g_kh [BHN*(size_t)S_*HD_];
__device__ __nv_bfloat16  g_kl [BHN*(size_t)S_*HD_];
__device__ __nv_bfloat16  g_vh [BHN*(size_t)S_*HD_];
__device__ __nv_bfloat16  g_vl [BHN*(size_t)S_*HD_];

// ---------------- PTX helpers ----------------
__device__ __forceinline__ uint32_t smem_u32(const void* p) {
    uint32_t a;
    asm("{ .reg .u64 t; cvta.to.shared.u64 t, %1; cvt.u32.u64 %0, t; }" : "=r"(a) : "l"(p));
    return a;
}

#define MBARRIER_INIT(addr, cnt) \
    asm volatile("mbarrier.init.shared.b64 [%0], %1;" :: "r"(addr), "r"(cnt) : "memory")
#define MBARRIER_ARRIVE(addr) \
    asm volatile("mbarrier.arrive.shared.b64 _, [%0];" :: "r"(addr) : "memory")
#define MBARRIER_EXPECT_TX(addr, bytes) \
    asm volatile("mbarrier.arrive.expect_tx.shared.b64 _, [%0], %1;" :: "r"(addr), "r"(bytes) : "memory")

#define MBARRIER_WAIT_PARITY(addr, phase) do { \
    uint32_t _m = (addr); uint32_t _p = (phase); uint32_t _d; \
    asm volatile("{\n\t.reg .pred p;\n\t" \
        "mbarrier.try_wait.parity.acquire.cta.shared::cta.b64 p, [%1], %2;\n\t" \
        "selp.b32 %0, 1, 0, p;\n\t}" : "=r"(_d) : "r"(_m), "r"(_p) : "memory"); \
    if (!_d) { \
        asm volatile("{\n\t.reg .pred P1;\n\t" \
            "WL_%=:\n\t" \
            "mbarrier.try_wait.parity.acquire.cta.shared::cta.b64 P1, [%0], %1, 0x989680;\n\t" \
            "@P1 bra.uni WD_%=;\n\t" \
            "bra.uni WL_%=;\n\t" \
            "WD_%=:\n\t}" :: "r"(_m), "r"(_p) : "memory"); \
    } \
} while (0)

#define MBARRIER_WAIT_PARITY_RELAXED(addr, phase) do { \
    uint32_t _m = (addr); uint32_t _p = (phase); uint32_t _d; \
    asm volatile("{\n\t.reg .pred p;\n\t" \
        "mbarrier.try_wait.parity.relaxed.cta.shared::cta.b64 p, [%1], %2, 0x989680;\n\t" \
        "selp.b32 %0, 1, 0, p;\n\t}" : "=r"(_d) : "r"(_m), "r"(_p) : "memory"); \
    if (!_d) { \
        asm volatile("{\n\t.reg .pred P1;\n\t" \
            "WL_%=:\n\t" \
            "mbarrier.try_wait.parity.relaxed.cta.shared::cta.b64 P1, [%0], %1, 0x989680;\n\t" \
            "@P1 bra.uni WD_%=;\n\t" \
            "bra.uni WL_%=;\n\t" \
            "WD_%=:\n\t}" :: "r"(_m), "r"(_p) : "memory"); \
    } \
} while (0)

__device__ __forceinline__ void tma2d(uint32_t dst, const void* map, int x, int y, uint32_t mbar) {
    asm volatile("cp.async.bulk.tensor.2d.shared::cta.global.tile.mbarrier::complete_tx::bytes "
                 "[%0], [%1, {%2, %3}], [%4];"
                 :: "r"(dst), "l"(map), "r"(x), "r"(y), "r"(mbar) : "memory");
}

__device__ __forceinline__ void ldsm4(uint32_t* r, uint32_t addr) {
    asm volatile("ldmatrix.sync.aligned.m8n8.x4.shared.b16 {%0,%1,%2,%3}, [%4];"
                 : "=r"(r[0]), "=r"(r[1]), "=r"(r[2]), "=r"(r[3]) : "r"(addr));
}
__device__ __forceinline__ void ldsm4t(uint32_t* r, uint32_t addr) {
    asm volatile("ldmatrix.sync.aligned.m8n8.x4.trans.shared.b16 {%0,%1,%2,%3}, [%4];"
                 : "=r"(r[0]), "=r"(r[1]), "=r"(r[2]), "=r"(r[3]) : "r"(addr));
}

__device__ __forceinline__ void mma16816(float* d, const uint32_t* a, const uint32_t* b) {
    asm volatile("mma.sync.aligned.m16n8k16.row.col.f32.bf16.bf16.f32 "
                 "{%0,%1,%2,%3}, {%4,%5,%6,%7}, {%8,%9}, {%0,%1,%2,%3};"
                 : "+f"(d[0]), "+f"(d[1]), "+f"(d[2]), "+f"(d[3])
                 : "r"(a[0]), "r"(a[1]), "r"(a[2]), "r"(a[3]), "r"(b[0]), "r"(b[1]));
}

__device__ __forceinline__ void cp16(uint32_t dst, const void* src) {
    asm volatile("cp.async.cg.shared.global [%0], [%1], 16;" :: "r"(dst), "l"(src) : "memory");
}
#define CP_COMMIT() asm volatile("cp.async.commit_group;" ::: "memory")
#define CP_WAIT(n)  asm volatile("cp.async.wait_group %0;" :: "n"(n) : "memory")

// ---------------- bf16 hi/lo split helper ----------------
__device__ __forceinline__ void split2(float a, float b, __nv_bfloat162& h, __nv_bfloat162& l) {
    __nv_bfloat16 ha = __float2bfloat16(a);
    __nv_bfloat16 hb = __float2bfloat16(b);
    h.x = ha; h.y = hb;
    l.x = __float2bfloat16(a - __bfloat162float(ha));
    l.y = __float2bfloat16(b - __bfloat162float(hb));
}

__device__ __forceinline__ float gelu_tanh(float u) {
    float c = 0.7978845608028654f * (u + 0.044715f * u * u * u);
    return 0.5f * u * (1.f + tanhf(c));
}

// ---------------- LayerNorm -> bf16 hi/lo ----------------
__global__ void __launch_bounds__(256)
ln_hl(const float* __restrict__ x, const float* __restrict__ w, const float* __restrict__ b,
      __nv_bfloat16* __restrict__ hi, __nv_bfloat16* __restrict__ lo)
{
    const int row = blockIdx.x;
    const int t   = threadIdx.x;
    float4 v = ((const float4*)(x + (size_t)row * H_))[t];
    float s  = v.x + v.y + v.z + v.w;
    float sq = v.x*v.x + v.y*v.y + v.z*v.z + v.w*v.w;
    #pragma unroll
    for (int o = 16; o > 0; o >>= 1) {
        s  += __shfl_xor_sync(0xffffffffu, s,  o);
        sq += __shfl_xor_sync(0xffffffffu, sq, o);
    }
    __shared__ float ss[8], ssq[8];
    const int wid = t >> 5, lid = t & 31;
    if (lid == 0) { ss[wid] = s; ssq[wid] = sq; }
    __syncthreads();
    if (wid == 0) {
        float s2 = (lid < 8) ? ss[lid]  : 0.f;
        float q2 = (lid < 8) ? ssq[lid] : 0.f;
        #pragma unroll
        for (int o = 4; o > 0; o >>= 1) {
            s2 += __shfl_xor_sync(0xffffffffu, s2, o);
            q2 += __shfl_xor_sync(0xffffffffu, q2, o);
        }
        if (lid == 0) { ss[0] = s2; ssq[0] = q2; }
    }
    __syncthreads();
    const float mean = ss[0] * (1.f / H_);
    const float var  = ssq[0] * (1.f / H_) - mean * mean;
    const float rstd = rsqrtf(var + 1e-5f);
    float4 wv = ((const float4*)w)[t];
    float4 bv = ((const float4*)b)[t];
    float y0 = (v.x - mean) * rstd * wv.x + bv.x;
    float y1 = (v.y - mean) * rstd * wv.y + bv.y;
    float y2 = (v.z - mean) * rstd * wv.z + bv.z;
    float y3 = (v.w - mean) * rstd * wv.w + bv.w;
    __nv_bfloat162 h0, l0, h1, l1;
    split2(y0, y1, h0, l0);
    split2(y2, y3, h1, l1);
    __nv_bfloat162* hp = (__nv_bfloat162*)(hi + (size_t)row * H_);
    __nv_bfloat162* lp = (__nv_bfloat162*)(lo + (size_t)row * H_);
    hp[t*2] = h0; hp[t*2+1] = h1;
    lp[t*2] = l0; lp[t*2+1] = l1;
}

// ---------------- fp32 -> bf16 hi/lo (weights) ----------------
__global__ void __launch_bounds__(256)
split4(const float* __restrict__ w, __nv_bfloat16* __restrict__ hi,
       __nv_bfloat16* __restrict__ lo, int n4)
{
    int i = blockIdx.x * blockDim.x + threadIdx.x;
    if (i >= n4) return;
    float4 v = ((const float4*)w)[i];
    __nv_bfloat162 h0, l0, h1, l1;
    split2(v.x, v.y, h0, l0);
    split2(v.z, v.w, h1, l1);
    ((__nv_bfloat162*)hi)[2*i]   = h0; ((__nv_bfloat162*)hi)[2*i+1] = h1;
    ((__nv_bfloat162*)lo)[2*i]   = l0; ((__nv_bfloat162*)lo)[2*i+1] = l1;
}

// ---------------- HMMA bf16x3 GEMM: C[M,N] = A[M,K] @ W[N,K]^T + epi ----------------
// MODE 0: +bias -> scatter qkv as bf16 hi/lo (Q scaled log2e/8), layout [(b*16+h), s, d]
// MODE 1: gelu(+bias) -> bf16 hi/lo (Chi/Clo)
// MODE 2: +bias+resid -> fp32 C
static constexpr int SMEM_BYTES = 3*65536 + 1024;

template<int MODE>
__global__ void __launch_bounds__(288, 1)
gemm_tc(const __grid_constant__ CUtensorMap mAh,
        const __grid_constant__ CUtensorMap mAl,
        const __grid_constant__ CUtensorMap mBh,
        const __grid_constant__ CUtensorMap mBl,
        const float* __restrict__ bias, const float* __restrict__ resid,
        float* __restrict__ C, __nv_bfloat16* __restrict__ Chi, __nv_bfloat16* __restrict__ Clo,
        __nv_bfloat16* __restrict__ qh, __nv_bfloat16* __restrict__ ql,
        __nv_bfloat16* __restrict__ kh, __nv_bfloat16* __restrict__ kl,
        __nv_bfloat16* __restrict__ vh, __nv_bfloat16* __restrict__ vl,
        int N, int nc)
{
    extern __shared__ char smem[];
    const uint32_t sb  = smem_u32(smem);
    const uint32_t st0 = (sb + 64 + 1023) & ~1023u;   // stage base, 1024-aligned
    const int tid = threadIdx.x;

    if (tid == 0) {
        #pragma unroll
        for (int i = 0; i < 3; i++) {
            MBARRIER_INIT(sb + 8*i, 1);         // full: TMA tx-based
            MBARRIER_INIT(sb + 24 + 8*i, 8);    // empty: one arrive per consumer warp
        }
    }
    __syncthreads();

    const int bx = blockIdx.x, by = blockIdx.y;

    if (tid >= 256) {
        if (tid == 256) {
            for (int c = 0; c < nc; c++) {
                const int s = c % 3, r = c / 3;
                const uint32_t stg = st0 + s * 65536;
                if (r > 0) MBARRIER_WAIT_PARITY_RELAXED(sb + 24 + 8*s, (r - 1) & 1);
                MBARRIER_EXPECT_TX(sb + 8*s, 65536u);
                const int kx = c * 64;
                tma2d(stg,         &mAh, kx, by * 128, sb + 8*s);
                tma2d(stg + 16384, &mAl, kx, by * 128, sb + 8*s);
                tma2d(stg + 32768, &mBh, kx, bx * 128, sb + 8*s);
                tma2d(stg + 49152, &mBl, kx, bx * 128, sb + 8*s);
            }
        }
        return;
    }

    const int lane = tid & 31;
    const int wm = (tid >> 5) >> 1;
    const int wn = (tid >> 5) & 1;

    const int arow0 = wm*32 + (lane & 15);
    const int acx   = lane >> 4;
    const int brow0 = wn*64 + (lane & 7) + ((lane >> 4) << 3);
    const int bcx   = (lane >> 3) & 1;

    float acc[2][8][4];
    #pragma unroll
    for (int i = 0; i < 2; i++)
        #pragma unroll
        for (int j = 0; j < 8; j++)
            #pragma unroll
            for (int q = 0; q < 4; q++) acc[i][j][q] = 0.f;

    for (int c = 0; c < nc; c++) {
        const int s = c % 3, r = c / 3;
        const uint32_t stg = st0 + s * 65536;
        MBARRIER_WAIT_PARITY(sb + 8*s, r & 1);

        #pragma unroll
        for (int ks = 0; ks < 4; ks++) {
            uint32_t ah[2][4], al[2][4], bh[4][4], bl[4][4];
            #pragma unroll
            for (int i = 0; i < 2; i++) {
                const int row = arow0 + i*16;
                const int cc  = 2*ks + acx;
                const uint32_t off = row*128 + (((uint32_t)(cc ^ (row & 7))) << 4);
                ldsm4(ah[i], stg + off);
                ldsm4(al[i], stg + 16384 + off);
            }
            #pragma unroll
            for (int jt = 0; jt < 4; jt++) {
                const int row = brow0 + jt*16;
                const int cc  = 2*ks + bcx;
                const uint32_t off = row*128 + (((uint32_t)(cc ^ (row & 7))) << 4);
                ldsm4(bh[jt], stg + 32768 + off);
                ldsm4(bl[jt], stg + 49152 + off);
            }
            #pragma unroll
            for (int i = 0; i < 2; i++)
                #pragma unroll
                for (int j = 0; j < 8; j++) {
                    const uint32_t* ph = &bh[j>>1][(j&1)*2];
                    const uint32_t* pl = &bl[j>>1][(j&1)*2];
                    mma16816(acc[i][j], ah[i], ph);
                    mma16816(acc[i][j], ah[i], pl);
                    mma16816(acc[i][j], al[i], ph);
                }
        }
        if (lane == 0) MBARRIER_ARRIVE(sb + 24 + 8*s);
    }

    // ---- epilogue ----
    const int rbase = by*128 + wm*32 + (lane >> 2);
    const int cbase = bx*128 + wn*64 + (lane & 3)*2;
    #pragma unroll
    for (int j = 0; j < 8; j++) {
        const int col = cbase + j*8;
        const float bx0 = bias[col], bx1 = bias[col + 1];
        #pragma unroll
        for (int i = 0; i < 2; i++) {
            #pragma unroll
            for (int half = 0; half < 2; half++) {
                const int rowg = rbase + i*16 + half*8;
                float v0 = acc[i][j][half*2 + 0] + bx0;
                float v1 = acc[i][j][half*2 + 1] + bx1;
                if (MODE == 0) {
                    const int hh   = col / 192;
                    const int rem  = col - hh*192;
                    const int whch = rem >> 6;
                    const int d    = rem & 63;
                    const int ss   = rowg >> 1, bb = rowg & 1;
                    const size_t dst = ((size_t)(bb*16 + hh) * S_ + ss) * HD_ + d;
                    if (whch == 0) { v0 *= 0.18033688011f; v1 *= 0.18033688011f; }  // log2(e)/8
                    __nv_bfloat162 ph2, pl2;
                    split2(v0, v1, ph2, pl2);
                    __nv_bfloat16* dh = (whch == 0) ? qh : (whch == 1) ? kh : vh;
                    __nv_bfloat16* dl = (whch == 0) ? ql : (whch == 1) ? kl : vl;
                    *(__nv_bfloat162*)&dh[dst] = ph2;
                    *(__nv_bfloat162*)&dl[dst] = pl2;
                } else if (MODE == 1) {
                    const size_t off = (size_t)rowg * N + col;
                    v0 = gelu_tanh(v0);
                    v1 = gelu_tanh(v1);
                    __nv_bfloat162 h, l;
                    split2(v0, v1, h, l);
                    *(__nv_bfloat162*)&Chi[off] = h;
                    *(__nv_bfloat162*)&Clo[off] = l;
                } else {
                    const size_t off = (size_t)rowg * N + col;
                    float2 rr = *(const float2*)&resid[off];
                    v0 += rr.x; v1 += rr.y;
                    float2 o; o.x = v0; o.y = v1;
                    *(float2*)&C[off] = o;
                }
            }
        }
    }
}

// ---------------- Flash attention (bf16 HMMA, causal) ----------------
// BQ=128, BKV=64, 8 warps x 16 query rows, 2 CTAs/SM.
// QK^T: 3-term bf16 split (score accuracy). PV: PhVh + PhVl (P single bf16).
// Scores in log2 units (Q pre-scaled by log2e/8); exp2f softmax.
static constexpr int FLASH_SMEM = 96*1024 + 1024;

__global__ void __launch_bounds__(256, 2)
flash_mma(const __nv_bfloat16* __restrict__ Qh, const __nv_bfloat16* __restrict__ Ql,
          const __nv_bfloat16* __restrict__ Kh, const __nv_bfloat16* __restrict__ Kl,
          const __nv_bfloat16* __restrict__ Vh, const __nv_bfloat16* __restrict__ Vl,
          __nv_bfloat16* __restrict__ ohi, __nv_bfloat16* __restrict__ olo)
{
    extern __shared__ char smem[];
    const uint32_t sq  = (smem_u32(smem) + 1023) & ~1023u;
    const uint32_t sqh = sq, sql = sq + 16384;
    const uint32_t skv = sq + 32768;   // + buf*32768; within: Kh 0, Kl 8192, Vh 16384, Vl 24576

    const int tid  = threadIdx.x;
    const int lane = tid & 31;
    const int wq   = tid >> 5;            // warp -> 16 query rows
    const int bhid = blockIdx.y;          // b*16+h
    const int bb   = bhid >> 4;
    const int hh   = bhid & 15;
    const int qi   = (int)gridDim.x - 1 - (int)blockIdx.x;   // heavy tiles first
    const int q0   = qi << 7;
    const int ntiles = (q0 >> 6) + 2;

    const size_t hbase = (size_t)bhid * (S_ * HD_);

    // ---- prologue: load Q (hi/lo) + KV tile 0 ----
    #pragma unroll
    for (int i = 0; i < 4; i++) {
        const int idx = tid*4 + i;           // 0..1023 over 128 rows x 8 chunks
        const int row = idx >> 3, cc = idx & 7;
        const uint32_t off = row*128 + (uint32_t)((cc ^ (row & 7)) << 4);
        const size_t src = hbase + (size_t)(q0 + row) * HD_ + cc*8;
        cp16(sqh + off, Qh + src);
        cp16(sql + off, Ql + src);
    }
    {
        #pragma unroll
        for (int i = 0; i < 2; i++) {
            const int idx = tid*2 + i;       // 0..511 over 64 rows x 8 chunks
            const int row = idx >> 3, cc = idx & 7;
            const uint32_t off = row*128 + (uint32_t)((cc ^ (row & 7)) << 4);
            const size_t src = hbase + (size_t)row * HD_ + cc*8;
            cp16(skv + off,         Kh + src);
            cp16(skv + 8192  + off, Kl + src);
            cp16(skv + 16384 + off, Vh + src);
            cp16(skv + 24576 + off, Vl + src);
        }
    }
    CP_COMMIT();
    CP_WAIT(0);
    __syncthreads();

    // ---- Q fragments (registers, persist across kv loop) ----
    uint32_t qfh[4][4], qfl[4][4];
    {
        const int row = wq*16 + (lane & 15);
        #pragma unroll
        for (int ks = 0; ks < 4; ks++) {
            const int cc = 2*ks + (lane >> 4);
            const uint32_t off = row*128 + (uint32_t)((cc ^ (row & 7)) << 4);
            ldsm4(qfh[ks], sqh + off);
            ldsm4(qfl[ks], sql + off);
        }
    }

    float m_i[2] = {-1e30f, -1e30f};
    float l_i[2] = {0.f, 0.f};
    float O[8][4];
    #pragma unroll
    for (int j = 0; j < 8; j++)
        #pragma unroll
        for (int q = 0; q < 4; q++) O[j][q] = 0.f;

    const int my_last_row = q0 + wq*16 + 15;

    for (int kt = 0; kt < ntiles; kt++) {
        const int t0 = kt << 6;
        __syncthreads();   // all warps done with buf[(kt+1)&1]'s previous contents
        if (kt + 1 < ntiles) {
            const uint32_t stg = skv + ((kt+1) & 1) * 32768;
            const int tn0 = (kt+1) << 6;
            #pragma unroll
            for (int i = 0; i < 2; i++) {
                const int idx = tid*2 + i;
                const int row = idx >> 3, cc = idx & 7;
                const uint32_t off = row*128 + (uint32_t)((cc ^ (row & 7)) << 4);
                const size_t src = hbase + (size_t)(tn0 + row) * HD_ + cc*8;
                cp16(stg + off,         Kh + src);
                cp16(stg + 8192  + off, Kl + src);
                cp16(stg + 16384 + off, Vh + src);
                cp16(stg + 24576 + off, Vl + src);
            }
        }
        CP_COMMIT();
        CP_WAIT(1);
        __syncthreads();

        if (t0 > my_last_row) continue;   // tile fully masked for this warp

        const uint32_t stg = skv + (kt & 1) * 32768;
        const uint32_t skh = stg, skl = stg + 8192, svh = stg + 16384, svl = stg + 24576;

        // ---- scores S = Qh Kh^T + Qh Kl^T + Ql Kh^T (16x64 per warp) ----
        float sc[8][4];
        #pragma unroll
        for (int j = 0; j < 8; j++)
            #pragma unroll
            for (int q = 0; q < 4; q++) sc[j][q] = 0.f;

        const int krow_b = (lane & 7) + ((lane >> 4) << 3);
        #pragma unroll
        for (int ks = 0; ks < 4; ks++) {
            const int cc = 2*ks + ((lane >> 3) & 1);
            #pragma unroll
            for (int jt = 0; jt < 4; jt++) {
                uint32_t bhf[4], blf[4];
                const int row = jt*16 + krow_b;
                const uint32_t off = row*128 + (uint32_t)((cc ^ (row & 7)) << 4);
                ldsm4(bhf, skh + off);
                ldsm4(blf, skl + off);
                float* s0 = sc[2*jt];
                float* s1 = sc[2*jt+1];
                mma16816(s0, qfh[ks], &bhf[0]);
                mma16816(s0, qfh[ks], &blf[0]);
                mma16816(s0, qfl[ks], &bhf[0]);
                mma16816(s1, qfh[ks], &bhf[2]);
                mma16816(s1, qfh[ks], &blf[2]);
                mma16816(s1, qfl[ks], &bhf[2]);
            }
        }

        // ---- causal mask (last two kv tiles only) ----
        if (kt >= ntiles - 2) {
            const int r0g = q0 + wq*16 + (lane >> 2);
            #pragma unroll
            for (int j = 0; j < 8; j++) {
                const int c0 = t0 + j*8 + (lane & 3)*2;
                if (c0     > r0g)     sc[j][0] = -1e30f;
                if (c0 + 1 > r0g)     sc[j][1] = -1e30f;
                if (c0     > r0g + 8) sc[j][2] = -1e30f;
                if (c0 + 1 > r0g + 8) sc[j][3] = -1e30f;
            }
        }

        // ---- online softmax in log2 domain (2 rows per thread) ----
        #pragma unroll
        for (int v = 0; v < 2; v++) {
            float rm = -1e30f;
            #pragma unroll
            for (int j = 0; j < 8; j++)
                rm = fmaxf(rm, fmaxf(sc[j][2*v], sc[j][2*v+1]));
            rm = fmaxf(rm, __shfl_xor_sync(0xffffffffu, rm, 1));
            rm = fmaxf(rm, __shfl_xor_sync(0xffffffffu, rm, 2));
            const float mnew = fmaxf(m_i[v], rm);
            const float corr = exp2f(m_i[v] - mnew);
            float rs = 0.f;
            #pragma unroll
            for (int j = 0; j < 8; j++) {
                float p0 = exp2f(sc[j][2*v]   - mnew);
                float p1 = exp2f(sc[j][2*v+1] - mnew);
                sc[j][2*v] = p0; sc[j][2*v+1] = p1;
                rs += p0 + p1;
            }
            rs += __shfl_xor_sync(0xffffffffu, rs, 1);
            rs += __shfl_xor_sync(0xffffffffu, rs, 2);
            l_i[v] = l_i[v] * corr + rs;
            m_i[v] = mnew;
            #pragma unroll
            for (int j = 0; j < 8; j++) { O[j][2*v] *= corr; O[j][2*v+1] *= corr; }
        }

        // ---- O += Ph Vh + Ph Vl (P single bf16) ----
        const int vrow_b = (lane & 7) + (((lane >> 3) & 1) << 3);
        #pragma unroll
        for (int kc = 0; kc < 4; kc++) {
            uint32_t pah[4];
            {
                __nv_bfloat162 h2;
                h2 = __float22bfloat162_rn(make_float2(sc[2*kc][0],   sc[2*kc][1]));   pah[0] = *(uint32_t*)&h2;
                h2 = __float22bfloat162_rn(make_float2(sc[2*kc][2],   sc[2*kc][3]));   pah[1] = *(uint32_t*)&h2;
                h2 = __float22bfloat162_rn(make_float2(sc[2*kc+1][0], sc[2*kc+1][1])); pah[2] = *(uint32_t*)&h2;
                h2 = __float22bfloat162_rn(make_float2(sc[2*kc+1][2], sc[2*kc+1][3])); pah[3] = *(uint32_t*)&h2;
            }
            const int vrow = kc*16 + vrow_b;
            #pragma unroll
            for (int p = 0; p < 4; p++) {
                const int cc = 2*p + (lane >> 4);
                const uint32_t off = vrow*128 + (uint32_t)((cc ^ (vrow & 7)) << 4);
                uint32_t vhf[4], vlf[4];
                ldsm4t(vhf, svh + off);
                ldsm4t(vlf, svl + off);
                mma16816(O[2*p],   pah, &vhf[0]);
                mma16816(O[2*p],   pah, &vlf[0]);
                mma16816(O[2*p+1], pah, &vhf[2]);
                mma16816(O[2*p+1], pah, &vlf[2]);
            }
        }
    }

    // ---- epilogue: normalize + split + store ----
    #pragma unroll
    for (int v = 0; v < 2; v++) {
        const float inv = 1.f / l_i[v];
        const int srow = q0 + wq*16 + (lane >> 2) + v*8;
        const size_t base = ((size_t)srow * B_ + bb) * H_ + hh*HD_ + (lane & 3)*2;
        #pragma unroll
        for (int j = 0; j < 8; j++) {
            float o0 = O[j][2*v]   * inv;
            float o1 = O[j][2*v+1] * inv;
            __nv_bfloat162 h2, l2;
            split2(o0, o1, h2, l2);
            *(__nv_bfloat162*)&ohi[base + j*8] = h2;
            *(__nv_bfloat162*)&olo[base + j*8] = l2;
        }
    }
}

// ---------------- host ----------------
typedef CUresult (CUDAAPI *TMEncodeFn)(
    CUtensorMap*, CUtensorMapDataType, cuuint32_t, void*,
    const cuuint64_t*, const cuuint64_t*, const cuuint32_t*, const cuuint32_t*,
    CUtensorMapInterleave, CUtensorMapSwizzle, CUtensorMapL2promotion, CUtensorMapFloatOOBfill);

static void enc_map(TMEncodeFn fn, CUtensorMap* m, void* p, uint64_t rows, uint64_t k)
{
    cuuint64_t dims[2]    = {k, rows};
    cuuint64_t strides[1] = {k * 2};
    cuuint32_t box[2]     = {64, 128};
    cuuint32_t es[2]      = {1, 1};
    fn(m, CU_TENSOR_MAP_DATA_TYPE_BFLOAT16, 2, p, dims, strides, box, es,
       CU_TENSOR_MAP_INTERLEAVE_NONE, CU_TENSOR_MAP_SWIZZLE_128B,
       CU_TENSOR_MAP_L2_PROMOTION_L2_128B, CU_TENSOR_MAP_FLOAT_OOB_FILL_NONE);
}

extern "C" void kernel_launch(void* const* d_in, const int* in_sizes, int n_in,
                              void* d_out, int out_size)
{
    const float* x     = (const float*)d_in[0];
    const float* ln1w  = (const float*)d_in[1];
    const float* ln1b  = (const float*)d_in[2];
    const float* wqkv  = (const float*)d_in[3];
    const float* bqkv  = (const float*)d_in[4];
    const float* wproj = (const float*)d_in[5];
    const float* bproj = (const float*)d_in[6];
    const float* ln2w  = (const float*)d_in[7];
    const float* ln2b  = (const float*)d_in[8];
    const float* wfc1  = (const float*)d_in[9];
    const float* bfc1  = (const float*)d_in[10];
    const float* wfc2  = (const float*)d_in[11];
    const float* bfc2  = (const float*)d_in[12];
    float* out = (float*)d_out;

    float *x1;
    __nv_bfloat16 *ah, *al, *mh, *ml, *wh, *wl, *qh, *ql, *kh, *kl, *vh, *vl;
    cudaGetSymbolAddress((void**)&x1,  g_x1);
    cudaGetSymbolAddress((void**)&ah,  g_ah);
    cudaGetSymbolAddress((void**)&al,  g_al);
    cudaGetSymbolAddress((void**)&mh,  g_mh);
    cudaGetSymbolAddress((void**)&ml,  g_ml);
    cudaGetSymbolAddress((void**)&wh,  g_wh);
    cudaGetSymbolAddress((void**)&wl,  g_wl);
    cudaGetSymbolAddress((void**)&qh,  g_qh);
    cudaGetSymbolAddress((void**)&ql,  g_ql);
    cudaGetSymbolAddress((void**)&kh,  g_kh);
    cudaGetSymbolAddress((void**)&kl,  g_kl);
    cudaGetSymbolAddress((void**)&vh,  g_vh);
    cudaGetSymbolAddress((void**)&vl,  g_vl);

    TMEncodeFn enc = nullptr;
    cudaDriverEntryPointQueryResult qres;
    cudaGetDriverEntryPointByVersion("cuTensorMapEncodeTiled", (void**)&enc, 12000,
                                     cudaEnableDefault, &qres);

    cudaFuncSetAttribute((const void*)gemm_tc<0>, cudaFuncAttributeMaxDynamicSharedMemorySize, SMEM_BYTES);
    cudaFuncSetAttribute((const void*)gemm_tc<1>, cudaFuncAttributeMaxDynamicSharedMemorySize, SMEM_BYTES);
    cudaFuncSetAttribute((const void*)gemm_tc<2>, cudaFuncAttributeMaxDynamicSharedMemorySize, SMEM_BYTES);
    cudaFuncSetAttribute((const void*)flash_mma,  cudaFuncAttributeMaxDynamicSharedMemorySize, FLASH_SMEM);

    CUtensorMap mAh, mAl, mBh, mBl;

    // 1) ln1 -> actA (hi/lo)
    ln_hl<<<ROWS, 256>>>(x, ln1w, ln1b, ah, al);
    // 2) qkv GEMM -> scatter Q/K/V bf16 hi/lo : [4096,3072], K=1024
    split4<<<(H3*H_/4 + 255)/256, 256>>>(wqkv, wh, wl, H3*H_/4);
    enc_map(enc, &mAh, ah, ROWS, H_);
    enc_map(enc, &mAl, al, ROWS, H_);
    enc_map(enc, &mBh, wh, H3, H_);
    enc_map(enc, &mBl, wl, H3, H_);
    gemm_tc<0><<<dim3(H3/128, ROWS/128), 288, SMEM_BYTES>>>(
        mAh, mAl, mBh, mBl, bqkv, nullptr, nullptr, nullptr, nullptr,
        qh, ql, kh, kl, vh, vl, H3, H_/64);
    // 3) flash attention (bf16 HMMA) -> ah/al
    flash_mma<<<dim3(S_/128, BHN), 256, FLASH_SMEM>>>(qh, ql, kh, kl, vh, vl, ah, al);
    // 4) x1 = x + attn @ wproj^T + b : [4096,1024], K=1024
    split4<<<(H_*H_/4 + 255)/256, 256>>>(wproj, wh, wl, H_*H_/4);
    enc_map(enc, &mBh, wh, H_, H_);
    enc_map(enc, &mBl, wl, H_, H_);
    gemm_tc<2><<<dim3(H_/128, ROWS/128), 288, SMEM_BYTES>>>(
        mAh, mAl, mBh, mBl, bproj, x, x1, nullptr, nullptr,
        nullptr, nullptr, nullptr, nullptr, nullptr, nullptr, H_, H_/64);
    // 5) ln2 -> ah/al
    ln_hl<<<ROWS, 256>>>(x1, ln2w, ln2b, ah, al);
    // 6) mid = gelu(ln2 @ wfc1^T + b) -> bf16 hi/lo : [4096,4096], K=1024
    split4<<<(H4*H_/4 + 255)/256, 256>>>(wfc1, wh, wl, H4*H_/4);
    enc_map(enc, &mBh, wh, H4, H_);
    enc_map(enc, &mBl, wl, H4, H_);
    gemm_tc<1><<<dim3(H4/128, ROWS/128), 288, SMEM_BYTES>>>(
        mAh, mAl, mBh, mBl, bfc1, nullptr, nullptr, mh, ml,
        nullptr, nullptr, nullptr, nullptr, nullptr, nullptr, H4, H_/64);
    // 7) out = x1 + mid @ wfc2^T + b : [4096,1024], K=4096
    split4<<<(H_*H4/4 + 255)/256, 256>>>(wfc2, wh, wl, H_*H4/4);
    enc_map(enc, &mAh, mh, ROWS, H4);
    enc_map(enc, &mAl, ml, ROWS, H4);
    enc_map(enc, &mBh, wh, H_, H4);
    enc_map(enc, &mBl, wl, H_, H4);
    gemm_tc<2><<<dim3(H_/128, ROWS/128), 288, SMEM_BYTES>>>(
        mAh, mAl, mBh, mBl, bfc2, x1, out, nullptr, nullptr,
        nullptr, nullptr, nullptr, nullptr, nullptr, nullptr, H_, H4/64);
}

// round 7
// speedup vs baseline: 5.0503x; 1.2792x over previous
#include <cuda_runtime.h>
#include <cuda.h>
#include <cuda_bf16.h>
#include <cuda_fp16.h>
#include <math.h>
#include <stdint.h>

// Problem dims (fixed by reference)
#define S_    2048
#define B_    2
#define H_    1024
#define NH_   16
#define HD_   64
#define ROWS  (S_*B_)      // 4096
#define H3    (3*H_)       // 3072
#define H4    (4*H_)       // 4096
#define BHN   (B_*NH_)     // 32

// ---------------- scratch (no allocations allowed) ----------------
__device__ float   g_x1 [ROWS*(size_t)H_];   // fp32 post-attn residual
__device__ __half  g_ah [ROWS*(size_t)H_];   // activation hi (fp16)
__device__ __half  g_al [ROWS*(size_t)H_];   // activation lo (fp16)
__device__ __half  g_mh [ROWS*(size_t)H4];   // mid hi (fc2 input)
__device__ __half  g_ml [ROWS*(size_t)H4];   // mid lo
__device__ __half  g_w  [H4*(size_t)H_];     // weight fp16 (reused)
// Q/K/V split buffers (bf16 hi/lo for flash), layout [(b*16+h), s, d]
__device__ __nv_bfloat16  g_qh [BHN*(size_t)S_*HD_];
__device__ __nv_bfloat16  g_ql [BHN*(size_t)S_*HD_];
__device__ __nv_bfloat16  g_kh [BHN*(size_t)S_*HD_];
__device__ __nv_bfloat16  g_kl [BHN*(size_t)S_*HD_];
__device__ __nv_bfloat16  g_vh [BHN*(size_t)S_*HD_];
__device__ __nv_bfloat16  g_vl [BHN*(size_t)S_*HD_];

// ---------------- PTX helpers ----------------
__device__ __forceinline__ uint32_t smem_u32(const void* p) {
    uint32_t a;
    asm("{ .reg .u64 t; cvta.to.shared.u64 t, %1; cvt.u32.u64 %0, t; }" : "=r"(a) : "l"(p));
    return a;
}

#define MBARRIER_INIT(addr, cnt) \
    asm volatile("mbarrier.init.shared.b64 [%0], %1;" :: "r"(addr), "r"(cnt) : "memory")
#define MBARRIER_ARRIVE(addr) \
    asm volatile("mbarrier.arrive.shared.b64 _, [%0];" :: "r"(addr) : "memory")
#define MBARRIER_EXPECT_TX(addr, bytes) \
    asm volatile("mbarrier.arrive.expect_tx.shared.b64 _, [%0], %1;" :: "r"(addr), "r"(bytes) : "memory")

#define MBARRIER_WAIT_PARITY(addr, phase) do { \
    uint32_t _m = (addr); uint32_t _p = (phase); uint32_t _d; \
    asm volatile("{\n\t.reg .pred p;\n\t" \
        "mbarrier.try_wait.parity.acquire.cta.shared::cta.b64 p, [%1], %2;\n\t" \
        "selp.b32 %0, 1, 0, p;\n\t}" : "=r"(_d) : "r"(_m), "r"(_p) : "memory"); \
    if (!_d) { \
        asm volatile("{\n\t.reg .pred P1;\n\t" \
            "WL_%=:\n\t" \
            "mbarrier.try_wait.parity.acquire.cta.shared::cta.b64 P1, [%0], %1, 0x989680;\n\t" \
            "@P1 bra.uni WD_%=;\n\t" \
            "bra.uni WL_%=;\n\t" \
            "WD_%=:\n\t}" :: "r"(_m), "r"(_p) : "memory"); \
    } \
} while (0)

#define MBARRIER_WAIT_PARITY_RELAXED(addr, phase) do { \
    uint32_t _m = (addr); uint32_t _p = (phase); uint32_t _d; \
    asm volatile("{\n\t.reg .pred p;\n\t" \
        "mbarrier.try_wait.parity.relaxed.cta.shared::cta.b64 p, [%1], %2, 0x989680;\n\t" \
        "selp.b32 %0, 1, 0, p;\n\t}" : "=r"(_d) : "r"(_m), "r"(_p) : "memory"); \
    if (!_d) { \
        asm volatile("{\n\t.reg .pred P1;\n\t" \
            "WL_%=:\n\t" \
            "mbarrier.try_wait.parity.relaxed.cta.shared::cta.b64 P1, [%0], %1, 0x989680;\n\t" \
            "@P1 bra.uni WD_%=;\n\t" \
            "bra.uni WL_%=;\n\t" \
            "WD_%=:\n\t}" :: "r"(_m), "r"(_p) : "memory"); \
    } \
} while (0)

__device__ __forceinline__ void tma2d(uint32_t dst, const void* map, int x, int y, uint32_t mbar) {
    asm volatile("cp.async.bulk.tensor.2d.shared::cta.global.tile.mbarrier::complete_tx::bytes "
                 "[%0], [%1, {%2, %3}], [%4];"
                 :: "r"(dst), "l"(map), "r"(x), "r"(y), "r"(mbar) : "memory");
}

__device__ __forceinline__ void ldsm4(uint32_t* r, uint32_t addr) {
    asm volatile("ldmatrix.sync.aligned.m8n8.x4.shared.b16 {%0,%1,%2,%3}, [%4];"
                 : "=r"(r[0]), "=r"(r[1]), "=r"(r[2]), "=r"(r[3]) : "r"(addr));
}
__device__ __forceinline__ void ldsm4t(uint32_t* r, uint32_t addr) {
    asm volatile("ldmatrix.sync.aligned.m8n8.x4.trans.shared.b16 {%0,%1,%2,%3}, [%4];"
                 : "=r"(r[0]), "=r"(r[1]), "=r"(r[2]), "=r"(r[3]) : "r"(addr));
}

// bf16 mma (flash)
__device__ __forceinline__ void mma16816(float* d, const uint32_t* a, const uint32_t* b) {
    asm volatile("mma.sync.aligned.m16n8k16.row.col.f32.bf16.bf16.f32 "
                 "{%0,%1,%2,%3}, {%4,%5,%6,%7}, {%8,%9}, {%0,%1,%2,%3};"
                 : "+f"(d[0]), "+f"(d[1]), "+f"(d[2]), "+f"(d[3])
                 : "r"(a[0]), "r"(a[1]), "r"(a[2]), "r"(a[3]), "r"(b[0]), "r"(b[1]));
}
// fp16 mma (GEMMs)
__device__ __forceinline__ void mma16816h(float* d, const uint32_t* a, const uint32_t* b) {
    asm volatile("mma.sync.aligned.m16n8k16.row.col.f32.f16.f16.f32 "
                 "{%0,%1,%2,%3}, {%4,%5,%6,%7}, {%8,%9}, {%0,%1,%2,%3};"
                 : "+f"(d[0]), "+f"(d[1]), "+f"(d[2]), "+f"(d[3])
                 : "r"(a[0]), "r"(a[1]), "r"(a[2]), "r"(a[3]), "r"(b[0]), "r"(b[1]));
}

__device__ __forceinline__ void cp16(uint32_t dst, const void* src) {
    asm volatile("cp.async.cg.shared.global [%0], [%1], 16;" :: "r"(dst), "l"(src) : "memory");
}
#define CP_COMMIT() asm volatile("cp.async.commit_group;" ::: "memory")
#define CP_WAIT(n)  asm volatile("cp.async.wait_group %0;" :: "n"(n) : "memory")

// ---------------- split helpers ----------------
__device__ __forceinline__ void split2bf(float a, float b, __nv_bfloat162& h, __nv_bfloat162& l) {
    __nv_bfloat16 ha = __float2bfloat16(a);
    __nv_bfloat16 hb = __float2bfloat16(b);
    h.x = ha; h.y = hb;
    l.x = __float2bfloat16(a - __bfloat162float(ha));
    l.y = __float2bfloat16(b - __bfloat162float(hb));
}
__device__ __forceinline__ void split2h(float a, float b, __half2& h, __half2& l) {
    __half ha = __float2half_rn(a);
    __half hb = __float2half_rn(b);
    h = __halves2half2(ha, hb);
    l = __halves2half2(__float2half_rn(a - __half2float(ha)),
                       __float2half_rn(b - __half2float(hb)));
}

__device__ __forceinline__ float gelu_tanh(float u) {
    float c = 0.7978845608028654f * (u + 0.044715f * u * u * u);
    return 0.5f * u * (1.f + tanhf(c));
}

// ---------------- LayerNorm -> fp16 hi/lo ----------------
__global__ void __launch_bounds__(256)
ln_hl(const float* __restrict__ x, const float* __restrict__ w, const float* __restrict__ b,
      __half* __restrict__ hi, __half* __restrict__ lo)
{
    const int row = blockIdx.x;
    const int t   = threadIdx.x;
    float4 v = ((const float4*)(x + (size_t)row * H_))[t];
    float s  = v.x + v.y + v.z + v.w;
    float sq = v.x*v.x + v.y*v.y + v.z*v.z + v.w*v.w;
    #pragma unroll
    for (int o = 16; o > 0; o >>= 1) {
        s  += __shfl_xor_sync(0xffffffffu, s,  o);
        sq += __shfl_xor_sync(0xffffffffu, sq, o);
    }
    __shared__ float ss[8], ssq[8];
    const int wid = t >> 5, lid = t & 31;
    if (lid == 0) { ss[wid] = s; ssq[wid] = sq; }
    __syncthreads();
    if (wid == 0) {
        float s2 = (lid < 8) ? ss[lid]  : 0.f;
        float q2 = (lid < 8) ? ssq[lid] : 0.f;
        #pragma unroll
        for (int o = 4; o > 0; o >>= 1) {
            s2 += __shfl_xor_sync(0xffffffffu, s2, o);
            q2 += __shfl_xor_sync(0xffffffffu, q2, o);
        }
        if (lid == 0) { ss[0] = s2; ssq[0] = q2; }
    }
    __syncthreads();
    const float mean = ss[0] * (1.f / H_);
    const float var  = ssq[0] * (1.f / H_) - mean * mean;
    const float rstd = rsqrtf(var + 1e-5f);
    float4 wv = ((const float4*)w)[t];
    float4 bv = ((const float4*)b)[t];
    float y0 = (v.x - mean) * rstd * wv.x + bv.x;
    float y1 = (v.y - mean) * rstd * wv.y + bv.y;
    float y2 = (v.z - mean) * rstd * wv.z + bv.z;
    float y3 = (v.w - mean) * rstd * wv.w + bv.w;
    __half2 h0, l0, h1, l1;
    split2h(y0, y1, h0, l0);
    split2h(y2, y3, h1, l1);
    __half2* hp = (__half2*)(hi + (size_t)row * H_);
    __half2* lp = (__half2*)(lo + (size_t)row * H_);
    hp[t*2] = h0; hp[t*2+1] = h1;
    lp[t*2] = l0; lp[t*2+1] = l1;
}

// ---------------- fp32 -> fp16 (weights, single) ----------------
__global__ void __launch_bounds__(256)
cvt16(const float* __restrict__ w, __half* __restrict__ o, int n4)
{
    int i = blockIdx.x * blockDim.x + threadIdx.x;
    if (i >= n4) return;
    float4 v = ((const float4*)w)[i];
    ((__half2*)o)[2*i]   = __floats2half2_rn(v.x, v.y);
    ((__half2*)o)[2*i+1] = __floats2half2_rn(v.z, v.w);
}

// ---------------- fp16 2-term GEMM: C[M,N] = (Ah+Al)[M,K] @ W[N,K]^T + epi ----------------
// MODE 0: +bias -> scatter qkv as bf16 hi/lo (Q scaled log2e/8), layout [(b*16+h), s, d]
// MODE 1: gelu(+bias) -> fp16 hi/lo (Chi/Clo)
// MODE 2: +bias+resid -> fp32 C
// Stage = Ah(16K) + Al(16K) + B(16K) = 48KB, 3 stages.
static constexpr int SMEM_BYTES = 3*49152 + 1024;

template<int MODE>
__global__ void __launch_bounds__(288, 1)
gemm_tc(const __grid_constant__ CUtensorMap mAh,
        const __grid_constant__ CUtensorMap mAl,
        const __grid_constant__ CUtensorMap mB,
        const float* __restrict__ bias, const float* __restrict__ resid,
        float* __restrict__ C, __half* __restrict__ Chi, __half* __restrict__ Clo,
        __nv_bfloat16* __restrict__ qh, __nv_bfloat16* __restrict__ ql,
        __nv_bfloat16* __restrict__ kh, __nv_bfloat16* __restrict__ kl,
        __nv_bfloat16* __restrict__ vh, __nv_bfloat16* __restrict__ vl,
        int N, int nc)
{
    extern __shared__ char smem[];
    const uint32_t sb  = smem_u32(smem);
    const uint32_t st0 = (sb + 64 + 1023) & ~1023u;   // stage base, 1024-aligned
    const int tid = threadIdx.x;

    if (tid == 0) {
        #pragma unroll
        for (int i = 0; i < 3; i++) {
            MBARRIER_INIT(sb + 8*i, 1);         // full: TMA tx-based
            MBARRIER_INIT(sb + 24 + 8*i, 8);    // empty: one arrive per consumer warp
        }
    }
    __syncthreads();

    const int bx = blockIdx.x, by = blockIdx.y;

    if (tid >= 256) {
        if (tid == 256) {
            for (int c = 0; c < nc; c++) {
                const int s = c % 3, r = c / 3;
                const uint32_t stg = st0 + s * 49152;
                if (r > 0) MBARRIER_WAIT_PARITY_RELAXED(sb + 24 + 8*s, (r - 1) & 1);
                MBARRIER_EXPECT_TX(sb + 8*s, 49152u);
                const int kx = c * 64;
                tma2d(stg,         &mAh, kx, by * 128, sb + 8*s);
                tma2d(stg + 16384, &mAl, kx, by * 128, sb + 8*s);
                tma2d(stg + 32768, &mB,  kx, bx * 128, sb + 8*s);
            }
        }
        return;
    }

    const int lane = tid & 31;
    const int wm = (tid >> 5) >> 1;
    const int wn = (tid >> 5) & 1;

    const int arow0 = wm*32 + (lane & 15);
    const int acx   = lane >> 4;
    const int brow0 = wn*64 + (lane & 7) + ((lane >> 4) << 3);
    const int bcx   = (lane >> 3) & 1;

    float acc[2][8][4];
    #pragma unroll
    for (int i = 0; i < 2; i++)
        #pragma unroll
        for (int j = 0; j < 8; j++)
            #pragma unroll
            for (int q = 0; q < 4; q++) acc[i][j][q] = 0.f;

    for (int c = 0; c < nc; c++) {
        const int s = c % 3, r = c / 3;
        const uint32_t stg = st0 + s * 49152;
        MBARRIER_WAIT_PARITY(sb + 8*s, r & 1);

        #pragma unroll
        for (int ks = 0; ks < 4; ks++) {
            uint32_t ah[2][4], al[2][4], bh[4][4];
            #pragma unroll
            for (int i = 0; i < 2; i++) {
                const int row = arow0 + i*16;
                const int cc  = 2*ks + acx;
                const uint32_t off = row*128 + (((uint32_t)(cc ^ (row & 7))) << 4);
                ldsm4(ah[i], stg + off);
                ldsm4(al[i], stg + 16384 + off);
            }
            #pragma unroll
            for (int jt = 0; jt < 4; jt++) {
                const int row = brow0 + jt*16;
                const int cc  = 2*ks + bcx;
                const uint32_t off = row*128 + (((uint32_t)(cc ^ (row & 7))) << 4);
                ldsm4(bh[jt], stg + 32768 + off);
            }
            #pragma unroll
            for (int i = 0; i < 2; i++)
                #pragma unroll
                for (int j = 0; j < 8; j++) {
                    const uint32_t* pb = &bh[j>>1][(j&1)*2];
                    mma16816h(acc[i][j], ah[i], pb);
                    mma16816h(acc[i][j], al[i], pb);
                }
        }
        if (lane == 0) MBARRIER_ARRIVE(sb + 24 + 8*s);
    }

    // ---- epilogue ----
    const int rbase = by*128 + wm*32 + (lane >> 2);
    const int cbase = bx*128 + wn*64 + (lane & 3)*2;
    #pragma unroll
    for (int j = 0; j < 8; j++) {
        const int col = cbase + j*8;
        const float bx0 = bias[col], bx1 = bias[col + 1];
        #pragma unroll
        for (int i = 0; i < 2; i++) {
            #pragma unroll
            for (int half = 0; half < 2; half++) {
                const int rowg = rbase + i*16 + half*8;
                float v0 = acc[i][j][half*2 + 0] + bx0;
                float v1 = acc[i][j][half*2 + 1] + bx1;
                if (MODE == 0) {
                    const int hh   = col / 192;
                    const int rem  = col - hh*192;
                    const int whch = rem >> 6;
                    const int d    = rem & 63;
                    const int ss   = rowg >> 1, bb = rowg & 1;
                    const size_t dst = ((size_t)(bb*16 + hh) * S_ + ss) * HD_ + d;
                    if (whch == 0) { v0 *= 0.18033688011f; v1 *= 0.18033688011f; }  // log2(e)/8
                    __nv_bfloat162 ph2, pl2;
                    split2bf(v0, v1, ph2, pl2);
                    __nv_bfloat16* dh = (whch == 0) ? qh : (whch == 1) ? kh : vh;
                    __nv_bfloat16* dl = (whch == 0) ? ql : (whch == 1) ? kl : vl;
                    *(__nv_bfloat162*)&dh[dst] = ph2;
                    *(__nv_bfloat162*)&dl[dst] = pl2;
                } else if (MODE == 1) {
                    const size_t off = (size_t)rowg * N + col;
                    v0 = gelu_tanh(v0);
                    v1 = gelu_tanh(v1);
                    __half2 h, l;
                    split2h(v0, v1, h, l);
                    *(__half2*)&Chi[off] = h;
                    *(__half2*)&Clo[off] = l;
                } else {
                    const size_t off = (size_t)rowg * N + col;
                    float2 rr = *(const float2*)&resid[off];
                    v0 += rr.x; v1 += rr.y;
                    float2 o; o.x = v0; o.y = v1;
                    *(float2*)&C[off] = o;
                }
            }
        }
    }
}

// ---------------- Flash attention (bf16 HMMA, causal) ----------------
// Output stored as fp16 hi/lo bit patterns (feeds fp16 proj GEMM).
static constexpr int FLASH_SMEM = 96*1024 + 1024;

__global__ void __launch_bounds__(256, 2)
flash_mma(const __nv_bfloat16* __restrict__ Qh, const __nv_bfloat16* __restrict__ Ql,
          const __nv_bfloat16* __restrict__ Kh, const __nv_bfloat16* __restrict__ Kl,
          const __nv_bfloat16* __restrict__ Vh, const __nv_bfloat16* __restrict__ Vl,
          __half* __restrict__ ohi, __half* __restrict__ olo)
{
    extern __shared__ char smem[];
    const uint32_t sq  = (smem_u32(smem) + 1023) & ~1023u;
    const uint32_t sqh = sq, sql = sq + 16384;
    const uint32_t skv = sq + 32768;

    const int tid  = threadIdx.x;
    const int lane = tid & 31;
    const int wq   = tid >> 5;
    const int bhid = blockIdx.y;
    const int bb   = bhid >> 4;
    const int hh   = bhid & 15;
    const int qi   = (int)gridDim.x - 1 - (int)blockIdx.x;
    const int q0   = qi << 7;
    const int ntiles = (q0 >> 6) + 2;

    const size_t hbase = (size_t)bhid * (S_ * HD_);

    #pragma unroll
    for (int i = 0; i < 4; i++) {
        const int idx = tid*4 + i;
        const int row = idx >> 3, cc = idx & 7;
        const uint32_t off = row*128 + (uint32_t)((cc ^ (row & 7)) << 4);
        const size_t src = hbase + (size_t)(q0 + row) * HD_ + cc*8;
        cp16(sqh + off, Qh + src);
        cp16(sql + off, Ql + src);
    }
    {
        #pragma unroll
        for (int i = 0; i < 2; i++) {
            const int idx = tid*2 + i;
            const int row = idx >> 3, cc = idx & 7;
            const uint32_t off = row*128 + (uint32_t)((cc ^ (row & 7)) << 4);
            const size_t src = hbase + (size_t)row * HD_ + cc*8;
            cp16(skv + off,         Kh + src);
            cp16(skv + 8192  + off, Kl + src);
            cp16(skv + 16384 + off, Vh + src);
            cp16(skv + 24576 + off, Vl + src);
        }
    }
    CP_COMMIT();
    CP_WAIT(0);
    __syncthreads();

    uint32_t qfh[4][4], qfl[4][4];
    {
        const int row = wq*16 + (lane & 15);
        #pragma unroll
        for (int ks = 0; ks < 4; ks++) {
            const int cc = 2*ks + (lane >> 4);
            const uint32_t off = row*128 + (uint32_t)((cc ^ (row & 7)) << 4);
            ldsm4(qfh[ks], sqh + off);
            ldsm4(qfl[ks], sql + off);
        }
    }

    float m_i[2] = {-1e30f, -1e30f};
    float l_i[2] = {0.f, 0.f};
    float O[8][4];
    #pragma unroll
    for (int j = 0; j < 8; j++)
        #pragma unroll
        for (int q = 0; q < 4; q++) O[j][q] = 0.f;

    const int my_last_row = q0 + wq*16 + 15;

    for (int kt = 0; kt < ntiles; kt++) {
        const int t0 = kt << 6;
        __syncthreads();
        if (kt + 1 < ntiles) {
            const uint32_t stg = skv + ((kt+1) & 1) * 32768;
            const int tn0 = (kt+1) << 6;
            #pragma unroll
            for (int i = 0; i < 2; i++) {
                const int idx = tid*2 + i;
                const int row = idx >> 3, cc = idx & 7;
                const uint32_t off = row*128 + (uint32_t)((cc ^ (row & 7)) << 4);
                const size_t src = hbase + (size_t)(tn0 + row) * HD_ + cc*8;
                cp16(stg + off,         Kh + src);
                cp16(stg + 8192  + off, Kl + src);
                cp16(stg + 16384 + off, Vh + src);
                cp16(stg + 24576 + off, Vl + src);
            }
        }
        CP_COMMIT();
        CP_WAIT(1);
        __syncthreads();

        if (t0 > my_last_row) continue;

        const uint32_t stg = skv + (kt & 1) * 32768;
        const uint32_t skh = stg, skl = stg + 8192, svh = stg + 16384, svl = stg + 24576;

        float sc[8][4];
        #pragma unroll
        for (int j = 0; j < 8; j++)
            #pragma unroll
            for (int q = 0; q < 4; q++) sc[j][q] = 0.f;

        const int krow_b = (lane & 7) + ((lane >> 4) << 3);
        #pragma unroll
        for (int ks = 0; ks < 4; ks++) {
            const int cc = 2*ks + ((lane >> 3) & 1);
            #pragma unroll
            for (int jt = 0; jt < 4; jt++) {
                uint32_t bhf[4], blf[4];
                const int row = jt*16 + krow_b;
                const uint32_t off = row*128 + (uint32_t)((cc ^ (row & 7)) << 4);
                ldsm4(bhf, skh + off);
                ldsm4(blf, skl + off);
                float* s0 = sc[2*jt];
                float* s1 = sc[2*jt+1];
                mma16816(s0, qfh[ks], &bhf[0]);
                mma16816(s0, qfh[ks], &blf[0]);
                mma16816(s0, qfl[ks], &bhf[0]);
                mma16816(s1, qfh[ks], &bhf[2]);
                mma16816(s1, qfh[ks], &blf[2]);
                mma16816(s1, qfl[ks], &bhf[2]);
            }
        }

        if (kt >= ntiles - 2) {
            const int r0g = q0 + wq*16 + (lane >> 2);
            #pragma unroll
            for (int j = 0; j < 8; j++) {
                const int c0 = t0 + j*8 + (lane & 3)*2;
                if (c0     > r0g)     sc[j][0] = -1e30f;
                if (c0 + 1 > r0g)     sc[j][1] = -1e30f;
                if (c0     > r0g + 8) sc[j][2] = -1e30f;
                if (c0 + 1 > r0g + 8) sc[j][3] = -1e30f;
            }
        }

        #pragma unroll
        for (int v = 0; v < 2; v++) {
            float rm = -1e30f;
            #pragma unroll
            for (int j = 0; j < 8; j++)
                rm = fmaxf(rm, fmaxf(sc[j][2*v], sc[j][2*v+1]));
            rm = fmaxf(rm, __shfl_xor_sync(0xffffffffu, rm, 1));
            rm = fmaxf(rm, __shfl_xor_sync(0xffffffffu, rm, 2));
            const float mnew = fmaxf(m_i[v], rm);
            const float corr = exp2f(m_i[v] - mnew);
            float rs = 0.f;
            #pragma unroll
            for (int j = 0; j < 8; j++) {
                float p0 = exp2f(sc[j][2*v]   - mnew);
                float p1 = exp2f(sc[j][2*v+1] - mnew);
                sc[j][2*v] = p0; sc[j][2*v+1] = p1;
                rs += p0 + p1;
            }
            rs += __shfl_xor_sync(0xffffffffu, rs, 1);
            rs += __shfl_xor_sync(0xffffffffu, rs, 2);
            l_i[v] = l_i[v] * corr + rs;
            m_i[v] = mnew;
            #pragma unroll
            for (int j = 0; j < 8; j++) { O[j][2*v] *= corr; O[j][2*v+1] *= corr; }
        }

        const int vrow_b = (lane & 7) + (((lane >> 3) & 1) << 3);
        #pragma unroll
        for (int kc = 0; kc < 4; kc++) {
            uint32_t pah[4];
            {
                __nv_bfloat162 h2;
                h2 = __float22bfloat162_rn(make_float2(sc[2*kc][0],   sc[2*kc][1]));   pah[0] = *(uint32_t*)&h2;
                h2 = __float22bfloat162_rn(make_float2(sc[2*kc][2],   sc[2*kc][3]));   pah[1] = *(uint32_t*)&h2;
                h2 = __float22bfloat162_rn(make_float2(sc[2*kc+1][0], sc[2*kc+1][1])); pah[2] = *(uint32_t*)&h2;
                h2 = __float22bfloat162_rn(make_float2(sc[2*kc+1][2], sc[2*kc+1][3])); pah[3] = *(uint32_t*)&h2;
            }
            const int vrow = kc*16 + vrow_b;
            #pragma unroll
            for (int p = 0; p < 4; p++) {
                const int cc = 2*p + (lane >> 4);
                const uint32_t off = vrow*128 + (uint32_t)((cc ^ (vrow & 7)) << 4);
                uint32_t vhf[4], vlf[4];
                ldsm4t(vhf, svh + off);
                ldsm4t(vlf, svl + off);
                mma16816(O[2*p],   pah, &vhf[0]);
                mma16816(O[2*p],   pah, &vlf[0]);
                mma16816(O[2*p+1], pah, &vhf[2]);
                mma16816(O[2*p+1], pah, &vlf[2]);
            }
        }
    }

    // ---- epilogue: normalize + fp16 split + store (bit-pattern via uint32) ----
    #pragma unroll
    for (int v = 0; v < 2; v++) {
        const float inv = 1.f / l_i[v];
        const int srow = q0 + wq*16 + (lane >> 2) + v*8;
        const size_t base = ((size_t)srow * B_ + bb) * H_ + hh*HD_ + (lane & 3)*2;
        #pragma unroll
        for (int j = 0; j < 8; j++) {
            float o0 = O[j][2*v]   * inv;
            float o1 = O[j][2*v+1] * inv;
            __half2 h2, l2;
            split2h(o0, o1, h2, l2);
            *(uint32_t*)&ohi[base + j*8] = *(uint32_t*)&h2;
            *(uint32_t*)&olo[base + j*8] = *(uint32_t*)&l2;
        }
    }
}

// ---------------- host ----------------
typedef CUresult (CUDAAPI *TMEncodeFn)(
    CUtensorMap*, CUtensorMapDataType, cuuint32_t, void*,
    const cuuint64_t*, const cuuint64_t*, const cuuint32_t*, const cuuint32_t*,
    CUtensorMapInterleave, CUtensorMapSwizzle, CUtensorMapL2promotion, CUtensorMapFloatOOBfill);

static void enc_map(TMEncodeFn fn, CUtensorMap* m, void* p, uint64_t rows, uint64_t k)
{
    cuuint64_t dims[2]    = {k, rows};
    cuuint64_t strides[1] = {k * 2};
    cuuint32_t box[2]     = {64, 128};
    cuuint32_t es[2]      = {1, 1};
    fn(m, CU_TENSOR_MAP_DATA_TYPE_FLOAT16, 2, p, dims, strides, box, es,
       CU_TENSOR_MAP_INTERLEAVE_NONE, CU_TENSOR_MAP_SWIZZLE_128B,
       CU_TENSOR_MAP_L2_PROMOTION_L2_128B, CU_TENSOR_MAP_FLOAT_OOB_FILL_NONE);
}

extern "C" void kernel_launch(void* const* d_in, const int* in_sizes, int n_in,
                              void* d_out, int out_size)
{
    const float* x     = (const float*)d_in[0];
    const float* ln1w  = (const float*)d_in[1];
    const float* ln1b  = (const float*)d_in[2];
    const float* wqkv  = (const float*)d_in[3];
    const float* bqkv  = (const float*)d_in[4];
    const float* wproj = (const float*)d_in[5];
    const float* bproj = (const float*)d_in[6];
    const float* ln2w  = (const float*)d_in[7];
    const float* ln2b  = (const float*)d_in[8];
    const float* wfc1  = (const float*)d_in[9];
    const float* bfc1  = (const float*)d_in[10];
    const float* wfc2  = (const float*)d_in[11];
    const float* bfc2  = (const float*)d_in[12];
    float* out = (float*)d_out;

    float *x1;
    __half *ah, *al, *mh, *ml, *w16;
    __nv_bfloat16 *qh, *ql, *kh, *kl, *vh, *vl;
    cudaGetSymbolAddress((void**)&x1,  g_x1);
    cudaGetSymbolAddress((void**)&ah,  g_ah);
    cudaGetSymbolAddress((void**)&al,  g_al);
    cudaGetSymbolAddress((void**)&mh,  g_mh);
    cudaGetSymbolAddress((void**)&ml,  g_ml);
    cudaGetSymbolAddress((void**)&w16, g_w);
    cudaGetSymbolAddress((void**)&qh,  g_qh);
    cudaGetSymbolAddress((void**)&ql,  g_ql);
    cudaGetSymbolAddress((void**)&kh,  g_kh);
    cudaGetSymbolAddress((void**)&kl,  g_kl);
    cudaGetSymbolAddress((void**)&vh,  g_vh);
    cudaGetSymbolAddress((void**)&vl,  g_vl);

    TMEncodeFn enc = nullptr;
    cudaDriverEntryPointQueryResult qres;
    cudaGetDriverEntryPointByVersion("cuTensorMapEncodeTiled", (void**)&enc, 12000,
                                     cudaEnableDefault, &qres);

    cudaFuncSetAttribute((const void*)gemm_tc<0>, cudaFuncAttributeMaxDynamicSharedMemorySize, SMEM_BYTES);
    cudaFuncSetAttribute((const void*)gemm_tc<1>, cudaFuncAttributeMaxDynamicSharedMemorySize, SMEM_BYTES);
    cudaFuncSetAttribute((const void*)gemm_tc<2>, cudaFuncAttributeMaxDynamicSharedMemorySize, SMEM_BYTES);
    cudaFuncSetAttribute((const void*)flash_mma,  cudaFuncAttributeMaxDynamicSharedMemorySize, FLASH_SMEM);

    CUtensorMap mAh, mAl, mB;

    // 1) ln1 -> ah/al (fp16 hi/lo)
    ln_hl<<<ROWS, 256>>>(x, ln1w, ln1b, ah, al);
    // 2) qkv GEMM -> scatter Q/K/V bf16 hi/lo : [4096,3072], K=1024
    cvt16<<<(H3*H_/4 + 255)/256, 256>>>(wqkv, w16, H3*H_/4);
    enc_map(enc, &mAh, ah, ROWS, H_);
    enc_map(enc, &mAl, al, ROWS, H_);
    enc_map(enc, &mB,  w16, H3, H_);
    gemm_tc<0><<<dim3(H3/128, ROWS/128), 288, SMEM_BYTES>>>(
        mAh, mAl, mB, bqkv, nullptr, nullptr, nullptr, nullptr,
        qh, ql, kh, kl, vh, vl, H3, H_/64);
    // 3) flash attention (bf16 HMMA) -> ah/al (fp16 hi/lo)
    flash_mma<<<dim3(S_/128, BHN), 256, FLASH_SMEM>>>(qh, ql, kh, kl, vh, vl, ah, al);
    // 4) x1 = x + attn @ wproj^T + b : [4096,1024], K=1024
    cvt16<<<(H_*H_/4 + 255)/256, 256>>>(wproj, w16, H_*H_/4);
    enc_map(enc, &mB, w16, H_, H_);
    gemm_tc<2><<<dim3(H_/128, ROWS/128), 288, SMEM_BYTES>>>(
        mAh, mAl, mB, bproj, x, x1, nullptr, nullptr,
        nullptr, nullptr, nullptr, nullptr, nullptr, nullptr, H_, H_/64);
    // 5) ln2 -> ah/al
    ln_hl<<<ROWS, 256>>>(x1, ln2w, ln2b, ah, al);
    // 6) mid = gelu(ln2 @ wfc1^T + b) -> fp16 hi/lo : [4096,4096], K=1024
    cvt16<<<(H4*H_/4 + 255)/256, 256>>>(wfc1, w16, H4*H_/4);
    enc_map(enc, &mB, w16, H4, H_);
    gemm_tc<1><<<dim3(H4/128, ROWS/128), 288, SMEM_BYTES>>>(
        mAh, mAl, mB, bfc1, nullptr, nullptr, mh, ml,
        nullptr, nullptr, nullptr, nullptr, nullptr, nullptr, H4, H_/64);
    // 7) out = x1 + mid @ wfc2^T + b : [4096,1024], K=4096
    cvt16<<<(H_*H4/4 + 255)/256, 256>>>(wfc2, w16, H_*H4/4);
    enc_map(enc, &mAh, mh, ROWS, H4);
    enc_map(enc, &mAl, ml, ROWS, H4);
    enc_map(enc, &mB,  w16, H_, H4);
    gemm_tc<2><<<dim3(H_/128, ROWS/128), 288, SMEM_BYTES>>>(
        mAh, mAl, mB, bfc2, x1, out, nullptr, nullptr,
        nullptr, nullptr, nullptr, nullptr, nullptr, nullptr, H_, H4/64);
}

// round 8
// speedup vs baseline: 5.4999x; 1.0890x over previous
#include <cuda_runtime.h>
#include <cuda.h>
#include <cuda_bf16.h>
#include <cuda_fp16.h>
#include <math.h>
#include <stdint.h>

// Problem dims (fixed by reference)
#define S_    2048
#define B_    2
#define H_    1024
#define NH_   16
#define HD_   64
#define ROWS  (S_*B_)      // 4096
#define H3    (3*H_)       // 3072
#define H4    (4*H_)       // 4096
#define BHN   (B_*NH_)     // 32

// ---------------- scratch (no allocations allowed) ----------------
__device__ float   g_x1 [ROWS*(size_t)H_];   // fp32 post-attn residual
__device__ __half  g_ah [ROWS*(size_t)H_];   // activation hi (fp16)
__device__ __half  g_al [ROWS*(size_t)H_];   // activation lo (fp16)
__device__ __half  g_mh [ROWS*(size_t)H4];   // mid hi (fc2 input)
__device__ __half  g_ml [ROWS*(size_t)H4];   // mid lo
__device__ __half  g_w  [H4*(size_t)H_];     // weight fp16 (reused)
// Q (hi/lo) + K,V (single) fp16 buffers, layout [(b*16+h), s, d]
__device__ __half  g_qh [BHN*(size_t)S_*HD_];
__device__ __half  g_ql [BHN*(size_t)S_*HD_];
__device__ __half  g_k  [BHN*(size_t)S_*HD_];
__device__ __half  g_v  [BHN*(size_t)S_*HD_];

// ---------------- PTX helpers ----------------
__device__ __forceinline__ uint32_t smem_u32(const void* p) {
    uint32_t a;
    asm("{ .reg .u64 t; cvta.to.shared.u64 t, %1; cvt.u32.u64 %0, t; }" : "=r"(a) : "l"(p));
    return a;
}

#define MBARRIER_INIT(addr, cnt) \
    asm volatile("mbarrier.init.shared.b64 [%0], %1;" :: "r"(addr), "r"(cnt) : "memory")
#define MBARRIER_ARRIVE(addr) \
    asm volatile("mbarrier.arrive.shared.b64 _, [%0];" :: "r"(addr) : "memory")
#define MBARRIER_EXPECT_TX(addr, bytes) \
    asm volatile("mbarrier.arrive.expect_tx.shared.b64 _, [%0], %1;" :: "r"(addr), "r"(bytes) : "memory")

#define MBARRIER_WAIT_PARITY(addr, phase) do { \
    uint32_t _m = (addr); uint32_t _p = (phase); uint32_t _d; \
    asm volatile("{\n\t.reg .pred p;\n\t" \
        "mbarrier.try_wait.parity.acquire.cta.shared::cta.b64 p, [%1], %2;\n\t" \
        "selp.b32 %0, 1, 0, p;\n\t}" : "=r"(_d) : "r"(_m), "r"(_p) : "memory"); \
    if (!_d) { \
        asm volatile("{\n\t.reg .pred P1;\n\t" \
            "WL_%=:\n\t" \
            "mbarrier.try_wait.parity.acquire.cta.shared::cta.b64 P1, [%0], %1, 0x989680;\n\t" \
            "@P1 bra.uni WD_%=;\n\t" \
            "bra.uni WL_%=;\n\t" \
            "WD_%=:\n\t}" :: "r"(_m), "r"(_p) : "memory"); \
    } \
} while (0)

#define MBARRIER_WAIT_PARITY_RELAXED(addr, phase) do { \
    uint32_t _m = (addr); uint32_t _p = (phase); uint32_t _d; \
    asm volatile("{\n\t.reg .pred p;\n\t" \
        "mbarrier.try_wait.parity.relaxed.cta.shared::cta.b64 p, [%1], %2, 0x989680;\n\t" \
        "selp.b32 %0, 1, 0, p;\n\t}" : "=r"(_d) : "r"(_m), "r"(_p) : "memory"); \
    if (!_d) { \
        asm volatile("{\n\t.reg .pred P1;\n\t" \
            "WL_%=:\n\t" \
            "mbarrier.try_wait.parity.relaxed.cta.shared::cta.b64 P1, [%0], %1, 0x989680;\n\t" \
            "@P1 bra.uni WD_%=;\n\t" \
            "bra.uni WL_%=;\n\t" \
            "WD_%=:\n\t}" :: "r"(_m), "r"(_p) : "memory"); \
    } \
} while (0)

__device__ __forceinline__ void tma2d(uint32_t dst, const void* map, int x, int y, uint32_t mbar) {
    asm volatile("cp.async.bulk.tensor.2d.shared::cta.global.tile.mbarrier::complete_tx::bytes "
                 "[%0], [%1, {%2, %3}], [%4];"
                 :: "r"(dst), "l"(map), "r"(x), "r"(y), "r"(mbar) : "memory");
}

__device__ __forceinline__ void ldsm4(uint32_t* r, uint32_t addr) {
    asm volatile("ldmatrix.sync.aligned.m8n8.x4.shared.b16 {%0,%1,%2,%3}, [%4];"
                 : "=r"(r[0]), "=r"(r[1]), "=r"(r[2]), "=r"(r[3]) : "r"(addr));
}
__device__ __forceinline__ void ldsm4t(uint32_t* r, uint32_t addr) {
    asm volatile("ldmatrix.sync.aligned.m8n8.x4.trans.shared.b16 {%0,%1,%2,%3}, [%4];"
                 : "=r"(r[0]), "=r"(r[1]), "=r"(r[2]), "=r"(r[3]) : "r"(addr));
}

// fp16 mma
__device__ __forceinline__ void mma16816h(float* d, const uint32_t* a, const uint32_t* b) {
    asm volatile("mma.sync.aligned.m16n8k16.row.col.f32.f16.f16.f32 "
                 "{%0,%1,%2,%3}, {%4,%5,%6,%7}, {%8,%9}, {%0,%1,%2,%3};"
                 : "+f"(d[0]), "+f"(d[1]), "+f"(d[2]), "+f"(d[3])
                 : "r"(a[0]), "r"(a[1]), "r"(a[2]), "r"(a[3]), "r"(b[0]), "r"(b[1]));
}

__device__ __forceinline__ void cp16(uint32_t dst, const void* src) {
    asm volatile("cp.async.cg.shared.global [%0], [%1], 16;" :: "r"(dst), "l"(src) : "memory");
}
#define CP_COMMIT() asm volatile("cp.async.commit_group;" ::: "memory")
#define CP_WAIT(n)  asm volatile("cp.async.wait_group %0;" :: "n"(n) : "memory")

// ---------------- split helpers ----------------
__device__ __forceinline__ void split2h(float a, float b, __half2& h, __half2& l) {
    __half ha = __float2half_rn(a);
    __half hb = __float2half_rn(b);
    h = __halves2half2(ha, hb);
    l = __halves2half2(__float2half_rn(a - __half2float(ha)),
                       __float2half_rn(b - __half2float(hb)));
}

__device__ __forceinline__ float gelu_tanh(float u) {
    float c = 0.7978845608028654f * (u + 0.044715f * u * u * u);
    return 0.5f * u * (1.f + tanhf(c));
}

// ---------------- LayerNorm -> fp16 hi/lo ----------------
__global__ void __launch_bounds__(256)
ln_hl(const float* __restrict__ x, const float* __restrict__ w, const float* __restrict__ b,
      __half* __restrict__ hi, __half* __restrict__ lo)
{
    const int row = blockIdx.x;
    const int t   = threadIdx.x;
    float4 v = ((const float4*)(x + (size_t)row * H_))[t];
    float s  = v.x + v.y + v.z + v.w;
    float sq = v.x*v.x + v.y*v.y + v.z*v.z + v.w*v.w;
    #pragma unroll
    for (int o = 16; o > 0; o >>= 1) {
        s  += __shfl_xor_sync(0xffffffffu, s,  o);
        sq += __shfl_xor_sync(0xffffffffu, sq, o);
    }
    __shared__ float ss[8], ssq[8];
    const int wid = t >> 5, lid = t & 31;
    if (lid == 0) { ss[wid] = s; ssq[wid] = sq; }
    __syncthreads();
    if (wid == 0) {
        float s2 = (lid < 8) ? ss[lid]  : 0.f;
        float q2 = (lid < 8) ? ssq[lid] : 0.f;
        #pragma unroll
        for (int o = 4; o > 0; o >>= 1) {
            s2 += __shfl_xor_sync(0xffffffffu, s2, o);
            q2 += __shfl_xor_sync(0xffffffffu, q2, o);
        }
        if (lid == 0) { ss[0] = s2; ssq[0] = q2; }
    }
    __syncthreads();
    const float mean = ss[0] * (1.f / H_);
    const float var  = ssq[0] * (1.f / H_) - mean * mean;
    const float rstd = rsqrtf(var + 1e-5f);
    float4 wv = ((const float4*)w)[t];
    float4 bv = ((const float4*)b)[t];
    float y0 = (v.x - mean) * rstd * wv.x + bv.x;
    float y1 = (v.y - mean) * rstd * wv.y + bv.y;
    float y2 = (v.z - mean) * rstd * wv.z + bv.z;
    float y3 = (v.w - mean) * rstd * wv.w + bv.w;
    __half2 h0, l0, h1, l1;
    split2h(y0, y1, h0, l0);
    split2h(y2, y3, h1, l1);
    __half2* hp = (__half2*)(hi + (size_t)row * H_);
    __half2* lp = (__half2*)(lo + (size_t)row * H_);
    hp[t*2] = h0; hp[t*2+1] = h1;
    lp[t*2] = l0; lp[t*2+1] = l1;
}

// ---------------- fp32 -> fp16 (weights, single) ----------------
__global__ void __launch_bounds__(256)
cvt16(const float* __restrict__ w, __half* __restrict__ o, int n4)
{
    int i = blockIdx.x * blockDim.x + threadIdx.x;
    if (i >= n4) return;
    float4 v = ((const float4*)w)[i];
    ((__half2*)o)[2*i]   = __floats2half2_rn(v.x, v.y);
    ((__half2*)o)[2*i+1] = __floats2half2_rn(v.z, v.w);
}

// ---------------- fp16 2-term GEMM: C[M,N] = (Ah+Al)[M,K] @ W[N,K]^T + epi ----------------
// MODE 0: +bias -> scatter Q (hi/lo, scaled log2e/8) and K,V (single fp16)
// MODE 1: gelu(+bias) -> fp16 hi/lo (Chi/Clo)
// MODE 2: +bias+resid -> fp32 C
static constexpr int SMEM_BYTES = 3*49152 + 1024;

template<int MODE>
__global__ void __launch_bounds__(288, 1)
gemm_tc(const __grid_constant__ CUtensorMap mAh,
        const __grid_constant__ CUtensorMap mAl,
        const __grid_constant__ CUtensorMap mB,
        const float* __restrict__ bias, const float* __restrict__ resid,
        float* __restrict__ C, __half* __restrict__ Chi, __half* __restrict__ Clo,
        __half* __restrict__ qh, __half* __restrict__ ql,
        __half* __restrict__ kk, __half* __restrict__ vv,
        int N, int nc)
{
    extern __shared__ char smem[];
    const uint32_t sb  = smem_u32(smem);
    const uint32_t st0 = (sb + 64 + 1023) & ~1023u;
    const int tid = threadIdx.x;

    if (tid == 0) {
        #pragma unroll
        for (int i = 0; i < 3; i++) {
            MBARRIER_INIT(sb + 8*i, 1);
            MBARRIER_INIT(sb + 24 + 8*i, 8);
        }
    }
    __syncthreads();

    const int bx = blockIdx.x, by = blockIdx.y;

    if (tid >= 256) {
        if (tid == 256) {
            for (int c = 0; c < nc; c++) {
                const int s = c % 3, r = c / 3;
                const uint32_t stg = st0 + s * 49152;
                if (r > 0) MBARRIER_WAIT_PARITY_RELAXED(sb + 24 + 8*s, (r - 1) & 1);
                MBARRIER_EXPECT_TX(sb + 8*s, 49152u);
                const int kx = c * 64;
                tma2d(stg,         &mAh, kx, by * 128, sb + 8*s);
                tma2d(stg + 16384, &mAl, kx, by * 128, sb + 8*s);
                tma2d(stg + 32768, &mB,  kx, bx * 128, sb + 8*s);
            }
        }
        return;
    }

    const int lane = tid & 31;
    const int wm = (tid >> 5) >> 1;
    const int wn = (tid >> 5) & 1;

    const int arow0 = wm*32 + (lane & 15);
    const int acx   = lane >> 4;
    const int brow0 = wn*64 + (lane & 7) + ((lane >> 4) << 3);
    const int bcx   = (lane >> 3) & 1;

    float acc[2][8][4];
    #pragma unroll
    for (int i = 0; i < 2; i++)
        #pragma unroll
        for (int j = 0; j < 8; j++)
            #pragma unroll
            for (int q = 0; q < 4; q++) acc[i][j][q] = 0.f;

    for (int c = 0; c < nc; c++) {
        const int s = c % 3, r = c / 3;
        const uint32_t stg = st0 + s * 49152;
        MBARRIER_WAIT_PARITY(sb + 8*s, r & 1);

        #pragma unroll
        for (int ks = 0; ks < 4; ks++) {
            uint32_t ah[2][4], al[2][4], bh[4][4];
            #pragma unroll
            for (int i = 0; i < 2; i++) {
                const int row = arow0 + i*16;
                const int cc  = 2*ks + acx;
                const uint32_t off = row*128 + (((uint32_t)(cc ^ (row & 7))) << 4);
                ldsm4(ah[i], stg + off);
                ldsm4(al[i], stg + 16384 + off);
            }
            #pragma unroll
            for (int jt = 0; jt < 4; jt++) {
                const int row = brow0 + jt*16;
                const int cc  = 2*ks + bcx;
                const uint32_t off = row*128 + (((uint32_t)(cc ^ (row & 7))) << 4);
                ldsm4(bh[jt], stg + 32768 + off);
            }
            #pragma unroll
            for (int i = 0; i < 2; i++)
                #pragma unroll
                for (int j = 0; j < 8; j++) {
                    const uint32_t* pb = &bh[j>>1][(j&1)*2];
                    mma16816h(acc[i][j], ah[i], pb);
                    mma16816h(acc[i][j], al[i], pb);
                }
        }
        if (lane == 0) MBARRIER_ARRIVE(sb + 24 + 8*s);
    }

    // ---- epilogue ----
    const int rbase = by*128 + wm*32 + (lane >> 2);
    const int cbase = bx*128 + wn*64 + (lane & 3)*2;
    #pragma unroll
    for (int j = 0; j < 8; j++) {
        const int col = cbase + j*8;
        const float bx0 = bias[col], bx1 = bias[col + 1];
        #pragma unroll
        for (int i = 0; i < 2; i++) {
            #pragma unroll
            for (int half = 0; half < 2; half++) {
                const int rowg = rbase + i*16 + half*8;
                float v0 = acc[i][j][half*2 + 0] + bx0;
                float v1 = acc[i][j][half*2 + 1] + bx1;
                if (MODE == 0) {
                    const int hh   = col / 192;
                    const int rem  = col - hh*192;
                    const int whch = rem >> 6;
                    const int d    = rem & 63;
                    const int ss   = rowg >> 1, bb = rowg & 1;
                    const size_t dst = ((size_t)(bb*16 + hh) * S_ + ss) * HD_ + d;
                    if (whch == 0) {
                        v0 *= 0.18033688011f; v1 *= 0.18033688011f;   // log2(e)/8
                        __half2 ph2, pl2;
                        split2h(v0, v1, ph2, pl2);
                        *(__half2*)&qh[dst] = ph2;
                        *(__half2*)&ql[dst] = pl2;
                    } else {
                        __half* dp = (whch == 1) ? kk : vv;
                        *(__half2*)&dp[dst] = __floats2half2_rn(v0, v1);
                    }
                } else if (MODE == 1) {
                    const size_t off = (size_t)rowg * N + col;
                    v0 = gelu_tanh(v0);
                    v1 = gelu_tanh(v1);
                    __half2 h, l;
                    split2h(v0, v1, h, l);
                    *(__half2*)&Chi[off] = h;
                    *(__half2*)&Clo[off] = l;
                } else {
                    const size_t off = (size_t)rowg * N + col;
                    float2 rr = *(const float2*)&resid[off];
                    v0 += rr.x; v1 += rr.y;
                    float2 o; o.x = v0; o.y = v1;
                    *(float2*)&C[off] = o;
                }
            }
        }
    }
}

// ---------------- Flash attention (fp16 HMMA, causal) ----------------
// BQ=128, BKV=64, 8 warps, 2 CTAs/SM.
// QK^T: (Qh+Ql) @ K (2-term). PV: P @ V (1-term). Scores in log2 units; exp2f.
// smem: Qh(16K) Ql(16K) + 2 x [K(8K) V(8K)] = 80KB dynamic.
static constexpr int FLASH_SMEM = 80*1024 + 1024;

__global__ void __launch_bounds__(256, 2)
flash_mma(const __half* __restrict__ Qh, const __half* __restrict__ Ql,
          const __half* __restrict__ K,  const __half* __restrict__ V,
          __half* __restrict__ ohi, __half* __restrict__ olo)
{
    extern __shared__ char smem[];
    const uint32_t sq  = (smem_u32(smem) + 1023) & ~1023u;
    const uint32_t sqh = sq, sql = sq + 16384;
    const uint32_t skv = sq + 32768;   // + buf*16384; within: K 0, V 8192

    const int tid  = threadIdx.x;
    const int lane = tid & 31;
    const int wq   = tid >> 5;
    const int bhid = blockIdx.y;
    const int bb   = bhid >> 4;
    const int hh   = bhid & 15;
    const int qi   = (int)gridDim.x - 1 - (int)blockIdx.x;
    const int q0   = qi << 7;
    const int ntiles = (q0 >> 6) + 2;

    const size_t hbase = (size_t)bhid * (S_ * HD_);

    // ---- prologue: load Q (hi/lo) + KV tile 0 ----
    #pragma unroll
    for (int i = 0; i < 4; i++) {
        const int idx = tid*4 + i;
        const int row = idx >> 3, cc = idx & 7;
        const uint32_t off = row*128 + (uint32_t)((cc ^ (row & 7)) << 4);
        const size_t src = hbase + (size_t)(q0 + row) * HD_ + cc*8;
        cp16(sqh + off, Qh + src);
        cp16(sql + off, Ql + src);
    }
    {
        #pragma unroll
        for (int i = 0; i < 2; i++) {
            const int idx = tid*2 + i;
            const int row = idx >> 3, cc = idx & 7;
            const uint32_t off = row*128 + (uint32_t)((cc ^ (row & 7)) << 4);
            const size_t src = hbase + (size_t)row * HD_ + cc*8;
            cp16(skv + off,        K + src);
            cp16(skv + 8192 + off, V + src);
        }
    }
    CP_COMMIT();
    CP_WAIT(0);
    __syncthreads();

    // ---- Q fragments (registers) ----
    uint32_t qfh[4][4], qfl[4][4];
    {
        const int row = wq*16 + (lane & 15);
        #pragma unroll
        for (int ks = 0; ks < 4; ks++) {
            const int cc = 2*ks + (lane >> 4);
            const uint32_t off = row*128 + (uint32_t)((cc ^ (row & 7)) << 4);
            ldsm4(qfh[ks], sqh + off);
            ldsm4(qfl[ks], sql + off);
        }
    }

    float m_i[2] = {-1e30f, -1e30f};
    float l_i[2] = {0.f, 0.f};
    float O[8][4];
    #pragma unroll
    for (int j = 0; j < 8; j++)
        #pragma unroll
        for (int q = 0; q < 4; q++) O[j][q] = 0.f;

    const int my_last_row = q0 + wq*16 + 15;

    for (int kt = 0; kt < ntiles; kt++) {
        const int t0 = kt << 6;
        __syncthreads();
        if (kt + 1 < ntiles) {
            const uint32_t stg = skv + ((kt+1) & 1) * 16384;
            const int tn0 = (kt+1) << 6;
            #pragma unroll
            for (int i = 0; i < 2; i++) {
                const int idx = tid*2 + i;
                const int row = idx >> 3, cc = idx & 7;
                const uint32_t off = row*128 + (uint32_t)((cc ^ (row & 7)) << 4);
                const size_t src = hbase + (size_t)(tn0 + row) * HD_ + cc*8;
                cp16(stg + off,        K + src);
                cp16(stg + 8192 + off, V + src);
            }
        }
        CP_COMMIT();
        CP_WAIT(1);
        __syncthreads();

        if (t0 > my_last_row) continue;

        const uint32_t stg = skv + (kt & 1) * 16384;
        const uint32_t sk = stg, sv = stg + 8192;

        // ---- scores S = (Qh + Ql) K^T (16x64 per warp) ----
        float sc[8][4];
        #pragma unroll
        for (int j = 0; j < 8; j++)
            #pragma unroll
            for (int q = 0; q < 4; q++) sc[j][q] = 0.f;

        const int krow_b = (lane & 7) + ((lane >> 4) << 3);
        #pragma unroll
        for (int ks = 0; ks < 4; ks++) {
            const int cc = 2*ks + ((lane >> 3) & 1);
            #pragma unroll
            for (int jt = 0; jt < 4; jt++) {
                uint32_t bf[4];
                const int row = jt*16 + krow_b;
                const uint32_t off = row*128 + (uint32_t)((cc ^ (row & 7)) << 4);
                ldsm4(bf, sk + off);
                float* s0 = sc[2*jt];
                float* s1 = sc[2*jt+1];
                mma16816h(s0, qfh[ks], &bf[0]);
                mma16816h(s0, qfl[ks], &bf[0]);
                mma16816h(s1, qfh[ks], &bf[2]);
                mma16816h(s1, qfl[ks], &bf[2]);
            }
        }

        // ---- causal mask (last two kv tiles only) ----
        if (kt >= ntiles - 2) {
            const int r0g = q0 + wq*16 + (lane >> 2);
            #pragma unroll
            for (int j = 0; j < 8; j++) {
                const int c0 = t0 + j*8 + (lane & 3)*2;
                if (c0     > r0g)     sc[j][0] = -1e30f;
                if (c0 + 1 > r0g)     sc[j][1] = -1e30f;
                if (c0     > r0g + 8) sc[j][2] = -1e30f;
                if (c0 + 1 > r0g + 8) sc[j][3] = -1e30f;
            }
        }

        // ---- online softmax in log2 domain ----
        #pragma unroll
        for (int v = 0; v < 2; v++) {
            float rm = -1e30f;
            #pragma unroll
            for (int j = 0; j < 8; j++)
                rm = fmaxf(rm, fmaxf(sc[j][2*v], sc[j][2*v+1]));
            rm = fmaxf(rm, __shfl_xor_sync(0xffffffffu, rm, 1));
            rm = fmaxf(rm, __shfl_xor_sync(0xffffffffu, rm, 2));
            const float mnew = fmaxf(m_i[v], rm);
            const float corr = exp2f(m_i[v] - mnew);
            float rs = 0.f;
            #pragma unroll
            for (int j = 0; j < 8; j++) {
                float p0 = exp2f(sc[j][2*v]   - mnew);
                float p1 = exp2f(sc[j][2*v+1] - mnew);
                sc[j][2*v] = p0; sc[j][2*v+1] = p1;
                rs += p0 + p1;
            }
            rs += __shfl_xor_sync(0xffffffffu, rs, 1);
            rs += __shfl_xor_sync(0xffffffffu, rs, 2);
            l_i[v] = l_i[v] * corr + rs;
            m_i[v] = mnew;
            #pragma unroll
            for (int j = 0; j < 8; j++) { O[j][2*v] *= corr; O[j][2*v+1] *= corr; }
        }

        // ---- O += P V (single fp16 term) ----
        const int vrow_b = (lane & 7) + (((lane >> 3) & 1) << 3);
        #pragma unroll
        for (int kc = 0; kc < 4; kc++) {
            uint32_t pah[4];
            {
                __half2 h2;
                h2 = __floats2half2_rn(sc[2*kc][0],   sc[2*kc][1]);   pah[0] = *(uint32_t*)&h2;
                h2 = __floats2half2_rn(sc[2*kc][2],   sc[2*kc][3]);   pah[1] = *(uint32_t*)&h2;
                h2 = __floats2half2_rn(sc[2*kc+1][0], sc[2*kc+1][1]); pah[2] = *(uint32_t*)&h2;
                h2 = __floats2half2_rn(sc[2*kc+1][2], sc[2*kc+1][3]); pah[3] = *(uint32_t*)&h2;
            }
            const int vrow = kc*16 + vrow_b;
            #pragma unroll
            for (int p = 0; p < 4; p++) {
                const int cc = 2*p + (lane >> 4);
                const uint32_t off = vrow*128 + (uint32_t)((cc ^ (vrow & 7)) << 4);
                uint32_t vf[4];
                ldsm4t(vf, sv + off);
                mma16816h(O[2*p],   pah, &vf[0]);
                mma16816h(O[2*p+1], pah, &vf[2]);
            }
        }
    }

    // ---- epilogue: normalize + fp16 split + store ----
    #pragma unroll
    for (int v = 0; v < 2; v++) {
        const float inv = 1.f / l_i[v];
        const int srow = q0 + wq*16 + (lane >> 2) + v*8;
        const size_t base = ((size_t)srow * B_ + bb) * H_ + hh*HD_ + (lane & 3)*2;
        #pragma unroll
        for (int j = 0; j < 8; j++) {
            float o0 = O[j][2*v]   * inv;
            float o1 = O[j][2*v+1] * inv;
            __half2 h2, l2;
            split2h(o0, o1, h2, l2);
            *(uint32_t*)&ohi[base + j*8] = *(uint32_t*)&h2;
            *(uint32_t*)&olo[base + j*8] = *(uint32_t*)&l2;
        }
    }
}

// ---------------- host ----------------
typedef CUresult (CUDAAPI *TMEncodeFn)(
    CUtensorMap*, CUtensorMapDataType, cuuint32_t, void*,
    const cuuint64_t*, const cuuint64_t*, const cuuint32_t*, const cuuint32_t*,
    CUtensorMapInterleave, CUtensorMapSwizzle, CUtensorMapL2promotion, CUtensorMapFloatOOBfill);

static void enc_map(TMEncodeFn fn, CUtensorMap* m, void* p, uint64_t rows, uint64_t k)
{
    cuuint64_t dims[2]    = {k, rows};
    cuuint64_t strides[1] = {k * 2};
    cuuint32_t box[2]     = {64, 128};
    cuuint32_t es[2]      = {1, 1};
    fn(m, CU_TENSOR_MAP_DATA_TYPE_FLOAT16, 2, p, dims, strides, box, es,
       CU_TENSOR_MAP_INTERLEAVE_NONE, CU_TENSOR_MAP_SWIZZLE_128B,
       CU_TENSOR_MAP_L2_PROMOTION_L2_128B, CU_TENSOR_MAP_FLOAT_OOB_FILL_NONE);
}

extern "C" void kernel_launch(void* const* d_in, const int* in_sizes, int n_in,
                              void* d_out, int out_size)
{
    const float* x     = (const float*)d_in[0];
    const float* ln1w  = (const float*)d_in[1];
    const float* ln1b  = (const float*)d_in[2];
    const float* wqkv  = (const float*)d_in[3];
    const float* bqkv  = (const float*)d_in[4];
    const float* wproj = (const float*)d_in[5];
    const float* bproj = (const float*)d_in[6];
    const float* ln2w  = (const float*)d_in[7];
    const float* ln2b  = (const float*)d_in[8];
    const float* wfc1  = (const float*)d_in[9];
    const float* bfc1  = (const float*)d_in[10];
    const float* wfc2  = (const float*)d_in[11];
    const float* bfc2  = (const float*)d_in[12];
    float* out = (float*)d_out;

    float *x1;
    __half *ah, *al, *mh, *ml, *w16, *qh, *ql, *kk, *vv;
    cudaGetSymbolAddress((void**)&x1,  g_x1);
    cudaGetSymbolAddress((void**)&ah,  g_ah);
    cudaGetSymbolAddress((void**)&al,  g_al);
    cudaGetSymbolAddress((void**)&mh,  g_mh);
    cudaGetSymbolAddress((void**)&ml,  g_ml);
    cudaGetSymbolAddress((void**)&w16, g_w);
    cudaGetSymbolAddress((void**)&qh,  g_qh);
    cudaGetSymbolAddress((void**)&ql,  g_ql);
    cudaGetSymbolAddress((void**)&kk,  g_k);
    cudaGetSymbolAddress((void**)&vv,  g_v);

    TMEncodeFn enc = nullptr;
    cudaDriverEntryPointQueryResult qres;
    cudaGetDriverEntryPointByVersion("cuTensorMapEncodeTiled", (void**)&enc, 12000,
                                     cudaEnableDefault, &qres);

    cudaFuncSetAttribute((const void*)gemm_tc<0>, cudaFuncAttributeMaxDynamicSharedMemorySize, SMEM_BYTES);
    cudaFuncSetAttribute((const void*)gemm_tc<1>, cudaFuncAttributeMaxDynamicSharedMemorySize, SMEM_BYTES);
    cudaFuncSetAttribute((const void*)gemm_tc<2>, cudaFuncAttributeMaxDynamicSharedMemorySize, SMEM_BYTES);
    cudaFuncSetAttribute((const void*)flash_mma,  cudaFuncAttributeMaxDynamicSharedMemorySize, FLASH_SMEM);

    CUtensorMap mAh, mAl, mB;

    // 1) ln1 -> ah/al (fp16 hi/lo)
    ln_hl<<<ROWS, 256>>>(x, ln1w, ln1b, ah, al);
    // 2) qkv GEMM -> scatter Q hi/lo + K,V single : [4096,3072], K=1024
    cvt16<<<(H3*H_/4 + 255)/256, 256>>>(wqkv, w16, H3*H_/4);
    enc_map(enc, &mAh, ah, ROWS, H_);
    enc_map(enc, &mAl, al, ROWS, H_);
    enc_map(enc, &mB,  w16, H3, H_);
    gemm_tc<0><<<dim3(H3/128, ROWS/128), 288, SMEM_BYTES>>>(
        mAh, mAl, mB, bqkv, nullptr, nullptr, nullptr, nullptr,
        qh, ql, kk, vv, H3, H_/64);
    // 3) flash attention (fp16 HMMA) -> ah/al (fp16 hi/lo)
    flash_mma<<<dim3(S_/128, BHN), 256, FLASH_SMEM>>>(qh, ql, kk, vv, ah, al);
    // 4) x1 = x + attn @ wproj^T + b : [4096,1024], K=1024
    cvt16<<<(H_*H_/4 + 255)/256, 256>>>(wproj, w16, H_*H_/4);
    enc_map(enc, &mB, w16, H_, H_);
    gemm_tc<2><<<dim3(H_/128, ROWS/128), 288, SMEM_BYTES>>>(
        mAh, mAl, mB, bproj, x, x1, nullptr, nullptr,
        nullptr, nullptr, nullptr, nullptr, H_, H_/64);
    // 5) ln2 -> ah/al
    ln_hl<<<ROWS, 256>>>(x1, ln2w, ln2b, ah, al);
    // 6) mid = gelu(ln2 @ wfc1^T + b) -> fp16 hi/lo : [4096,4096], K=1024
    cvt16<<<(H4*H_/4 + 255)/256, 256>>>(wfc1, w16, H4*H_/4);
    enc_map(enc, &mB, w16, H4, H_);
    gemm_tc<1><<<dim3(H4/128, ROWS/128), 288, SMEM_BYTES>>>(
        mAh, mAl, mB, bfc1, nullptr, nullptr, mh, ml,
        nullptr, nullptr, nullptr, nullptr, H4, H_/64);
    // 7) out = x1 + mid @ wfc2^T + b : [4096,1024], K=4096
    cvt16<<<(H_*H4/4 + 255)/256, 256>>>(wfc2, w16, H_*H4/4);
    enc_map(enc, &mAh, mh, ROWS, H4);
    enc_map(enc, &mAl, ml, ROWS, H4);
    enc_map(enc, &mB,  w16, H_, H4);
    gemm_tc<2><<<dim3(H_/128, ROWS/128), 288, SMEM_BYTES>>>(
        mAh, mAl, mB, bfc2, x1, out, nullptr, nullptr,
        nullptr, nullptr, nullptr, nullptr, H_, H4/64);
}

// round 9
// speedup vs baseline: 8.7362x; 1.5884x over previous
#include <cuda_runtime.h>
#include <cuda.h>
#include <cuda_fp16.h>
#include <math.h>
#include <stdint.h>

// Problem dims (fixed by reference)
#define S_    2048
#define B_    2
#define H_    1024
#define NH_   16
#define HD_   64
#define ROWS  (S_*B_)      // 4096
#define H3    (3*H_)       // 3072
#define H4    (4*H_)       // 4096
#define BHN   (B_*NH_)     // 32

// ---------------- scratch (no allocations allowed) ----------------
__device__ float   g_x1   [ROWS*(size_t)H_];   // fp32 post-attn residual
__device__ __half  g_a    [ROWS*(size_t)H_];   // activation (single fp16)
__device__ __half  g_m    [ROWS*(size_t)H4];   // mid (fc2 input)
__device__ __half  g_wqkv [H3*(size_t)H_];
__device__ __half  g_wproj[H_*(size_t)H_];
__device__ __half  g_wfc1 [H4*(size_t)H_];
__device__ __half  g_wfc2 [H_*(size_t)H4];
// Q,K,V single fp16, layout [(b*16+h), s, d]
__device__ __half  g_q [BHN*(size_t)S_*HD_];
__device__ __half  g_k [BHN*(size_t)S_*HD_];
__device__ __half  g_v [BHN*(size_t)S_*HD_];

// ---------------- PTX helpers ----------------
__device__ __forceinline__ uint32_t smem_u32(const void* p) {
    uint32_t a;
    asm("{ .reg .u64 t; cvta.to.shared.u64 t, %1; cvt.u32.u64 %0, t; }" : "=r"(a) : "l"(p));
    return a;
}

#define MBARRIER_INIT(addr, cnt) \
    asm volatile("mbarrier.init.shared.b64 [%0], %1;" :: "r"(addr), "r"(cnt) : "memory")
#define MBARRIER_ARRIVE(addr) \
    asm volatile("mbarrier.arrive.shared.b64 _, [%0];" :: "r"(addr) : "memory")
#define MBARRIER_EXPECT_TX(addr, bytes) \
    asm volatile("mbarrier.arrive.expect_tx.shared.b64 _, [%0], %1;" :: "r"(addr), "r"(bytes) : "memory")

#define MBARRIER_WAIT_PARITY(addr, phase) do { \
    uint32_t _m = (addr); uint32_t _p = (phase); uint32_t _d; \
    asm volatile("{\n\t.reg .pred p;\n\t" \
        "mbarrier.try_wait.parity.acquire.cta.shared::cta.b64 p, [%1], %2;\n\t" \
        "selp.b32 %0, 1, 0, p;\n\t}" : "=r"(_d) : "r"(_m), "r"(_p) : "memory"); \
    if (!_d) { \
        asm volatile("{\n\t.reg .pred P1;\n\t" \
            "WL_%=:\n\t" \
            "mbarrier.try_wait.parity.acquire.cta.shared::cta.b64 P1, [%0], %1, 0x989680;\n\t" \
            "@P1 bra.uni WD_%=;\n\t" \
            "bra.uni WL_%=;\n\t" \
            "WD_%=:\n\t}" :: "r"(_m), "r"(_p) : "memory"); \
    } \
} while (0)

#define MBARRIER_WAIT_PARITY_RELAXED(addr, phase) do { \
    uint32_t _m = (addr); uint32_t _p = (phase); uint32_t _d; \
    asm volatile("{\n\t.reg .pred p;\n\t" \
        "mbarrier.try_wait.parity.relaxed.cta.shared::cta.b64 p, [%1], %2, 0x989680;\n\t" \
        "selp.b32 %0, 1, 0, p;\n\t}" : "=r"(_d) : "r"(_m), "r"(_p) : "memory"); \
    if (!_d) { \
        asm volatile("{\n\t.reg .pred P1;\n\t" \
            "WL_%=:\n\t" \
            "mbarrier.try_wait.parity.relaxed.cta.shared::cta.b64 P1, [%0], %1, 0x989680;\n\t" \
            "@P1 bra.uni WD_%=;\n\t" \
            "bra.uni WL_%=;\n\t" \
            "WD_%=:\n\t}" :: "r"(_m), "r"(_p) : "memory"); \
    } \
} while (0)

__device__ __forceinline__ void tma2d(uint32_t dst, const void* map, int x, int y, uint32_t mbar) {
    asm volatile("cp.async.bulk.tensor.2d.shared::cta.global.tile.mbarrier::complete_tx::bytes "
                 "[%0], [%1, {%2, %3}], [%4];"
                 :: "r"(dst), "l"(map), "r"(x), "r"(y), "r"(mbar) : "memory");
}

__device__ __forceinline__ void ldsm4(uint32_t* r, uint32_t addr) {
    asm volatile("ldmatrix.sync.aligned.m8n8.x4.shared.b16 {%0,%1,%2,%3}, [%4];"
                 : "=r"(r[0]), "=r"(r[1]), "=r"(r[2]), "=r"(r[3]) : "r"(addr));
}
__device__ __forceinline__ void ldsm4t(uint32_t* r, uint32_t addr) {
    asm volatile("ldmatrix.sync.aligned.m8n8.x4.trans.shared.b16 {%0,%1,%2,%3}, [%4];"
                 : "=r"(r[0]), "=r"(r[1]), "=r"(r[2]), "=r"(r[3]) : "r"(addr));
}

__device__ __forceinline__ void mma16816h(float* d, const uint32_t* a, const uint32_t* b) {
    asm volatile("mma.sync.aligned.m16n8k16.row.col.f32.f16.f16.f32 "
                 "{%0,%1,%2,%3}, {%4,%5,%6,%7}, {%8,%9}, {%0,%1,%2,%3};"
                 : "+f"(d[0]), "+f"(d[1]), "+f"(d[2]), "+f"(d[3])
                 : "r"(a[0]), "r"(a[1]), "r"(a[2]), "r"(a[3]), "r"(b[0]), "r"(b[1]));
}

__device__ __forceinline__ void cp16(uint32_t dst, const void* src) {
    asm volatile("cp.async.cg.shared.global [%0], [%1], 16;" :: "r"(dst), "l"(src) : "memory");
}
#define CP_COMMIT() asm volatile("cp.async.commit_group;" ::: "memory")
#define CP_WAIT(n)  asm volatile("cp.async.wait_group %0;" :: "n"(n) : "memory")

__device__ __forceinline__ float gelu_tanh(float u) {
    float c = 0.7978845608028654f * (u + 0.044715f * u * u * u);
    return 0.5f * u * (1.f + tanhf(c));
}

// ---------------- LayerNorm -> fp16 (single) ----------------
__global__ void __launch_bounds__(256)
ln_h(const float* __restrict__ x, const float* __restrict__ w, const float* __restrict__ b,
     __half* __restrict__ y)
{
    const int row = blockIdx.x;
    const int t   = threadIdx.x;
    float4 v = ((const float4*)(x + (size_t)row * H_))[t];
    float s  = v.x + v.y + v.z + v.w;
    float sq = v.x*v.x + v.y*v.y + v.z*v.z + v.w*v.w;
    #pragma unroll
    for (int o = 16; o > 0; o >>= 1) {
        s  += __shfl_xor_sync(0xffffffffu, s,  o);
        sq += __shfl_xor_sync(0xffffffffu, sq, o);
    }
    __shared__ float ss[8], ssq[8];
    const int wid = t >> 5, lid = t & 31;
    if (lid == 0) { ss[wid] = s; ssq[wid] = sq; }
    __syncthreads();
    if (wid == 0) {
        float s2 = (lid < 8) ? ss[lid]  : 0.f;
        float q2 = (lid < 8) ? ssq[lid] : 0.f;
        #pragma unroll
        for (int o = 4; o > 0; o >>= 1) {
            s2 += __shfl_xor_sync(0xffffffffu, s2, o);
            q2 += __shfl_xor_sync(0xffffffffu, q2, o);
        }
        if (lid == 0) { ss[0] = s2; ssq[0] = q2; }
    }
    __syncthreads();
    const float mean = ss[0] * (1.f / H_);
    const float var  = ssq[0] * (1.f / H_) - mean * mean;
    const float rstd = rsqrtf(var + 1e-5f);
    float4 wv = ((const float4*)w)[t];
    float4 bv = ((const float4*)b)[t];
    float y0 = (v.x - mean) * rstd * wv.x + bv.x;
    float y1 = (v.y - mean) * rstd * wv.y + bv.y;
    float y2 = (v.z - mean) * rstd * wv.z + bv.z;
    float y3 = (v.w - mean) * rstd * wv.w + bv.w;
    __half2* yp = (__half2*)(y + (size_t)row * H_);
    yp[t*2]   = __floats2half2_rn(y0, y1);
    yp[t*2+1] = __floats2half2_rn(y2, y3);
}

// ---------------- all weights fp32 -> fp16 in one kernel ----------------
#define N4_QKV  (H3*H_/4)
#define N4_PROJ (H_*H_/4)
#define N4_FC1  (H4*H_/4)
#define N4_FC2  (H_*H4/4)
#define N4_ALL  (N4_QKV + N4_PROJ + N4_FC1 + N4_FC2)

__global__ void __launch_bounds__(256)
cvt_all(const float* __restrict__ w0, const float* __restrict__ w1,
        const float* __restrict__ w2, const float* __restrict__ w3,
        __half* __restrict__ o0, __half* __restrict__ o1,
        __half* __restrict__ o2, __half* __restrict__ o3)
{
    int i = blockIdx.x * blockDim.x + threadIdx.x;
    if (i >= N4_ALL) return;
    const float* s; __half* d; int k = i;
    if (k < N4_QKV)                { s = w0; d = o0; }
    else if ((k -= N4_QKV)  < N4_PROJ) { s = w1; d = o1; }
    else if ((k -= N4_PROJ) < N4_FC1)  { s = w2; d = o2; }
    else { k -= N4_FC1;              s = w3; d = o3; }
    float4 v = ((const float4*)s)[k];
    ((__half2*)d)[2*k]   = __floats2half2_rn(v.x, v.y);
    ((__half2*)d)[2*k+1] = __floats2half2_rn(v.z, v.w);
}

// ---------------- fp16 1-term GEMM: C[M,N] = A[M,K] @ W[N,K]^T + epi ----------------
// MODE 0: +bias -> scatter Q (scaled log2e/8), K, V (single fp16)
// MODE 1: gelu(+bias) -> fp16 C16
// MODE 2: +bias+resid -> fp32 C
// Stage = A(16K) + B(16K) = 32KB, 3 stages; 2 CTAs/SM.
static constexpr int SMEM_BYTES = 3*32768 + 1024;

template<int MODE>
__global__ void __launch_bounds__(288, 2)
gemm_tc(const __grid_constant__ CUtensorMap mA,
        const __grid_constant__ CUtensorMap mB,
        const float* __restrict__ bias, const float* __restrict__ resid,
        float* __restrict__ C, __half* __restrict__ C16,
        __half* __restrict__ qq, __half* __restrict__ kk, __half* __restrict__ vv,
        int N, int nc)
{
    extern __shared__ char smem[];
    const uint32_t sb  = smem_u32(smem);
    const uint32_t st0 = (sb + 64 + 1023) & ~1023u;
    const int tid = threadIdx.x;

    if (tid == 0) {
        #pragma unroll
        for (int i = 0; i < 3; i++) {
            MBARRIER_INIT(sb + 8*i, 1);
            MBARRIER_INIT(sb + 24 + 8*i, 8);
        }
    }
    __syncthreads();

    const int bx = blockIdx.x, by = blockIdx.y;

    if (tid >= 256) {
        if (tid == 256) {
            for (int c = 0; c < nc; c++) {
                const int s = c % 3, r = c / 3;
                const uint32_t stg = st0 + s * 32768;
                if (r > 0) MBARRIER_WAIT_PARITY_RELAXED(sb + 24 + 8*s, (r - 1) & 1);
                MBARRIER_EXPECT_TX(sb + 8*s, 32768u);
                const int kx = c * 64;
                tma2d(stg,         &mA, kx, by * 128, sb + 8*s);
                tma2d(stg + 16384, &mB, kx, bx * 128, sb + 8*s);
            }
        }
        return;
    }

    const int lane = tid & 31;
    const int wm = (tid >> 5) >> 1;
    const int wn = (tid >> 5) & 1;

    const int arow0 = wm*32 + (lane & 15);
    const int acx   = lane >> 4;
    const int brow0 = wn*64 + (lane & 7) + ((lane >> 4) << 3);
    const int bcx   = (lane >> 3) & 1;

    float acc[2][8][4];
    #pragma unroll
    for (int i = 0; i < 2; i++)
        #pragma unroll
        for (int j = 0; j < 8; j++)
            #pragma unroll
            for (int q = 0; q < 4; q++) acc[i][j][q] = 0.f;

    for (int c = 0; c < nc; c++) {
        const int s = c % 3, r = c / 3;
        const uint32_t stg = st0 + s * 32768;
        MBARRIER_WAIT_PARITY(sb + 8*s, r & 1);

        #pragma unroll
        for (int ks = 0; ks < 4; ks++) {
            uint32_t af[2][4], bf[4][4];
            #pragma unroll
            for (int i = 0; i < 2; i++) {
                const int row = arow0 + i*16;
                const int cc  = 2*ks + acx;
                const uint32_t off = row*128 + (((uint32_t)(cc ^ (row & 7))) << 4);
                ldsm4(af[i], stg + off);
            }
            #pragma unroll
            for (int jt = 0; jt < 4; jt++) {
                const int row = brow0 + jt*16;
                const int cc  = 2*ks + bcx;
                const uint32_t off = row*128 + (((uint32_t)(cc ^ (row & 7))) << 4);
                ldsm4(bf[jt], stg + 16384 + off);
            }
            #pragma unroll
            for (int i = 0; i < 2; i++)
                #pragma unroll
                for (int j = 0; j < 8; j++)
                    mma16816h(acc[i][j], af[i], &bf[j>>1][(j&1)*2]);
        }
        if (lane == 0) MBARRIER_ARRIVE(sb + 24 + 8*s);
    }

    // ---- epilogue ----
    const int rbase = by*128 + wm*32 + (lane >> 2);
    const int cbase = bx*128 + wn*64 + (lane & 3)*2;
    #pragma unroll
    for (int j = 0; j < 8; j++) {
        const int col = cbase + j*8;
        const float bx0 = bias[col], bx1 = bias[col + 1];
        #pragma unroll
        for (int i = 0; i < 2; i++) {
            #pragma unroll
            for (int half = 0; half < 2; half++) {
                const int rowg = rbase + i*16 + half*8;
                float v0 = acc[i][j][half*2 + 0] + bx0;
                float v1 = acc[i][j][half*2 + 1] + bx1;
                if (MODE == 0) {
                    const int hh   = col / 192;
                    const int rem  = col - hh*192;
                    const int whch = rem >> 6;
                    const int d    = rem & 63;
                    const int ss   = rowg >> 1, bb = rowg & 1;
                    const size_t dst = ((size_t)(bb*16 + hh) * S_ + ss) * HD_ + d;
                    if (whch == 0) { v0 *= 0.18033688011f; v1 *= 0.18033688011f; }  // log2(e)/8
                    __half* dp = (whch == 0) ? qq : (whch == 1) ? kk : vv;
                    *(__half2*)&dp[dst] = __floats2half2_rn(v0, v1);
                } else if (MODE == 1) {
                    const size_t off = (size_t)rowg * N + col;
                    *(__half2*)&C16[off] = __floats2half2_rn(gelu_tanh(v0), gelu_tanh(v1));
                } else {
                    const size_t off = (size_t)rowg * N + col;
                    float2 rr = *(const float2*)&resid[off];
                    float2 o; o.x = v0 + rr.x; o.y = v1 + rr.y;
                    *(float2*)&C[off] = o;
                }
            }
        }
    }
}

// ---------------- Flash attention (fp16 HMMA, causal) ----------------
// BQ=128, BKV=64, 8 warps, 2 CTAs/SM. QK^T 1-term, PV 1-term, exp2 softmax.
// smem: Q(16K) + 2 x [K(8K) V(8K)] = 48KB dynamic.
static constexpr int FLASH_SMEM = 48*1024 + 1024;

__global__ void __launch_bounds__(256, 2)
flash_mma(const __half* __restrict__ Q, const __half* __restrict__ K,
          const __half* __restrict__ V, __half* __restrict__ Out)
{
    extern __shared__ char smem[];
    const uint32_t sq  = (smem_u32(smem) + 1023) & ~1023u;
    const uint32_t skv = sq + 16384;   // + buf*16384; within: K 0, V 8192

    const int tid  = threadIdx.x;
    const int lane = tid & 31;
    const int wq   = tid >> 5;
    const int bhid = blockIdx.y;
    const int bb   = bhid >> 4;
    const int hh   = bhid & 15;
    const int qi   = (int)gridDim.x - 1 - (int)blockIdx.x;
    const int q0   = qi << 7;
    const int ntiles = (q0 >> 6) + 2;

    const size_t hbase = (size_t)bhid * (S_ * HD_);

    // ---- prologue: load Q + KV tile 0 ----
    #pragma unroll
    for (int i = 0; i < 4; i++) {
        const int idx = tid*4 + i;
        const int row = idx >> 3, cc = idx & 7;
        const uint32_t off = row*128 + (uint32_t)((cc ^ (row & 7)) << 4);
        const size_t src = hbase + (size_t)(q0 + row) * HD_ + cc*8;
        cp16(sq + off, Q + src);
    }
    {
        #pragma unroll
        for (int i = 0; i < 2; i++) {
            const int idx = tid*2 + i;
            const int row = idx >> 3, cc = idx & 7;
            const uint32_t off = row*128 + (uint32_t)((cc ^ (row & 7)) << 4);
            const size_t src = hbase + (size_t)row * HD_ + cc*8;
            cp16(skv + off,        K + src);
            cp16(skv + 8192 + off, V + src);
        }
    }
    CP_COMMIT();
    CP_WAIT(0);
    __syncthreads();

    // ---- Q fragments (registers) ----
    uint32_t qf[4][4];
    {
        const int row = wq*16 + (lane & 15);
        #pragma unroll
        for (int ks = 0; ks < 4; ks++) {
            const int cc = 2*ks + (lane >> 4);
            const uint32_t off = row*128 + (uint32_t)((cc ^ (row & 7)) << 4);
            ldsm4(qf[ks], sq + off);
        }
    }

    float m_i[2] = {-1e30f, -1e30f};
    float l_i[2] = {0.f, 0.f};
    float O[8][4];
    #pragma unroll
    for (int j = 0; j < 8; j++)
        #pragma unroll
        for (int q = 0; q < 4; q++) O[j][q] = 0.f;

    const int my_last_row = q0 + wq*16 + 15;

    for (int kt = 0; kt < ntiles; kt++) {
        const int t0 = kt << 6;
        __syncthreads();
        if (kt + 1 < ntiles) {
            const uint32_t stg = skv + ((kt+1) & 1) * 16384;
            const int tn0 = (kt+1) << 6;
            #pragma unroll
            for (int i = 0; i < 2; i++) {
                const int idx = tid*2 + i;
                const int row = idx >> 3, cc = idx & 7;
                const uint32_t off = row*128 + (uint32_t)((cc ^ (row & 7)) << 4);
                const size_t src = hbase + (size_t)(tn0 + row) * HD_ + cc*8;
                cp16(stg + off,        K + src);
                cp16(stg + 8192 + off, V + src);
            }
        }
        CP_COMMIT();
        CP_WAIT(1);
        __syncthreads();

        if (t0 > my_last_row) continue;

        const uint32_t stg = skv + (kt & 1) * 16384;
        const uint32_t sk = stg, sv = stg + 8192;

        // ---- scores S = Q K^T ----
        float sc[8][4];
        #pragma unroll
        for (int j = 0; j < 8; j++)
            #pragma unroll
            for (int q = 0; q < 4; q++) sc[j][q] = 0.f;

        const int krow_b = (lane & 7) + ((lane >> 4) << 3);
        #pragma unroll
        for (int ks = 0; ks < 4; ks++) {
            const int cc = 2*ks + ((lane >> 3) & 1);
            #pragma unroll
            for (int jt = 0; jt < 4; jt++) {
                uint32_t bf[4];
                const int row = jt*16 + krow_b;
                const uint32_t off = row*128 + (uint32_t)((cc ^ (row & 7)) << 4);
                ldsm4(bf, sk + off);
                mma16816h(sc[2*jt],   qf[ks], &bf[0]);
                mma16816h(sc[2*jt+1], qf[ks], &bf[2]);
            }
        }

        // ---- causal mask (last two kv tiles only) ----
        if (kt >= ntiles - 2) {
            const int r0g = q0 + wq*16 + (lane >> 2);
            #pragma unroll
            for (int j = 0; j < 8; j++) {
                const int c0 = t0 + j*8 + (lane & 3)*2;
                if (c0     > r0g)     sc[j][0] = -1e30f;
                if (c0 + 1 > r0g)     sc[j][1] = -1e30f;
                if (c0     > r0g + 8) sc[j][2] = -1e30f;
                if (c0 + 1 > r0g + 8) sc[j][3] = -1e30f;
            }
        }

        // ---- online softmax in log2 domain ----
        #pragma unroll
        for (int v = 0; v < 2; v++) {
            float rm = -1e30f;
            #pragma unroll
            for (int j = 0; j < 8; j++)
                rm = fmaxf(rm, fmaxf(sc[j][2*v], sc[j][2*v+1]));
            rm = fmaxf(rm, __shfl_xor_sync(0xffffffffu, rm, 1));
            rm = fmaxf(rm, __shfl_xor_sync(0xffffffffu, rm, 2));
            const float mnew = fmaxf(m_i[v], rm);
            const float corr = exp2f(m_i[v] - mnew);
            float rs = 0.f;
            #pragma unroll
            for (int j = 0; j < 8; j++) {
                float p0 = exp2f(sc[j][2*v]   - mnew);
                float p1 = exp2f(sc[j][2*v+1] - mnew);
                sc[j][2*v] = p0; sc[j][2*v+1] = p1;
                rs += p0 + p1;
            }
            rs += __shfl_xor_sync(0xffffffffu, rs, 1);
            rs += __shfl_xor_sync(0xffffffffu, rs, 2);
            l_i[v] = l_i[v] * corr + rs;
            m_i[v] = mnew;
            #pragma unroll
            for (int j = 0; j < 8; j++) { O[j][2*v] *= corr; O[j][2*v+1] *= corr; }
        }

        // ---- O += P V ----
        const int vrow_b = (lane & 7) + (((lane >> 3) & 1) << 3);
        #pragma unroll
        for (int kc = 0; kc < 4; kc++) {
            uint32_t pah[4];
            {
                __half2 h2;
                h2 = __floats2half2_rn(sc[2*kc][0],   sc[2*kc][1]);   pah[0] = *(uint32_t*)&h2;
                h2 = __floats2half2_rn(sc[2*kc][2],   sc[2*kc][3]);   pah[1] = *(uint32_t*)&h2;
                h2 = __floats2half2_rn(sc[2*kc+1][0], sc[2*kc+1][1]); pah[2] = *(uint32_t*)&h2;
                h2 = __floats2half2_rn(sc[2*kc+1][2], sc[2*kc+1][3]); pah[3] = *(uint32_t*)&h2;
            }
            const int vrow = kc*16 + vrow_b;
            #pragma unroll
            for (int p = 0; p < 4; p++) {
                const int cc = 2*p + (lane >> 4);
                const uint32_t off = vrow*128 + (uint32_t)((cc ^ (vrow & 7)) << 4);
                uint32_t vf[4];
                ldsm4t(vf, sv + off);
                mma16816h(O[2*p],   pah, &vf[0]);
                mma16816h(O[2*p+1], pah, &vf[2]);
            }
        }
    }

    // ---- epilogue: normalize + store fp16 ----
    #pragma unroll
    for (int v = 0; v < 2; v++) {
        const float inv = 1.f / l_i[v];
        const int srow = q0 + wq*16 + (lane >> 2) + v*8;
        const size_t base = ((size_t)srow * B_ + bb) * H_ + hh*HD_ + (lane & 3)*2;
        #pragma unroll
        for (int j = 0; j < 8; j++) {
            __half2 h2 = __floats2half2_rn(O[j][2*v] * inv, O[j][2*v+1] * inv);
            *(__half2*)&Out[base + j*8] = h2;
        }
    }
}

// ---------------- host ----------------
typedef CUresult (CUDAAPI *TMEncodeFn)(
    CUtensorMap*, CUtensorMapDataType, cuuint32_t, void*,
    const cuuint64_t*, const cuuint64_t*, const cuuint32_t*, const cuuint32_t*,
    CUtensorMapInterleave, CUtensorMapSwizzle, CUtensorMapL2promotion, CUtensorMapFloatOOBfill);

static void enc_map(TMEncodeFn fn, CUtensorMap* m, void* p, uint64_t rows, uint64_t k)
{
    cuuint64_t dims[2]    = {k, rows};
    cuuint64_t strides[1] = {k * 2};
    cuuint32_t box[2]     = {64, 128};
    cuuint32_t es[2]      = {1, 1};
    fn(m, CU_TENSOR_MAP_DATA_TYPE_FLOAT16, 2, p, dims, strides, box, es,
       CU_TENSOR_MAP_INTERLEAVE_NONE, CU_TENSOR_MAP_SWIZZLE_128B,
       CU_TENSOR_MAP_L2_PROMOTION_L2_128B, CU_TENSOR_MAP_FLOAT_OOB_FILL_NONE);
}

extern "C" void kernel_launch(void* const* d_in, const int* in_sizes, int n_in,
                              void* d_out, int out_size)
{
    const float* x     = (const float*)d_in[0];
    const float* ln1w  = (const float*)d_in[1];
    const float* ln1b  = (const float*)d_in[2];
    const float* wqkv  = (const float*)d_in[3];
    const float* bqkv  = (const float*)d_in[4];
    const float* wproj = (const float*)d_in[5];
    const float* bproj = (const float*)d_in[6];
    const float* ln2w  = (const float*)d_in[7];
    const float* ln2b  = (const float*)d_in[8];
    const float* wfc1  = (const float*)d_in[9];
    const float* bfc1  = (const float*)d_in[10];
    const float* wfc2  = (const float*)d_in[11];
    const float* bfc2  = (const float*)d_in[12];
    float* out = (float*)d_out;

    float *x1;
    __half *a16, *m16, *wq16, *wp16, *w116, *w216, *qq, *kk, *vv;
    cudaGetSymbolAddress((void**)&x1,   g_x1);
    cudaGetSymbolAddress((void**)&a16,  g_a);
    cudaGetSymbolAddress((void**)&m16,  g_m);
    cudaGetSymbolAddress((void**)&wq16, g_wqkv);
    cudaGetSymbolAddress((void**)&wp16, g_wproj);
    cudaGetSymbolAddress((void**)&w116, g_wfc1);
    cudaGetSymbolAddress((void**)&w216, g_wfc2);
    cudaGetSymbolAddress((void**)&qq,   g_q);
    cudaGetSymbolAddress((void**)&kk,   g_k);
    cudaGetSymbolAddress((void**)&vv,   g_v);

    TMEncodeFn enc = nullptr;
    cudaDriverEntryPointQueryResult qres;
    cudaGetDriverEntryPointByVersion("cuTensorMapEncodeTiled", (void**)&enc, 12000,
                                     cudaEnableDefault, &qres);

    cudaFuncSetAttribute((const void*)gemm_tc<0>, cudaFuncAttributeMaxDynamicSharedMemorySize, SMEM_BYTES);
    cudaFuncSetAttribute((const void*)gemm_tc<1>, cudaFuncAttributeMaxDynamicSharedMemorySize, SMEM_BYTES);
    cudaFuncSetAttribute((const void*)gemm_tc<2>, cudaFuncAttributeMaxDynamicSharedMemorySize, SMEM_BYTES);
    cudaFuncSetAttribute((const void*)flash_mma,  cudaFuncAttributeMaxDynamicSharedMemorySize, FLASH_SMEM);

    CUtensorMap mA, mB;

    // 0) convert all weights to fp16 (one kernel)
    cvt_all<<<(N4_ALL + 255)/256, 256>>>(wqkv, wproj, wfc1, wfc2, wq16, wp16, w116, w216);
    // 1) ln1 -> a16
    ln_h<<<ROWS, 256>>>(x, ln1w, ln1b, a16);
    // 2) qkv GEMM -> scatter Q/K/V : [4096,3072], K=1024
    enc_map(enc, &mA, a16, ROWS, H_);
    enc_map(enc, &mB, wq16, H3, H_);
    gemm_tc<0><<<dim3(H3/128, ROWS/128), 288, SMEM_BYTES>>>(
        mA, mB, bqkv, nullptr, nullptr, nullptr, qq, kk, vv, H3, H_/64);
    // 3) flash attention -> a16
    flash_mma<<<dim3(S_/128, BHN), 256, FLASH_SMEM>>>(qq, kk, vv, a16);
    // 4) x1 = x + attn @ wproj^T + b : [4096,1024], K=1024
    enc_map(enc, &mB, wp16, H_, H_);
    gemm_tc<2><<<dim3(H_/128, ROWS/128), 288, SMEM_BYTES>>>(
        mA, mB, bproj, x, x1, nullptr, nullptr, nullptr, nullptr, H_, H_/64);
    // 5) ln2 -> a16
    ln_h<<<ROWS, 256>>>(x1, ln2w, ln2b, a16);
    // 6) mid = gelu(ln2 @ wfc1^T + b) -> m16 : [4096,4096], K=1024
    enc_map(enc, &mB, w116, H4, H_);
    gemm_tc<1><<<dim3(H4/128, ROWS/128), 288, SMEM_BYTES>>>(
        mA, mB, bfc1, nullptr, nullptr, m16, nullptr, nullptr, nullptr, H4, H_/64);
    // 7) out = x1 + mid @ wfc2^T + b : [4096,1024], K=4096
    enc_map(enc, &mA, m16, ROWS, H4);
    enc_map(enc, &mB, w216, H_, H4);
    gemm_tc<2><<<dim3(H_/128, ROWS/128), 288, SMEM_BYTES>>>(
        mA, mB, bfc2, x1, out, nullptr, nullptr, nullptr, nullptr, H_, H4/64);
}